// round 2
// baseline (speedup 1.0000x reference)
#include <cuda_runtime.h>
#include <math.h>

#define BB 2
#define NN 1024
#define FSZ 1024
#define FZ 64
#define HH 16
#define CC 64

// ---------------- scratch (device globals: no runtime allocation) ----------------
__device__ float g_q[BB*NN*HH*CC];                 // 8 MB
__device__ float g_k[BB*NN*HH*CC];                 // 8 MB
__device__ float g_v[BB*NN*HH*CC];                 // 8 MB
__device__ float g_bias[(size_t)BB*HH*NN*NN];      // 134 MB, (b,h,q,k)

// ---------------- 1) QKV projection: Y = s @ W, fp32 tiled GEMM ----------------
// M=2048, N=1024, K=1024.  BM=128, BN=64, BK=16, 256 threads, 8x4 microtile.
#define GBM 128
#define GBN 64
#define GBK 16

__global__ __launch_bounds__(256) void qkv_gemm_kernel(
    const float* __restrict__ s,
    const float* __restrict__ Wq,
    const float* __restrict__ Wk,
    const float* __restrict__ Wv)
{
    const float* W = (blockIdx.z == 0) ? Wq : (blockIdx.z == 1) ? Wk : Wv;
    float* out     = (blockIdx.z == 0) ? g_q : (blockIdx.z == 1) ? g_k : g_v;

    __shared__ float As[GBK][GBM];   // A stored transposed: As[k][m]
    __shared__ float Bs[GBK][GBN];

    const int tid = threadIdx.x;
    const int m0 = blockIdx.y * GBM;
    const int n0 = blockIdx.x * GBN;
    const int tx = tid % 16;      // n microtile
    const int ty = tid / 16;      // m microtile

    float acc[8][4];
    #pragma unroll
    for (int i = 0; i < 8; i++)
        #pragma unroll
        for (int j = 0; j < 4; j++) acc[i][j] = 0.f;

    const int ar0 = tid / 4;            // 0..63
    const int ac  = (tid % 4) * 4;      // 0,4,8,12
    const int br  = tid / 16;           // 0..15
    const int bc  = (tid % 16) * 4;     // 0..60

    for (int k0 = 0; k0 < FSZ; k0 += GBK) {
        #pragma unroll
        for (int p = 0; p < 2; p++) {
            int r = ar0 + p * 64;
            float4 va = *(const float4*)&s[(size_t)(m0 + r) * FSZ + k0 + ac];
            As[ac + 0][r] = va.x; As[ac + 1][r] = va.y;
            As[ac + 2][r] = va.z; As[ac + 3][r] = va.w;
        }
        float4 vb = *(const float4*)&W[(size_t)(k0 + br) * (HH * CC) + n0 + bc];
        *(float4*)&Bs[br][bc] = vb;
        __syncthreads();

        #pragma unroll
        for (int kk = 0; kk < GBK; kk++) {
            float a[8], b[4];
            *(float4*)&a[0] = *(float4*)&As[kk][ty * 8];
            *(float4*)&a[4] = *(float4*)&As[kk][ty * 8 + 4];
            *(float4*)&b[0] = *(float4*)&Bs[kk][tx * 4];
            #pragma unroll
            for (int i = 0; i < 8; i++)
                #pragma unroll
                for (int j = 0; j < 4; j++)
                    acc[i][j] = fmaf(a[i], b[j], acc[i][j]);
        }
        __syncthreads();
    }

    #pragma unroll
    for (int i = 0; i < 8; i++)
        *(float4*)&out[(size_t)(m0 + ty * 8 + i) * (HH * CC) + n0 + tx * 4] =
            *(float4*)&acc[i][0];
}

// ---------------- 2) RoPE on q, k (in place) ----------------
__global__ void rope_kernel(const int* __restrict__ positions)
{
    int idx = blockIdx.x * blockDim.x + threadIdx.x;   // B*N*H*32
    if (idx >= BB * NN * HH * 32) return;
    int i = idx % 32;
    int h = (idx / 32) % HH;
    int n = (idx / (32 * HH)) % NN;
    int b = idx / (32 * HH * NN);

    float pos = (float)positions[b * NN + n];
    float ts  = powf(10000.0f, (float)i / 32.0f);
    float ang = pos / ts;
    float sv, cv;
    sincosf(ang, &sv, &cv);

    size_t base = ((size_t)(b * NN + n) * HH + h) * CC;
    float q1 = g_q[base + i], q2 = g_q[base + i + 32];
    g_q[base + i]      = q1 * cv - q2 * sv;
    g_q[base + i + 32] = q2 * cv + q1 * sv;
    float k1 = g_k[base + i], k2 = g_k[base + i + 32];
    g_k[base + i]      = k1 * cv - k2 * sv;
    g_k[base + i + 32] = k2 * cv + k1 * sv;
}

// ---------------- 3) bias[b,h,q,k] = sum_f pair[b,q,k,f] * Wb[f,h] ----------------
// One block: fixed (b,q), 32 consecutive k, all 16 h. Skip fully-masked blocks
// (causal + sorted segment ids) -> only ~1/4 of `pair` read.
__global__ __launch_bounds__(256) void bias_kernel(
    const float* __restrict__ pair,
    const float* __restrict__ Wb,
    const int* __restrict__ seg)
{
    const int k0 = blockIdx.x * 32;
    const int q  = blockIdx.y;
    const int b  = blockIdx.z;
    if (k0 > q) return;
    const int segq = seg[b * NN + q];
    const int khi  = min(k0 + 31, q);
    if (seg[b * NN + khi] != segq) return;   // sorted: whole block below segment

    __shared__ float sp[64 * 33];    // f-major, pad 33 for conflict-free reads
    __shared__ float sWb[64 * 16];
    const int tid = threadIdx.x;

    const float* psrc = &pair[(((size_t)b * NN + q) * NN + k0) * FZ];
    #pragma unroll
    for (int p = 0; p < 2; p++) {
        int l  = tid + p * 256;
        int kk = l / 16;
        int f4 = (l % 16) * 4;
        float4 v = *(const float4*)&psrc[(size_t)kk * FZ + f4];
        sp[(f4 + 0) * 33 + kk] = v.x;
        sp[(f4 + 1) * 33 + kk] = v.y;
        sp[(f4 + 2) * 33 + kk] = v.z;
        sp[(f4 + 3) * 33 + kk] = v.w;
    }
    *(float4*)&sWb[tid * 4] = *(const float4*)&Wb[tid * 4];
    __syncthreads();

    const int kk = tid % 32;
    const int h0 = tid / 32;         // 0..7, also handles h0+8
    float a0 = 0.f, a1 = 0.f;
    #pragma unroll
    for (int f = 0; f < 64; f++) {
        float v = sp[f * 33 + kk];
        a0 = fmaf(v, sWb[f * 16 + h0],     a0);
        a1 = fmaf(v, sWb[f * 16 + h0 + 8], a1);
    }
    g_bias[(((size_t)b * HH + h0)     * NN + q) * NN + k0 + kk] = a0;
    g_bias[(((size_t)b * HH + h0 + 8) * NN + q) * NN + k0 + kk] = a1;
}

// ---------------- 4) flash attention, fp32, 64x64 tiles ----------------
// Block = (b, h, q-tile of 64). 8 warps; warp w owns rows 8w..8w+7; lane owns
// columns {lane, lane+32}. Online softmax, bias added pre-softmax, causal +
// segment mask, per-tile segment skip.
__global__ __launch_bounds__(256) void attn_kernel(
    const int* __restrict__ seg, float* __restrict__ out)
{
    extern __shared__ float smdyn[];
    float* Qs = smdyn;              // 64*64
    float* Ks = Qs + 64 * 64;       // 64*65 (pad -> conflict-free column reads)
    float* Vs = Ks + 64 * 65;       // 64*65
    float* Ps = Vs + 64 * 65;       // 64*64
    int* seg_qs = (int*)(Ps + 64 * 64);   // 64
    int* seg_ks = seg_qs + 64;            // 64

    const int tid  = threadIdx.x;
    const int lane = tid & 31;
    const int w    = tid >> 5;
    const int qt   = blockIdx.x;
    const int h    = blockIdx.y;
    const int b    = blockIdx.z;
    const int q0   = qt * 64;
    const float sm_scale = 0.125f;  // 1/sqrt(64)

    #pragma unroll
    for (int p = 0; p < 4; p++) {
        int l  = tid + p * 256;
        int r  = l / 16;
        int c4 = (l % 16) * 4;
        float4 v = *(const float4*)&g_q[(((size_t)(b * NN + q0 + r)) * HH + h) * CC + c4];
        *(float4*)&Qs[r * 64 + c4] = v;
    }
    if (tid < 64) seg_qs[tid] = seg[b * NN + q0 + tid];
    __syncthreads();

    const int seg_q0 = seg_qs[0];
    int my_seg[8];
    #pragma unroll
    for (int r = 0; r < 8; r++) my_seg[r] = seg_qs[w * 8 + r];

    float m_i[8], l_i[8], O0[8], O1[8];
    #pragma unroll
    for (int r = 0; r < 8; r++) { m_i[r] = -1e30f; l_i[r] = 0.f; O0[r] = 0.f; O1[r] = 0.f; }

    for (int j = 0; j <= qt; j++) {
        const int k0 = j * 64;
        if (seg[b * NN + k0 + 63] < seg_q0) continue;   // tile entirely below segment
        __syncthreads();                                 // protect Ks/Vs reuse

        #pragma unroll
        for (int p = 0; p < 4; p++) {
            int l  = tid + p * 256;
            int r  = l / 16;
            int c4 = (l % 16) * 4;
            size_t gb = (((size_t)(b * NN + k0 + r)) * HH + h) * CC + c4;
            float4 vk = *(const float4*)&g_k[gb];
            Ks[r * 65 + c4 + 0] = vk.x; Ks[r * 65 + c4 + 1] = vk.y;
            Ks[r * 65 + c4 + 2] = vk.z; Ks[r * 65 + c4 + 3] = vk.w;
            float4 vv = *(const float4*)&g_v[gb];
            Vs[r * 65 + c4 + 0] = vv.x; Vs[r * 65 + c4 + 1] = vv.y;
            Vs[r * 65 + c4 + 2] = vv.z; Vs[r * 65 + c4 + 3] = vv.w;
        }
        if (tid < 64) seg_ks[tid] = seg[b * NN + k0 + tid];
        __syncthreads();

        // prefetch bias tile (coalesced; overlaps with S compute)
        float bv0[8], bv1[8];
        #pragma unroll
        for (int r = 0; r < 8; r++) {
            int qg = q0 + w * 8 + r;
            const float* bp = &g_bias[(((size_t)(b * HH + h)) * NN + qg) * NN + k0];
            bv0[r] = bp[lane];
            bv1[r] = bp[lane + 32];
        }

        // S = Q K^T
        float acc0[8], acc1[8];
        #pragma unroll
        for (int r = 0; r < 8; r++) { acc0[r] = 0.f; acc1[r] = 0.f; }
        #pragma unroll
        for (int f4 = 0; f4 < 64; f4 += 4) {
            float ka0[4], ka1[4];
            #pragma unroll
            for (int u = 0; u < 4; u++) {
                ka0[u] = Ks[lane * 65 + f4 + u];
                ka1[u] = Ks[(lane + 32) * 65 + f4 + u];
            }
            #pragma unroll
            for (int r = 0; r < 8; r++) {
                float4 q4 = *(float4*)&Qs[(w * 8 + r) * 64 + f4];
                acc0[r] = fmaf(q4.x, ka0[0], acc0[r]);
                acc0[r] = fmaf(q4.y, ka0[1], acc0[r]);
                acc0[r] = fmaf(q4.z, ka0[2], acc0[r]);
                acc0[r] = fmaf(q4.w, ka0[3], acc0[r]);
                acc1[r] = fmaf(q4.x, ka1[0], acc1[r]);
                acc1[r] = fmaf(q4.y, ka1[1], acc1[r]);
                acc1[r] = fmaf(q4.z, ka1[2], acc1[r]);
                acc1[r] = fmaf(q4.w, ka1[3], acc1[r]);
            }
        }

        // mask + bias + online softmax
        #pragma unroll
        for (int r = 0; r < 8; r++) {
            int qg  = q0 + w * 8 + r;
            int kg0 = k0 + lane, kg1 = k0 + lane + 32;
            bool v0 = (kg0 <= qg) && (seg_ks[lane]      == my_seg[r]);
            bool v1 = (kg1 <= qg) && (seg_ks[lane + 32] == my_seg[r]);
            float s0 = v0 ? fmaf(acc0[r], sm_scale, bv0[r]) : -1e30f;
            float s1 = v1 ? fmaf(acc1[r], sm_scale, bv1[r]) : -1e30f;

            float mr = fmaxf(s0, s1);
            #pragma unroll
            for (int off = 16; off > 0; off >>= 1)
                mr = fmaxf(mr, __shfl_xor_sync(0xffffffffu, mr, off));
            float mnew  = fmaxf(m_i[r], mr);
            float alpha = __expf(m_i[r] - mnew);
            m_i[r] = mnew;

            float p0 = (s0 > -1e29f) ? __expf(s0 - mnew) : 0.f;
            float p1 = (s1 > -1e29f) ? __expf(s1 - mnew) : 0.f;
            float rs = p0 + p1;
            #pragma unroll
            for (int off = 16; off > 0; off >>= 1)
                rs += __shfl_xor_sync(0xffffffffu, rs, off);
            l_i[r] = l_i[r] * alpha + rs;
            O0[r] *= alpha; O1[r] *= alpha;
            Ps[(w * 8 + r) * 64 + lane]      = p0;
            Ps[(w * 8 + r) * 64 + lane + 32] = p1;
        }
        __syncwarp();

        // O += P V
        #pragma unroll
        for (int k4 = 0; k4 < 64; k4 += 4) {
            float va0[4], va1[4];
            #pragma unroll
            for (int u = 0; u < 4; u++) {
                va0[u] = Vs[(k4 + u) * 65 + lane];
                va1[u] = Vs[(k4 + u) * 65 + lane + 32];
            }
            #pragma unroll
            for (int r = 0; r < 8; r++) {
                float4 p4 = *(float4*)&Ps[(w * 8 + r) * 64 + k4];
                O0[r] = fmaf(p4.x, va0[0], O0[r]);
                O0[r] = fmaf(p4.y, va0[1], O0[r]);
                O0[r] = fmaf(p4.z, va0[2], O0[r]);
                O0[r] = fmaf(p4.w, va0[3], O0[r]);
                O1[r] = fmaf(p4.x, va1[0], O1[r]);
                O1[r] = fmaf(p4.y, va1[1], O1[r]);
                O1[r] = fmaf(p4.z, va1[2], O1[r]);
                O1[r] = fmaf(p4.w, va1[3], O1[r]);
            }
        }
    }

    #pragma unroll
    for (int r = 0; r < 8; r++) {
        int qg = q0 + w * 8 + r;
        float inv = 1.f / l_i[r];
        size_t base = (((size_t)(b * NN + qg)) * HH + h) * CC;
        out[base + lane]      = O0[r] * inv;
        out[base + lane + 32] = O1[r] * inv;
    }
}

// ---------------- launcher ----------------
extern "C" void kernel_launch(void* const* d_in, const int* in_sizes, int n_in,
                              void* d_out, int out_size)
{
    const float* s    = (const float*)d_in[0];
    const float* pair = (const float*)d_in[1];
    const int*   segs = (const int*)d_in[2];
    const int*   pos  = (const int*)d_in[3];
    const float* Wq   = (const float*)d_in[4];
    const float* Wk   = (const float*)d_in[5];
    const float* Wv   = (const float*)d_in[6];
    const float* Wb   = (const float*)d_in[7];
    float* out = (float*)d_out;

    dim3 g1((HH * CC) / GBN, (BB * NN) / GBM, 3);
    qkv_gemm_kernel<<<g1, 256>>>(s, Wq, Wk, Wv);

    rope_kernel<<<(BB * NN * HH * 32) / 256, 256>>>(pos);

    dim3 g2(NN / 32, NN, BB);
    bias_kernel<<<g2, 256>>>(pair, Wb, segs);

    const int attn_smem = (64 * 64 + 64 * 65 * 2 + 64 * 64) * 4 + 128 * 4;
    cudaFuncSetAttribute(attn_kernel, cudaFuncAttributeMaxDynamicSharedMemorySize, attn_smem);
    dim3 g3(NN / 64, HH, BB);
    attn_kernel<<<g3, 256, attn_smem>>>(segs, out);
}

// round 5
// speedup vs baseline: 1.4238x; 1.4238x over previous
#include <cuda_runtime.h>
#include <cuda_bf16.h>
#include <math.h>
#include <stdint.h>

#define BB 2
#define NN 1024
#define FSZ 1024
#define FZ 64
#define HH 16
#define CC 64

// ---------------- scratch (device globals: no runtime allocation) ----------------
__device__ float g_q[BB*NN*HH*CC];                 // 8 MB
__device__ float g_k[BB*NN*HH*CC];                 // 8 MB
__device__ float g_v[BB*NN*HH*CC];                 // 8 MB
__device__ float g_bias[(size_t)BB*HH*NN*NN];      // 134 MB, (b,h,q,k)

// ================= helpers =================
__device__ __forceinline__ uint32_t smem_to_u32(const void* p) {
    uint32_t a;
    asm("{ .reg .u64 t; cvta.to.shared.u64 t, %1; cvt.u32.u64 %0, t; }" : "=r"(a) : "l"(p));
    return a;
}
__device__ __forceinline__ uint32_t pack_bf16x2(__nv_bfloat16 a, __nv_bfloat16 b) {
    __nv_bfloat162 t(a, b);
    return *reinterpret_cast<uint32_t*>(&t);
}
__device__ __forceinline__ void split2(float x, __nv_bfloat16& h, __nv_bfloat16& l) {
    h = __float2bfloat16(x);
    l = __float2bfloat16(x - __bfloat162float(h));
}
__device__ __forceinline__ void ldmatrix_x4(uint32_t& r0, uint32_t& r1, uint32_t& r2,
                                            uint32_t& r3, uint32_t addr) {
    asm volatile("ldmatrix.sync.aligned.m8n8.x4.shared.b16 {%0,%1,%2,%3}, [%4];"
                 : "=r"(r0), "=r"(r1), "=r"(r2), "=r"(r3) : "r"(addr));
}
__device__ __forceinline__ void mma_bf16(float* c, uint32_t a0, uint32_t a1, uint32_t a2,
                                         uint32_t a3, uint32_t b0, uint32_t b1) {
    asm volatile(
        "mma.sync.aligned.m16n8k16.row.col.f32.bf16.bf16.f32 "
        "{%0,%1,%2,%3}, {%4,%5,%6,%7}, {%8,%9}, {%0,%1,%2,%3};"
        : "+f"(c[0]), "+f"(c[1]), "+f"(c[2]), "+f"(c[3])
        : "r"(a0), "r"(a1), "r"(a2), "r"(a3), "r"(b0), "r"(b1));
}

// ---------------- 1) QKV projection via mma.sync bf16 split-precision ----------------
// M=2048, N=1024, K=1024. CTA tile 128x128, K-chunk 64, 8 warps (warp tile 32x64).
// SMEM bf16 tiles, row pad 72 elems (144 B) for conflict-free ldmatrix.
#define PADK 72
#define TILEB (128 * PADK * 2)            // 18432 B per tile
#define QKV_SMEM (4 * TILEB)              // A_hi, A_lo, B_hi, B_lo = 73728 B

__global__ void __launch_bounds__(256, 2) qkv_mma_kernel(
    const float* __restrict__ s,
    const float* __restrict__ Wq,
    const float* __restrict__ Wk,
    const float* __restrict__ Wv)
{
    extern __shared__ char smem[];
    const uint32_t sb = smem_to_u32(smem);
    const uint32_t oA_hi = 0, oA_lo = TILEB, oB_hi = 2 * TILEB, oB_lo = 3 * TILEB;

    const int tid  = threadIdx.x;
    const int lane = tid & 31;
    const int wid  = tid >> 5;
    const int g    = lane >> 2;        // group 0..7
    const int t    = lane & 3;

    const float* W = (blockIdx.z == 0) ? Wq : (blockIdx.z == 1) ? Wk : Wv;
    float* out     = (blockIdx.z == 0) ? g_q : (blockIdx.z == 1) ? g_k : g_v;
    const int m0 = blockIdx.y * 128;
    const int n0 = blockIdx.x * 128;
    const int wm = (wid >> 1) * 32;    // warp M offset within tile
    const int wn = (wid & 1) * 64;     // warp N offset within tile

    float acc[2][8][4];
    #pragma unroll
    for (int i = 0; i < 2; i++)
        #pragma unroll
        for (int j = 0; j < 8; j++)
            #pragma unroll
            for (int u = 0; u < 4; u++) acc[i][j][u] = 0.f;

    // precompute ldmatrix lane addresses (offsets within a tile, chunk-invariant)
    // A (per mf): row = wm + mf*16 + (lane&15), colhalf = lane>>4
    const uint32_t aRow = (uint32_t)(lane & 15);
    const uint32_t aColH = (uint32_t)(lane >> 4) * 16;     // bytes (8 bf16)
    // B (per nf pair): tile = lane>>3: n = nf*8 + (tile>>1)*8 + (lane&7), khalf = tile&1
    const uint32_t bTile = (uint32_t)(lane >> 3);
    const uint32_t bRow  = (bTile >> 1) * 8 + (uint32_t)(lane & 7);
    const uint32_t bColH = (bTile & 1) * 16;               // bytes

    #pragma unroll 1
    for (int c = 0; c < 16; c++) {
        const int k0 = c * 64;
        __syncthreads();

        // ---- load A chunk: s[m0..m0+127][k0..k0+63] -> hi/lo bf16 ----
        #pragma unroll
        for (int it = 0; it < 8; it++) {
            int idx = tid + it * 256;
            int r   = idx >> 4;
            int c4  = (idx & 15) << 2;
            float4 v = *(const float4*)&s[(size_t)(m0 + r) * FSZ + k0 + c4];
            __nv_bfloat16 hx, lx, hy, ly, hz, lz, hw, lw;
            split2(v.x, hx, lx); split2(v.y, hy, ly);
            split2(v.z, hz, lz); split2(v.w, hw, lw);
            uint32_t off = (uint32_t)(r * (PADK * 2) + c4 * 2);
            *(uint32_t*)(smem + oA_hi + off)     = pack_bf16x2(hx, hy);
            *(uint32_t*)(smem + oA_hi + off + 4) = pack_bf16x2(hz, hw);
            *(uint32_t*)(smem + oA_lo + off)     = pack_bf16x2(lx, ly);
            *(uint32_t*)(smem + oA_lo + off + 4) = pack_bf16x2(lz, lw);
        }

        // ---- load B chunk transposed: Bt[n][k] = W[k0+k][n0+n] ----
        {
            int n   = tid & 127;
            int th2 = tid >> 7;
            const float* wp = &W[(size_t)k0 * (HH * CC) + n0 + n];
            #pragma unroll
            for (int j = 0; j < 16; j++) {
                int kk = th2 * 32 + 2 * j;
                float x0 = wp[(size_t)kk * (HH * CC)];
                float x1 = wp[(size_t)(kk + 1) * (HH * CC)];
                __nv_bfloat16 h0, l0, h1, l1;
                split2(x0, h0, l0); split2(x1, h1, l1);
                uint32_t off = (uint32_t)(n * (PADK * 2) + kk * 2);
                *(uint32_t*)(smem + oB_hi + off) = pack_bf16x2(h0, h1);
                *(uint32_t*)(smem + oB_lo + off) = pack_bf16x2(l0, l1);
            }
        }
        __syncthreads();

        // ---- compute: 3 passes (AhBh, AhBl, AlBh) x 4 k-steps ----
        #pragma unroll
        for (int pass = 0; pass < 3; pass++) {
            const uint32_t Aoff = (pass == 2) ? oA_lo : oA_hi;
            const uint32_t Boff = (pass == 1) ? oB_lo : oB_hi;
            #pragma unroll
            for (int ks = 0; ks < 4; ks++) {
                const uint32_t kb = (uint32_t)(ks * 16) * 2;   // byte offset of k-step
                uint32_t af[2][4];
                #pragma unroll
                for (int mf = 0; mf < 2; mf++) {
                    uint32_t addr = sb + Aoff +
                        (uint32_t)(wm + mf * 16 + aRow) * (PADK * 2) + kb + aColH;
                    ldmatrix_x4(af[mf][0], af[mf][1], af[mf][2], af[mf][3], addr);
                }
                uint32_t bf[8][2];
                #pragma unroll
                for (int nf = 0; nf < 8; nf += 2) {
                    uint32_t addr = sb + Boff +
                        (uint32_t)(wn + nf * 8 + bRow) * (PADK * 2) + kb + bColH;
                    uint32_t r0, r1, r2, r3;
                    ldmatrix_x4(r0, r1, r2, r3, addr);
                    bf[nf][0] = r0;     bf[nf][1] = r1;
                    bf[nf + 1][0] = r2; bf[nf + 1][1] = r3;
                }
                #pragma unroll
                for (int mf = 0; mf < 2; mf++)
                    #pragma unroll
                    for (int nf = 0; nf < 8; nf++)
                        mma_bf16(acc[mf][nf], af[mf][0], af[mf][1], af[mf][2], af[mf][3],
                                 bf[nf][0], bf[nf][1]);
            }
        }
    }

    // ---- epilogue: write C ----
    #pragma unroll
    for (int mf = 0; mf < 2; mf++) {
        #pragma unroll
        for (int nf = 0; nf < 8; nf++) {
            int row = m0 + wm + mf * 16 + g;
            int col = n0 + wn + nf * 8 + 2 * t;
            float2 v0 = make_float2(acc[mf][nf][0], acc[mf][nf][1]);
            float2 v1 = make_float2(acc[mf][nf][2], acc[mf][nf][3]);
            *(float2*)&out[(size_t)row * (HH * CC) + col]       = v0;
            *(float2*)&out[(size_t)(row + 8) * (HH * CC) + col] = v1;
        }
    }
}

// ---------------- 2) RoPE on q, k (in place) ----------------
__global__ void rope_kernel(const int* __restrict__ positions)
{
    int idx = blockIdx.x * blockDim.x + threadIdx.x;   // B*N*H*32
    if (idx >= BB * NN * HH * 32) return;
    int i = idx % 32;
    int h = (idx / 32) % HH;
    int n = (idx / (32 * HH)) % NN;
    int b = idx / (32 * HH * NN);

    float pos = (float)positions[b * NN + n];
    float ts  = powf(10000.0f, (float)i / 32.0f);
    float ang = pos / ts;
    float sv, cv;
    sincosf(ang, &sv, &cv);

    size_t base = ((size_t)(b * NN + n) * HH + h) * CC;
    float q1 = g_q[base + i], q2 = g_q[base + i + 32];
    g_q[base + i]      = q1 * cv - q2 * sv;
    g_q[base + i + 32] = q2 * cv + q1 * sv;
    float k1 = g_k[base + i], k2 = g_k[base + i + 32];
    g_k[base + i]      = k1 * cv - k2 * sv;
    g_k[base + i + 32] = k2 * cv + k1 * sv;
}

// ---------------- 3) bias[b,h,q,k] = sum_f pair[b,q,k,f] * Wb[f,h] ----------------
__global__ __launch_bounds__(256) void bias_kernel(
    const float* __restrict__ pair,
    const float* __restrict__ Wb,
    const int* __restrict__ seg)
{
    const int k0 = blockIdx.x * 32;
    const int q  = blockIdx.y;
    const int b  = blockIdx.z;
    if (k0 > q) return;
    const int segq = seg[b * NN + q];
    const int khi  = min(k0 + 31, q);
    if (seg[b * NN + khi] != segq) return;

    __shared__ float sp[64 * 33];
    __shared__ float sWb[64 * 16];
    const int tid = threadIdx.x;

    const float* psrc = &pair[(((size_t)b * NN + q) * NN + k0) * FZ];
    #pragma unroll
    for (int p = 0; p < 2; p++) {
        int l  = tid + p * 256;
        int kk = l / 16;
        int f4 = (l % 16) * 4;
        float4 v = *(const float4*)&psrc[(size_t)kk * FZ + f4];
        sp[(f4 + 0) * 33 + kk] = v.x;
        sp[(f4 + 1) * 33 + kk] = v.y;
        sp[(f4 + 2) * 33 + kk] = v.z;
        sp[(f4 + 3) * 33 + kk] = v.w;
    }
    *(float4*)&sWb[tid * 4] = *(const float4*)&Wb[tid * 4];
    __syncthreads();

    const int kk = tid % 32;
    const int h0 = tid / 32;
    float a0 = 0.f, a1 = 0.f;
    #pragma unroll
    for (int f = 0; f < 64; f++) {
        float v = sp[f * 33 + kk];
        a0 = fmaf(v, sWb[f * 16 + h0],     a0);
        a1 = fmaf(v, sWb[f * 16 + h0 + 8], a1);
    }
    g_bias[(((size_t)b * HH + h0)     * NN + q) * NN + k0 + kk] = a0;
    g_bias[(((size_t)b * HH + h0 + 8) * NN + q) * NN + k0 + kk] = a1;
}

// ---------------- 4) flash attention, fp32, 64x64 tiles ----------------
__global__ __launch_bounds__(256) void attn_kernel(
    const int* __restrict__ seg, float* __restrict__ out)
{
    extern __shared__ float smdyn[];
    float* Qs = smdyn;              // 64*64
    float* Ks = Qs + 64 * 64;       // 64*65
    float* Vs = Ks + 64 * 65;       // 64*65
    float* Ps = Vs + 64 * 65;       // 64*64
    int* seg_qs = (int*)(Ps + 64 * 64);
    int* seg_ks = seg_qs + 64;

    const int tid  = threadIdx.x;
    const int lane = tid & 31;
    const int w    = tid >> 5;
    const int qt   = blockIdx.x;
    const int h    = blockIdx.y;
    const int b    = blockIdx.z;
    const int q0   = qt * 64;
    const float sm_scale = 0.125f;

    #pragma unroll
    for (int p = 0; p < 4; p++) {
        int l  = tid + p * 256;
        int r  = l / 16;
        int c4 = (l % 16) * 4;
        float4 v = *(const float4*)&g_q[(((size_t)(b * NN + q0 + r)) * HH + h) * CC + c4];
        *(float4*)&Qs[r * 64 + c4] = v;
    }
    if (tid < 64) seg_qs[tid] = seg[b * NN + q0 + tid];
    __syncthreads();

    const int seg_q0 = seg_qs[0];
    int my_seg[8];
    #pragma unroll
    for (int r = 0; r < 8; r++) my_seg[r] = seg_qs[w * 8 + r];

    float m_i[8], l_i[8], O0[8], O1[8];
    #pragma unroll
    for (int r = 0; r < 8; r++) { m_i[r] = -1e30f; l_i[r] = 0.f; O0[r] = 0.f; O1[r] = 0.f; }

    for (int j = 0; j <= qt; j++) {
        const int k0 = j * 64;
        if (seg[b * NN + k0 + 63] < seg_q0) continue;
        __syncthreads();

        #pragma unroll
        for (int p = 0; p < 4; p++) {
            int l  = tid + p * 256;
            int r  = l / 16;
            int c4 = (l % 16) * 4;
            size_t gb = (((size_t)(b * NN + k0 + r)) * HH + h) * CC + c4;
            float4 vk = *(const float4*)&g_k[gb];
            Ks[r * 65 + c4 + 0] = vk.x; Ks[r * 65 + c4 + 1] = vk.y;
            Ks[r * 65 + c4 + 2] = vk.z; Ks[r * 65 + c4 + 3] = vk.w;
            float4 vv = *(const float4*)&g_v[gb];
            Vs[r * 65 + c4 + 0] = vv.x; Vs[r * 65 + c4 + 1] = vv.y;
            Vs[r * 65 + c4 + 2] = vv.z; Vs[r * 65 + c4 + 3] = vv.w;
        }
        if (tid < 64) seg_ks[tid] = seg[b * NN + k0 + tid];
        __syncthreads();

        float bv0[8], bv1[8];
        #pragma unroll
        for (int r = 0; r < 8; r++) {
            int qg = q0 + w * 8 + r;
            const float* bp = &g_bias[(((size_t)(b * HH + h)) * NN + qg) * NN + k0];
            bv0[r] = bp[lane];
            bv1[r] = bp[lane + 32];
        }

        float acc0[8], acc1[8];
        #pragma unroll
        for (int r = 0; r < 8; r++) { acc0[r] = 0.f; acc1[r] = 0.f; }
        #pragma unroll
        for (int f4 = 0; f4 < 64; f4 += 4) {
            float ka0[4], ka1[4];
            #pragma unroll
            for (int u = 0; u < 4; u++) {
                ka0[u] = Ks[lane * 65 + f4 + u];
                ka1[u] = Ks[(lane + 32) * 65 + f4 + u];
            }
            #pragma unroll
            for (int r = 0; r < 8; r++) {
                float4 q4 = *(float4*)&Qs[(w * 8 + r) * 64 + f4];
                acc0[r] = fmaf(q4.x, ka0[0], acc0[r]);
                acc0[r] = fmaf(q4.y, ka0[1], acc0[r]);
                acc0[r] = fmaf(q4.z, ka0[2], acc0[r]);
                acc0[r] = fmaf(q4.w, ka0[3], acc0[r]);
                acc1[r] = fmaf(q4.x, ka1[0], acc1[r]);
                acc1[r] = fmaf(q4.y, ka1[1], acc1[r]);
                acc1[r] = fmaf(q4.z, ka1[2], acc1[r]);
                acc1[r] = fmaf(q4.w, ka1[3], acc1[r]);
            }
        }

        #pragma unroll
        for (int r = 0; r < 8; r++) {
            int qg  = q0 + w * 8 + r;
            int kg0 = k0 + lane, kg1 = k0 + lane + 32;
            bool v0 = (kg0 <= qg) && (seg_ks[lane]      == my_seg[r]);
            bool v1 = (kg1 <= qg) && (seg_ks[lane + 32] == my_seg[r]);
            float s0 = v0 ? fmaf(acc0[r], sm_scale, bv0[r]) : -1e30f;
            float s1 = v1 ? fmaf(acc1[r], sm_scale, bv1[r]) : -1e30f;

            float mr = fmaxf(s0, s1);
            #pragma unroll
            for (int off = 16; off > 0; off >>= 1)
                mr = fmaxf(mr, __shfl_xor_sync(0xffffffffu, mr, off));
            float mnew  = fmaxf(m_i[r], mr);
            float alpha = __expf(m_i[r] - mnew);
            m_i[r] = mnew;

            float p0 = (s0 > -1e29f) ? __expf(s0 - mnew) : 0.f;
            float p1 = (s1 > -1e29f) ? __expf(s1 - mnew) : 0.f;
            float rs = p0 + p1;
            #pragma unroll
            for (int off = 16; off > 0; off >>= 1)
                rs += __shfl_xor_sync(0xffffffffu, rs, off);
            l_i[r] = l_i[r] * alpha + rs;
            O0[r] *= alpha; O1[r] *= alpha;
            Ps[(w * 8 + r) * 64 + lane]      = p0;
            Ps[(w * 8 + r) * 64 + lane + 32] = p1;
        }
        __syncwarp();

        #pragma unroll
        for (int k4 = 0; k4 < 64; k4 += 4) {
            float va0[4], va1[4];
            #pragma unroll
            for (int u = 0; u < 4; u++) {
                va0[u] = Vs[(k4 + u) * 65 + lane];
                va1[u] = Vs[(k4 + u) * 65 + lane + 32];
            }
            #pragma unroll
            for (int r = 0; r < 8; r++) {
                float4 p4 = *(float4*)&Ps[(w * 8 + r) * 64 + k4];
                O0[r] = fmaf(p4.x, va0[0], O0[r]);
                O0[r] = fmaf(p4.y, va0[1], O0[r]);
                O0[r] = fmaf(p4.z, va0[2], O0[r]);
                O0[r] = fmaf(p4.w, va0[3], O0[r]);
                O1[r] = fmaf(p4.x, va1[0], O1[r]);
                O1[r] = fmaf(p4.y, va1[1], O1[r]);
                O1[r] = fmaf(p4.z, va1[2], O1[r]);
                O1[r] = fmaf(p4.w, va1[3], O1[r]);
            }
        }
    }

    #pragma unroll
    for (int r = 0; r < 8; r++) {
        int qg = q0 + w * 8 + r;
        float inv = 1.f / l_i[r];
        size_t base = (((size_t)(b * NN + qg)) * HH + h) * CC;
        out[base + lane]      = O0[r] * inv;
        out[base + lane + 32] = O1[r] * inv;
    }
}

// ---------------- launcher ----------------
extern "C" void kernel_launch(void* const* d_in, const int* in_sizes, int n_in,
                              void* d_out, int out_size)
{
    const float* s    = (const float*)d_in[0];
    const float* pair = (const float*)d_in[1];
    const int*   segs = (const int*)d_in[2];
    const int*   pos  = (const int*)d_in[3];
    const float* Wq   = (const float*)d_in[4];
    const float* Wk   = (const float*)d_in[5];
    const float* Wv   = (const float*)d_in[6];
    const float* Wb   = (const float*)d_in[7];
    float* out = (float*)d_out;

    cudaFuncSetAttribute(qkv_mma_kernel, cudaFuncAttributeMaxDynamicSharedMemorySize,
                         QKV_SMEM);
    dim3 g1((HH * CC) / 128, (BB * NN) / 128, 3);
    qkv_mma_kernel<<<g1, 256, QKV_SMEM>>>(s, Wq, Wk, Wv);

    rope_kernel<<<(BB * NN * HH * 32) / 256, 256>>>(pos);

    dim3 g2(NN / 32, NN, BB);
    bias_kernel<<<g2, 256>>>(pair, Wb, segs);

    const int attn_smem = (64 * 64 + 64 * 65 * 2 + 64 * 64) * 4 + 128 * 4;
    cudaFuncSetAttribute(attn_kernel, cudaFuncAttributeMaxDynamicSharedMemorySize, attn_smem);
    dim3 g3(NN / 64, HH, BB);
    attn_kernel<<<g3, 256, attn_smem>>>(segs, out);
}

// round 6
// speedup vs baseline: 1.5769x; 1.1075x over previous
#include <cuda_runtime.h>
#include <cuda_bf16.h>
#include <math.h>
#include <stdint.h>

#define BB 2
#define NN 1024
#define FSZ 1024
#define FZ 64
#define HH 16
#define CC 64

// ---------------- scratch (device globals: no runtime allocation) ----------------
__device__ float g_q[BB*NN*HH*CC];                        // 8 MB
__device__ float g_k[BB*NN*HH*CC];                        // 8 MB
__device__ float g_v[BB*NN*HH*CC];                        // 8 MB
__device__ __nv_bfloat16 g_bias[(size_t)BB*HH*NN*NN];     // 67 MB, (b,h,q,k)

// ================= helpers =================
__device__ __forceinline__ uint32_t smem_to_u32(const void* p) {
    uint32_t a;
    asm("{ .reg .u64 t; cvta.to.shared.u64 t, %1; cvt.u32.u64 %0, t; }" : "=r"(a) : "l"(p));
    return a;
}
__device__ __forceinline__ uint32_t pack_bf16x2(__nv_bfloat16 a, __nv_bfloat16 b) {
    __nv_bfloat162 t(a, b);
    return *reinterpret_cast<uint32_t*>(&t);
}
__device__ __forceinline__ void split2(float x, __nv_bfloat16& h, __nv_bfloat16& l) {
    h = __float2bfloat16(x);
    l = __float2bfloat16(x - __bfloat162float(h));
}
__device__ __forceinline__ void ldmatrix_x4(uint32_t& r0, uint32_t& r1, uint32_t& r2,
                                            uint32_t& r3, uint32_t addr) {
    asm volatile("ldmatrix.sync.aligned.m8n8.x4.shared.b16 {%0,%1,%2,%3}, [%4];"
                 : "=r"(r0), "=r"(r1), "=r"(r2), "=r"(r3) : "r"(addr));
}
__device__ __forceinline__ void ldmatrix_x4_trans(uint32_t& r0, uint32_t& r1, uint32_t& r2,
                                                  uint32_t& r3, uint32_t addr) {
    asm volatile("ldmatrix.sync.aligned.m8n8.x4.trans.shared.b16 {%0,%1,%2,%3}, [%4];"
                 : "=r"(r0), "=r"(r1), "=r"(r2), "=r"(r3) : "r"(addr));
}
__device__ __forceinline__ void mma_bf16(float* c, uint32_t a0, uint32_t a1, uint32_t a2,
                                         uint32_t a3, uint32_t b0, uint32_t b1) {
    asm volatile(
        "mma.sync.aligned.m16n8k16.row.col.f32.bf16.bf16.f32 "
        "{%0,%1,%2,%3}, {%4,%5,%6,%7}, {%8,%9}, {%0,%1,%2,%3};"
        : "+f"(c[0]), "+f"(c[1]), "+f"(c[2]), "+f"(c[3])
        : "r"(a0), "r"(a1), "r"(a2), "r"(a3), "r"(b0), "r"(b1));
}
__device__ __forceinline__ void mma_bf16a(float* c, const uint32_t* a, uint32_t b0, uint32_t b1) {
    mma_bf16(c, a[0], a[1], a[2], a[3], b0, b1);
}

// ---------------- 1) QKV projection via mma.sync bf16 split-precision ----------------
#define PADK 72
#define TILEB (128 * PADK * 2)            // 18432 B per tile
#define QKV_SMEM (4 * TILEB)              // A_hi, A_lo, B_hi, B_lo = 73728 B

__global__ void __launch_bounds__(256, 2) qkv_mma_kernel(
    const float* __restrict__ s,
    const float* __restrict__ Wq,
    const float* __restrict__ Wk,
    const float* __restrict__ Wv)
{
    extern __shared__ char smem[];
    const uint32_t sb = smem_to_u32(smem);
    const uint32_t oA_hi = 0, oA_lo = TILEB, oB_hi = 2 * TILEB, oB_lo = 3 * TILEB;

    const int tid  = threadIdx.x;
    const int lane = tid & 31;
    const int wid  = tid >> 5;
    const int g    = lane >> 2;
    const int t    = lane & 3;

    const float* W = (blockIdx.z == 0) ? Wq : (blockIdx.z == 1) ? Wk : Wv;
    float* out     = (blockIdx.z == 0) ? g_q : (blockIdx.z == 1) ? g_k : g_v;
    const int m0 = blockIdx.y * 128;
    const int n0 = blockIdx.x * 128;
    const int wm = (wid >> 1) * 32;
    const int wn = (wid & 1) * 64;

    float acc[2][8][4];
    #pragma unroll
    for (int i = 0; i < 2; i++)
        #pragma unroll
        for (int j = 0; j < 8; j++)
            #pragma unroll
            for (int u = 0; u < 4; u++) acc[i][j][u] = 0.f;

    const uint32_t aRow  = (uint32_t)(lane & 15);
    const uint32_t aColH = (uint32_t)(lane >> 4) * 16;
    const uint32_t bTile = (uint32_t)(lane >> 3);
    const uint32_t bRow  = (bTile >> 1) * 8 + (uint32_t)(lane & 7);
    const uint32_t bColH = (bTile & 1) * 16;

    #pragma unroll 1
    for (int c = 0; c < 16; c++) {
        const int k0 = c * 64;
        __syncthreads();

        #pragma unroll
        for (int it = 0; it < 8; it++) {
            int idx = tid + it * 256;
            int r   = idx >> 4;
            int c4  = (idx & 15) << 2;
            float4 v = *(const float4*)&s[(size_t)(m0 + r) * FSZ + k0 + c4];
            __nv_bfloat16 hx, lx, hy, ly, hz, lz, hw, lw;
            split2(v.x, hx, lx); split2(v.y, hy, ly);
            split2(v.z, hz, lz); split2(v.w, hw, lw);
            uint32_t off = (uint32_t)(r * (PADK * 2) + c4 * 2);
            *(uint32_t*)(smem + oA_hi + off)     = pack_bf16x2(hx, hy);
            *(uint32_t*)(smem + oA_hi + off + 4) = pack_bf16x2(hz, hw);
            *(uint32_t*)(smem + oA_lo + off)     = pack_bf16x2(lx, ly);
            *(uint32_t*)(smem + oA_lo + off + 4) = pack_bf16x2(lz, lw);
        }
        {
            int n   = tid & 127;
            int th2 = tid >> 7;
            const float* wp = &W[(size_t)k0 * (HH * CC) + n0 + n];
            #pragma unroll
            for (int j = 0; j < 16; j++) {
                int kk = th2 * 32 + 2 * j;
                float x0 = wp[(size_t)kk * (HH * CC)];
                float x1 = wp[(size_t)(kk + 1) * (HH * CC)];
                __nv_bfloat16 h0, l0, h1, l1;
                split2(x0, h0, l0); split2(x1, h1, l1);
                uint32_t off = (uint32_t)(n * (PADK * 2) + kk * 2);
                *(uint32_t*)(smem + oB_hi + off) = pack_bf16x2(h0, h1);
                *(uint32_t*)(smem + oB_lo + off) = pack_bf16x2(l0, l1);
            }
        }
        __syncthreads();

        #pragma unroll
        for (int pass = 0; pass < 3; pass++) {
            const uint32_t Aoff = (pass == 2) ? oA_lo : oA_hi;
            const uint32_t Boff = (pass == 1) ? oB_lo : oB_hi;
            #pragma unroll
            for (int ks = 0; ks < 4; ks++) {
                const uint32_t kb = (uint32_t)(ks * 16) * 2;
                uint32_t af[2][4];
                #pragma unroll
                for (int mf = 0; mf < 2; mf++) {
                    uint32_t addr = sb + Aoff +
                        (uint32_t)(wm + mf * 16 + aRow) * (PADK * 2) + kb + aColH;
                    ldmatrix_x4(af[mf][0], af[mf][1], af[mf][2], af[mf][3], addr);
                }
                uint32_t bf[8][2];
                #pragma unroll
                for (int nf = 0; nf < 8; nf += 2) {
                    uint32_t addr = sb + Boff +
                        (uint32_t)(wn + nf * 8 + bRow) * (PADK * 2) + kb + bColH;
                    uint32_t r0, r1, r2, r3;
                    ldmatrix_x4(r0, r1, r2, r3, addr);
                    bf[nf][0] = r0;     bf[nf][1] = r1;
                    bf[nf + 1][0] = r2; bf[nf + 1][1] = r3;
                }
                #pragma unroll
                for (int mf = 0; mf < 2; mf++)
                    #pragma unroll
                    for (int nf = 0; nf < 8; nf++)
                        mma_bf16(acc[mf][nf], af[mf][0], af[mf][1], af[mf][2], af[mf][3],
                                 bf[nf][0], bf[nf][1]);
            }
        }
    }

    #pragma unroll
    for (int mf = 0; mf < 2; mf++) {
        #pragma unroll
        for (int nf = 0; nf < 8; nf++) {
            int row = m0 + wm + mf * 16 + g;
            int col = n0 + wn + nf * 8 + 2 * t;
            float2 v0 = make_float2(acc[mf][nf][0], acc[mf][nf][1]);
            float2 v1 = make_float2(acc[mf][nf][2], acc[mf][nf][3]);
            *(float2*)&out[(size_t)row * (HH * CC) + col]       = v0;
            *(float2*)&out[(size_t)(row + 8) * (HH * CC) + col] = v1;
        }
    }
}

// ---------------- 2) RoPE on q, k (in place) ----------------
__global__ void rope_kernel(const int* __restrict__ positions)
{
    int idx = blockIdx.x * blockDim.x + threadIdx.x;
    if (idx >= BB * NN * HH * 32) return;
    int i = idx % 32;
    int h = (idx / 32) % HH;
    int n = (idx / (32 * HH)) % NN;
    int b = idx / (32 * HH * NN);

    float pos = (float)positions[b * NN + n];
    float ts  = powf(10000.0f, (float)i / 32.0f);
    float ang = pos / ts;
    float sv, cv;
    sincosf(ang, &sv, &cv);

    size_t base = ((size_t)(b * NN + n) * HH + h) * CC;
    float q1 = g_q[base + i], q2 = g_q[base + i + 32];
    g_q[base + i]      = q1 * cv - q2 * sv;
    g_q[base + i + 32] = q2 * cv + q1 * sv;
    float k1 = g_k[base + i], k2 = g_k[base + i + 32];
    g_k[base + i]      = k1 * cv - k2 * sv;
    g_k[base + i + 32] = k2 * cv + k1 * sv;
}

// ---------------- 3) bias[b,h,q,k] = sum_f pair[b,q,k,f] * Wb[f,h] (bf16 out) --------
__global__ __launch_bounds__(256) void bias_kernel(
    const float* __restrict__ pair,
    const float* __restrict__ Wb,
    const int* __restrict__ seg)
{
    const int k0 = blockIdx.x * 32;
    const int q  = blockIdx.y;
    const int b  = blockIdx.z;
    if (k0 > q) return;
    const int segq = seg[b * NN + q];
    const int khi  = min(k0 + 31, q);
    if (seg[b * NN + khi] != segq) return;

    __shared__ float sp[64 * 33];
    __shared__ float sWb[64 * 16];
    const int tid = threadIdx.x;

    const float* psrc = &pair[(((size_t)b * NN + q) * NN + k0) * FZ];
    #pragma unroll
    for (int p = 0; p < 2; p++) {
        int l  = tid + p * 256;
        int kk = l / 16;
        int f4 = (l % 16) * 4;
        float4 v = *(const float4*)&psrc[(size_t)kk * FZ + f4];
        sp[(f4 + 0) * 33 + kk] = v.x;
        sp[(f4 + 1) * 33 + kk] = v.y;
        sp[(f4 + 2) * 33 + kk] = v.z;
        sp[(f4 + 3) * 33 + kk] = v.w;
    }
    *(float4*)&sWb[tid * 4] = *(const float4*)&Wb[tid * 4];
    __syncthreads();

    const int kk = tid % 32;
    const int h0 = tid / 32;
    float a0 = 0.f, a1 = 0.f;
    #pragma unroll
    for (int f = 0; f < 64; f++) {
        float v = sp[f * 33 + kk];
        a0 = fmaf(v, sWb[f * 16 + h0],     a0);
        a1 = fmaf(v, sWb[f * 16 + h0 + 8], a1);
    }
    g_bias[(((size_t)b * HH + h0)     * NN + q) * NN + k0 + kk] = __float2bfloat16(a0);
    g_bias[(((size_t)b * HH + h0 + 8) * NN + q) * NN + k0 + kk] = __float2bfloat16(a1);
}

// ---------------- 4) flash attention via mma.sync, 128q x 64k tiles ----------------
// 8 warps; warp w owns q rows [w*16, w*16+16). Softmax reduction stays in-quad.
#define AQTB (128 * PADK * 2)     // 18432 (Q hi or lo)
#define AKTB (64 * PADK * 2)      // 9216  (K/V hi or lo)
#define ATTN_SMEM (2 * AQTB + 4 * AKTB + 256)

__global__ void __launch_bounds__(256) attn_mma_kernel(
    const int* __restrict__ seg, float* __restrict__ out)
{
    extern __shared__ char smem[];
    const uint32_t sb = smem_to_u32(smem);
    const uint32_t oQh = 0, oQl = AQTB;
    const uint32_t oKh = 2 * AQTB, oKl = oKh + AKTB, oVh = oKl + AKTB, oVl = oVh + AKTB;
    int* seg_ks = (int*)(smem + oVl + AKTB);

    const int tid  = threadIdx.x;
    const int lane = tid & 31;
    const int w    = tid >> 5;
    const int g    = lane >> 2;
    const int t    = lane & 3;
    const int qt   = 7 - blockIdx.x;          // heavy tiles first
    const int h    = blockIdx.y;
    const int b    = blockIdx.z;
    const int q0   = qt * 128;
    const float sm_scale = 0.125f;

    const int r0g = q0 + w * 16 + g;          // this thread's two rows
    const int r1g = r0g + 8;

    // load Q tile (128 x 64) split hi/lo into smem
    #pragma unroll
    for (int it = 0; it < 8; it++) {
        int idx = tid + it * 256;
        int r   = idx >> 4;
        int c4  = (idx & 15) << 2;
        float4 v = *(const float4*)&g_q[(((size_t)(b * NN + q0 + r)) * HH + h) * CC + c4];
        __nv_bfloat16 hx, lx, hy, ly, hz, lz, hw, lw;
        split2(v.x, hx, lx); split2(v.y, hy, ly);
        split2(v.z, hz, lz); split2(v.w, hw, lw);
        uint32_t off = (uint32_t)(r * (PADK * 2) + c4 * 2);
        *(uint32_t*)(smem + oQh + off)     = pack_bf16x2(hx, hy);
        *(uint32_t*)(smem + oQh + off + 4) = pack_bf16x2(hz, hw);
        *(uint32_t*)(smem + oQl + off)     = pack_bf16x2(lx, ly);
        *(uint32_t*)(smem + oQl + off + 4) = pack_bf16x2(lz, lw);
    }
    const int seg_q0  = seg[b * NN + q0];
    const int myseg0  = seg[b * NN + r0g];
    const int myseg1  = seg[b * NN + r1g];

    float O[8][4];
    #pragma unroll
    for (int nf = 0; nf < 8; nf++)
        #pragma unroll
        for (int u = 0; u < 4; u++) O[nf][u] = 0.f;
    float m0r = -1e30f, m1r = -1e30f, l0r = 0.f, l1r = 0.f;

    // ldmatrix lane addressing (chunk-invariant pieces)
    const uint32_t aRow  = (uint32_t)(lane & 15);
    const uint32_t aColH = (uint32_t)(lane >> 4) * 16;
    const uint32_t bTile = (uint32_t)(lane >> 3);
    const uint32_t bRow  = (bTile >> 1) * 8 + (uint32_t)(lane & 7);
    const uint32_t bColH = (bTile & 1) * 16;
    const uint32_t vRow  = ((bTile & 1) * 8 + (uint32_t)(lane & 7));   // + kf*16
    const uint32_t vColH = (uint32_t)(lane >> 4) * 16;                 // + cf*32

    const __nv_bfloat16* bias0 = &g_bias[(((size_t)(b * HH + h)) * NN + r0g) * NN];
    const __nv_bfloat16* bias1 = &g_bias[(((size_t)(b * HH + h)) * NN + r1g) * NN];

    const int jmax = 2 * qt + 1;
    #pragma unroll 1
    for (int j = 0; j <= jmax; j++) {
        const int k0 = j * 64;
        if (seg[b * NN + k0 + 63] < seg_q0) continue;
        __syncthreads();

        // load K/V tile (64 x 64) split hi/lo
        #pragma unroll
        for (int it = 0; it < 4; it++) {
            int idx = tid + it * 256;
            int r   = idx >> 4;
            int c4  = (idx & 15) << 2;
            size_t gb = (((size_t)(b * NN + k0 + r)) * HH + h) * CC + c4;
            uint32_t off = (uint32_t)(r * (PADK * 2) + c4 * 2);
            {
                float4 v = *(const float4*)&g_k[gb];
                __nv_bfloat16 hx, lx, hy, ly, hz, lz, hw, lw;
                split2(v.x, hx, lx); split2(v.y, hy, ly);
                split2(v.z, hz, lz); split2(v.w, hw, lw);
                *(uint32_t*)(smem + oKh + off)     = pack_bf16x2(hx, hy);
                *(uint32_t*)(smem + oKh + off + 4) = pack_bf16x2(hz, hw);
                *(uint32_t*)(smem + oKl + off)     = pack_bf16x2(lx, ly);
                *(uint32_t*)(smem + oKl + off + 4) = pack_bf16x2(lz, lw);
            }
            {
                float4 v = *(const float4*)&g_v[gb];
                __nv_bfloat16 hx, lx, hy, ly, hz, lz, hw, lw;
                split2(v.x, hx, lx); split2(v.y, hy, ly);
                split2(v.z, hz, lz); split2(v.w, hw, lw);
                *(uint32_t*)(smem + oVh + off)     = pack_bf16x2(hx, hy);
                *(uint32_t*)(smem + oVh + off + 4) = pack_bf16x2(hz, hw);
                *(uint32_t*)(smem + oVl + off)     = pack_bf16x2(lx, ly);
                *(uint32_t*)(smem + oVl + off + 4) = pack_bf16x2(lz, lw);
            }
        }
        if (tid < 64) seg_ks[tid] = seg[b * NN + k0 + tid];
        __syncthreads();

        // ---- S = Q K^T (3-pass split) ----
        float S[8][4];
        #pragma unroll
        for (int nf = 0; nf < 8; nf++)
            #pragma unroll
            for (int u = 0; u < 4; u++) S[nf][u] = 0.f;

        #pragma unroll
        for (int ks = 0; ks < 4; ks++) {
            const uint32_t kb = (uint32_t)(ks * 32);
            uint32_t qaddr = sb + (uint32_t)(w * 16 + aRow) * (PADK * 2) + kb + aColH;
            uint32_t qh[4], ql[4];
            ldmatrix_x4(qh[0], qh[1], qh[2], qh[3], qaddr + oQh);
            ldmatrix_x4(ql[0], ql[1], ql[2], ql[3], qaddr + oQl);
            #pragma unroll
            for (int np = 0; np < 4; np++) {
                uint32_t kaddr = sb + (uint32_t)(np * 16 + bRow) * (PADK * 2) + kb + bColH;
                uint32_t r0, r1, r2, r3;
                ldmatrix_x4(r0, r1, r2, r3, kaddr + oKh);
                mma_bf16a(S[2 * np],     qh, r0, r1);
                mma_bf16a(S[2 * np + 1], qh, r2, r3);
                mma_bf16a(S[2 * np],     ql, r0, r1);
                mma_bf16a(S[2 * np + 1], ql, r2, r3);
                ldmatrix_x4(r0, r1, r2, r3, kaddr + oKl);
                mma_bf16a(S[2 * np],     qh, r0, r1);
                mma_bf16a(S[2 * np + 1], qh, r2, r3);
            }
        }

        // ---- mask + bias + online softmax ----
        float mx0 = -1e30f, mx1 = -1e30f;
        #pragma unroll
        for (int nf = 0; nf < 8; nf++) {
            int cl = nf * 8 + 2 * t;         // local col
            int cg = k0 + cl;                // global col
            __nv_bfloat162 bb0 = *(const __nv_bfloat162*)&bias0[cg];
            __nv_bfloat162 bb1 = *(const __nv_bfloat162*)&bias1[cg];
            int sk0 = seg_ks[cl], sk1 = seg_ks[cl + 1];
            bool v00 = (cg     <= r0g) && (sk0 == myseg0);
            bool v01 = (cg + 1 <= r0g) && (sk1 == myseg0);
            bool v10 = (cg     <= r1g) && (sk0 == myseg1);
            bool v11 = (cg + 1 <= r1g) && (sk1 == myseg1);
            S[nf][0] = v00 ? fmaf(S[nf][0], sm_scale, __bfloat162float(bb0.x)) : -1e30f;
            S[nf][1] = v01 ? fmaf(S[nf][1], sm_scale, __bfloat162float(bb0.y)) : -1e30f;
            S[nf][2] = v10 ? fmaf(S[nf][2], sm_scale, __bfloat162float(bb1.x)) : -1e30f;
            S[nf][3] = v11 ? fmaf(S[nf][3], sm_scale, __bfloat162float(bb1.y)) : -1e30f;
            mx0 = fmaxf(mx0, fmaxf(S[nf][0], S[nf][1]));
            mx1 = fmaxf(mx1, fmaxf(S[nf][2], S[nf][3]));
        }
        mx0 = fmaxf(mx0, __shfl_xor_sync(0xffffffffu, mx0, 1));
        mx0 = fmaxf(mx0, __shfl_xor_sync(0xffffffffu, mx0, 2));
        mx1 = fmaxf(mx1, __shfl_xor_sync(0xffffffffu, mx1, 1));
        mx1 = fmaxf(mx1, __shfl_xor_sync(0xffffffffu, mx1, 2));

        float mn0 = fmaxf(m0r, mx0), mn1 = fmaxf(m1r, mx1);
        float al0 = __expf(m0r - mn0), al1 = __expf(m1r - mn1);
        m0r = mn0; m1r = mn1;

        float sum0 = 0.f, sum1 = 0.f;
        #pragma unroll
        for (int nf = 0; nf < 8; nf++) {
            float p0 = (S[nf][0] > -1e29f) ? __expf(S[nf][0] - mn0) : 0.f;
            float p1 = (S[nf][1] > -1e29f) ? __expf(S[nf][1] - mn0) : 0.f;
            float p2 = (S[nf][2] > -1e29f) ? __expf(S[nf][2] - mn1) : 0.f;
            float p3 = (S[nf][3] > -1e29f) ? __expf(S[nf][3] - mn1) : 0.f;
            S[nf][0] = p0; S[nf][1] = p1; S[nf][2] = p2; S[nf][3] = p3;
            sum0 += p0 + p1; sum1 += p2 + p3;
        }
        sum0 += __shfl_xor_sync(0xffffffffu, sum0, 1);
        sum0 += __shfl_xor_sync(0xffffffffu, sum0, 2);
        sum1 += __shfl_xor_sync(0xffffffffu, sum1, 1);
        sum1 += __shfl_xor_sync(0xffffffffu, sum1, 2);
        l0r = l0r * al0 + sum0;
        l1r = l1r * al1 + sum1;

        #pragma unroll
        for (int nf = 0; nf < 8; nf++) {
            O[nf][0] *= al0; O[nf][1] *= al0;
            O[nf][2] *= al1; O[nf][3] *= al1;
        }

        // ---- O += P V (3-pass split, V via ldmatrix.trans) ----
        #pragma unroll
        for (int kf = 0; kf < 4; kf++) {
            uint32_t ah[4], al[4];
            {
                __nv_bfloat16 h0, l0, h1, l1;
                split2(S[2 * kf][0], h0, l0); split2(S[2 * kf][1], h1, l1);
                ah[0] = pack_bf16x2(h0, h1);  al[0] = pack_bf16x2(l0, l1);
                split2(S[2 * kf][2], h0, l0); split2(S[2 * kf][3], h1, l1);
                ah[1] = pack_bf16x2(h0, h1);  al[1] = pack_bf16x2(l0, l1);
                split2(S[2 * kf + 1][0], h0, l0); split2(S[2 * kf + 1][1], h1, l1);
                ah[2] = pack_bf16x2(h0, h1);  al[2] = pack_bf16x2(l0, l1);
                split2(S[2 * kf + 1][2], h0, l0); split2(S[2 * kf + 1][3], h1, l1);
                ah[3] = pack_bf16x2(h0, h1);  al[3] = pack_bf16x2(l0, l1);
            }
            #pragma unroll
            for (int cf = 0; cf < 4; cf++) {
                uint32_t vaddr = sb + (uint32_t)(kf * 16 + vRow) * (PADK * 2)
                               + (uint32_t)(cf * 32) + vColH;
                uint32_t r0, r1, r2, r3;
                ldmatrix_x4_trans(r0, r1, r2, r3, vaddr + oVh);
                mma_bf16a(O[2 * cf],     ah, r0, r1);
                mma_bf16a(O[2 * cf + 1], ah, r2, r3);
                mma_bf16a(O[2 * cf],     al, r0, r1);
                mma_bf16a(O[2 * cf + 1], al, r2, r3);
                ldmatrix_x4_trans(r0, r1, r2, r3, vaddr + oVl);
                mma_bf16a(O[2 * cf],     ah, r0, r1);
                mma_bf16a(O[2 * cf + 1], ah, r2, r3);
            }
        }
    }

    // ---- finalize ----
    float inv0 = 1.f / l0r;
    float inv1 = 1.f / l1r;
    size_t base0 = (((size_t)(b * NN + r0g)) * HH + h) * CC;
    size_t base1 = (((size_t)(b * NN + r1g)) * HH + h) * CC;
    #pragma unroll
    for (int nf = 0; nf < 8; nf++) {
        int col = nf * 8 + 2 * t;
        *(float2*)&out[base0 + col] = make_float2(O[nf][0] * inv0, O[nf][1] * inv0);
        *(float2*)&out[base1 + col] = make_float2(O[nf][2] * inv1, O[nf][3] * inv1);
    }
}

// ---------------- launcher ----------------
extern "C" void kernel_launch(void* const* d_in, const int* in_sizes, int n_in,
                              void* d_out, int out_size)
{
    const float* s    = (const float*)d_in[0];
    const float* pair = (const float*)d_in[1];
    const int*   segs = (const int*)d_in[2];
    const int*   pos  = (const int*)d_in[3];
    const float* Wq   = (const float*)d_in[4];
    const float* Wk   = (const float*)d_in[5];
    const float* Wv   = (const float*)d_in[6];
    const float* Wb   = (const float*)d_in[7];
    float* out = (float*)d_out;

    cudaFuncSetAttribute(qkv_mma_kernel, cudaFuncAttributeMaxDynamicSharedMemorySize,
                         QKV_SMEM);
    dim3 g1((HH * CC) / 128, (BB * NN) / 128, 3);
    qkv_mma_kernel<<<g1, 256, QKV_SMEM>>>(s, Wq, Wk, Wv);

    rope_kernel<<<(BB * NN * HH * 32) / 256, 256>>>(pos);

    dim3 g2(NN / 32, NN, BB);
    bias_kernel<<<g2, 256>>>(pair, Wb, segs);

    cudaFuncSetAttribute(attn_mma_kernel, cudaFuncAttributeMaxDynamicSharedMemorySize,
                         ATTN_SMEM);
    dim3 g3(NN / 128, HH, BB);
    attn_mma_kernel<<<g3, 256, ATTN_SMEM>>>(segs, out);
}

// round 7
// speedup vs baseline: 1.8706x; 1.1862x over previous
#include <cuda_runtime.h>
#include <cuda_bf16.h>
#include <math.h>
#include <stdint.h>

#define BB 2
#define NN 1024
#define FSZ 1024
#define FZ 64
#define HH 16
#define CC 64

// ---------------- scratch (device globals: no runtime allocation) ----------------
__device__ float          g_qf[BB*HH*NN*CC];                 // fp32 q, head-major
__device__ float          g_kf[BB*HH*NN*CC];                 // fp32 k, head-major
__device__ __nv_bfloat16  g_q_hi[BB*HH*NN*CC];
__device__ __nv_bfloat16  g_q_lo[BB*HH*NN*CC];
__device__ __nv_bfloat16  g_k_hi[BB*HH*NN*CC];
__device__ __nv_bfloat16  g_k_lo[BB*HH*NN*CC];
__device__ __nv_bfloat16  g_v_hi[BB*HH*NN*CC];
__device__ __nv_bfloat16  g_v_lo[BB*HH*NN*CC];
__device__ __nv_bfloat16  g_s_hi[BB*NN*FSZ];
__device__ __nv_bfloat16  g_s_lo[BB*NN*FSZ];
__device__ __nv_bfloat16  g_wt_hi[3*FSZ*HH*CC];              // [z][n][k]
__device__ __nv_bfloat16  g_wt_lo[3*FSZ*HH*CC];
__device__ __nv_bfloat16  g_bias[(size_t)BB*HH*NN*NN];       // (b,h,q,k)

// ================= helpers =================
__device__ __forceinline__ uint32_t smem_to_u32(const void* p) {
    uint32_t a;
    asm("{ .reg .u64 t; cvta.to.shared.u64 t, %1; cvt.u32.u64 %0, t; }" : "=r"(a) : "l"(p));
    return a;
}
__device__ __forceinline__ uint32_t pack_bf16x2(__nv_bfloat16 a, __nv_bfloat16 b) {
    __nv_bfloat162 t(a, b);
    return *reinterpret_cast<uint32_t*>(&t);
}
__device__ __forceinline__ void split2(float x, __nv_bfloat16& h, __nv_bfloat16& l) {
    h = __float2bfloat16(x);
    l = __float2bfloat16(x - __bfloat162float(h));
}
__device__ __forceinline__ void ldmatrix_x4(uint32_t& r0, uint32_t& r1, uint32_t& r2,
                                            uint32_t& r3, uint32_t addr) {
    asm volatile("ldmatrix.sync.aligned.m8n8.x4.shared.b16 {%0,%1,%2,%3}, [%4];"
                 : "=r"(r0), "=r"(r1), "=r"(r2), "=r"(r3) : "r"(addr));
}
__device__ __forceinline__ void ldmatrix_x4_trans(uint32_t& r0, uint32_t& r1, uint32_t& r2,
                                                  uint32_t& r3, uint32_t addr) {
    asm volatile("ldmatrix.sync.aligned.m8n8.x4.trans.shared.b16 {%0,%1,%2,%3}, [%4];"
                 : "=r"(r0), "=r"(r1), "=r"(r2), "=r"(r3) : "r"(addr));
}
__device__ __forceinline__ void mma_bf16(float* c, uint32_t a0, uint32_t a1, uint32_t a2,
                                         uint32_t a3, uint32_t b0, uint32_t b1) {
    asm volatile(
        "mma.sync.aligned.m16n8k16.row.col.f32.bf16.bf16.f32 "
        "{%0,%1,%2,%3}, {%4,%5,%6,%7}, {%8,%9}, {%0,%1,%2,%3};"
        : "+f"(c[0]), "+f"(c[1]), "+f"(c[2]), "+f"(c[3])
        : "r"(a0), "r"(a1), "r"(a2), "r"(a3), "r"(b0), "r"(b1));
}
__device__ __forceinline__ void mma_bf16a(float* c, const uint32_t* a, uint32_t b0, uint32_t b1) {
    mma_bf16(c, a[0], a[1], a[2], a[3], b0, b1);
}
__device__ __forceinline__ void cp_async16(uint32_t dst, const void* src) {
    asm volatile(
        "{ .reg .u64 g; cvta.to.global.u64 g, %1; cp.async.cg.shared.global [%0], [g], 16; }"
        :: "r"(dst), "l"(src) : "memory");
}
#define CP_COMMIT() asm volatile("cp.async.commit_group;" ::: "memory")
template<int N> __device__ __forceinline__ void cp_wait() {
    asm volatile("cp.async.wait_group %0;" :: "n"(N) : "memory");
}

#define PADB 144                  // padded row stride in bytes (72 bf16)

// ---------------- 0a) split s -> hi/lo bf16 ----------------
__global__ void __launch_bounds__(256) prep_s_kernel(const float* __restrict__ s)
{
    int idx = blockIdx.x * 256 + threadIdx.x;        // 0..524287
    float4 v = *(const float4*)&s[(size_t)idx * 4];
    __nv_bfloat16 h0, l0, h1, l1, h2, l2, h3, l3;
    split2(v.x, h0, l0); split2(v.y, h1, l1);
    split2(v.z, h2, l2); split2(v.w, h3, l3);
    uint2 hv, lv;
    hv.x = pack_bf16x2(h0, h1); hv.y = pack_bf16x2(h2, h3);
    lv.x = pack_bf16x2(l0, l1); lv.y = pack_bf16x2(l2, l3);
    *(uint2*)&g_s_hi[(size_t)idx * 4] = hv;
    *(uint2*)&g_s_lo[(size_t)idx * 4] = lv;
}

// ---------------- 0b) transpose + split W -> Wt hi/lo [z][n][k] ----------------
__global__ void __launch_bounds__(256) prep_w_kernel(
    const float* __restrict__ Wq, const float* __restrict__ Wk, const float* __restrict__ Wv)
{
    const float* W = (blockIdx.z == 0) ? Wq : (blockIdx.z == 1) ? Wk : Wv;
    __shared__ float t[32][33];
    int k0 = blockIdx.y * 32, n0 = blockIdx.x * 32;
    #pragma unroll
    for (int i = 0; i < 4; i++) {
        int ky = threadIdx.y + i * 8;
        t[ky][threadIdx.x] = W[(size_t)(k0 + ky) * (HH * CC) + n0 + threadIdx.x];
    }
    __syncthreads();
    #pragma unroll
    for (int i = 0; i < 4; i++) {
        int ny = threadIdx.y + i * 8;
        float x = t[threadIdx.x][ny];
        __nv_bfloat16 h, l;
        split2(x, h, l);
        size_t adr = ((size_t)blockIdx.z * FSZ + n0 + ny) * FSZ + k0 + threadIdx.x;
        g_wt_hi[adr] = h;
        g_wt_lo[adr] = l;
    }
}

// ---------------- 1) QKV projection: cp.async double-buffered bf16 mma ----------------
#define QTILEB (128 * PADB)               // 18432 B per piece
#define QBUF   (4 * QTILEB)               // 73728 B per chunk buffer
#define QKV_SMEM (2 * QBUF)               // 147456

__device__ __forceinline__ void qkv_issue(uint32_t buf, int z, int m0, int n0, int k0, int tid)
{
    #pragma unroll
    for (int it = 0; it < 16; it++) {
        int idx  = tid + it * 256;
        int a    = idx >> 10;
        int idx2 = idx & 1023;
        int row  = idx2 >> 3;
        int c16  = idx2 & 7;
        const __nv_bfloat16* src;
        if (a == 0)      src = &g_s_hi[(size_t)(m0 + row) * FSZ + k0 + c16 * 8];
        else if (a == 1) src = &g_s_lo[(size_t)(m0 + row) * FSZ + k0 + c16 * 8];
        else if (a == 2) src = &g_wt_hi[((size_t)z * FSZ + n0 + row) * FSZ + k0 + c16 * 8];
        else             src = &g_wt_lo[((size_t)z * FSZ + n0 + row) * FSZ + k0 + c16 * 8];
        cp_async16(buf + (uint32_t)(a * QTILEB + row * PADB + c16 * 16), src);
    }
}

__global__ void __launch_bounds__(256, 1) qkv_mma_kernel()
{
    extern __shared__ char smem[];
    const uint32_t sb = smem_to_u32(smem);
    const int tid  = threadIdx.x;
    const int lane = tid & 31;
    const int wid  = tid >> 5;
    const int g    = lane >> 2;
    const int t    = lane & 3;
    const int z    = blockIdx.z;
    const int m0   = blockIdx.y * 128;
    const int n0   = blockIdx.x * 128;
    const int wm   = (wid >> 1) * 32;
    const int wn   = (wid & 1) * 64;

    float acc[2][8][4];
    #pragma unroll
    for (int i = 0; i < 2; i++)
        #pragma unroll
        for (int j = 0; j < 8; j++)
            #pragma unroll
            for (int u = 0; u < 4; u++) acc[i][j][u] = 0.f;

    const uint32_t aRow  = (uint32_t)(lane & 15);
    const uint32_t aColH = (uint32_t)(lane >> 4) * 16;
    const uint32_t bTile = (uint32_t)(lane >> 3);
    const uint32_t bRow  = (bTile >> 1) * 8 + (uint32_t)(lane & 7);
    const uint32_t bColH = (bTile & 1) * 16;

    qkv_issue(sb, z, m0, n0, 0, tid);
    CP_COMMIT();

    #pragma unroll 1
    for (int c = 0; c < 16; c++) {
        const uint32_t buf = sb + (uint32_t)(c & 1) * QBUF;
        if (c + 1 < 16) {
            qkv_issue(sb + (uint32_t)((c + 1) & 1) * QBUF, z, m0, n0, (c + 1) * 64, tid);
            CP_COMMIT();
            cp_wait<1>();
        } else {
            cp_wait<0>();
        }
        __syncthreads();

        #pragma unroll
        for (int pass = 0; pass < 3; pass++) {
            const uint32_t Ao = buf + (pass == 2 ? QTILEB : 0u);
            const uint32_t Bo = buf + 2u * QTILEB + (pass == 1 ? QTILEB : 0u);
            #pragma unroll
            for (int ks = 0; ks < 4; ks++) {
                const uint32_t kb = (uint32_t)(ks * 32);
                uint32_t af[2][4];
                #pragma unroll
                for (int mf = 0; mf < 2; mf++) {
                    uint32_t addr = Ao + (uint32_t)(wm + mf * 16 + aRow) * PADB + kb + aColH;
                    ldmatrix_x4(af[mf][0], af[mf][1], af[mf][2], af[mf][3], addr);
                }
                uint32_t bf[8][2];
                #pragma unroll
                for (int nf = 0; nf < 8; nf += 2) {
                    uint32_t addr = Bo + (uint32_t)(wn + nf * 8 + bRow) * PADB + kb + bColH;
                    uint32_t r0, r1, r2, r3;
                    ldmatrix_x4(r0, r1, r2, r3, addr);
                    bf[nf][0] = r0;     bf[nf][1] = r1;
                    bf[nf + 1][0] = r2; bf[nf + 1][1] = r3;
                }
                #pragma unroll
                for (int mf = 0; mf < 2; mf++)
                    #pragma unroll
                    for (int nf = 0; nf < 8; nf++)
                        mma_bf16(acc[mf][nf], af[mf][0], af[mf][1], af[mf][2], af[mf][3],
                                 bf[nf][0], bf[nf][1]);
            }
        }
        __syncthreads();
    }

    // epilogue: head-major writes
    #pragma unroll
    for (int mf = 0; mf < 2; mf++) {
        #pragma unroll
        for (int nf = 0; nf < 8; nf++) {
            int row = m0 + wm + mf * 16 + g;
            int b   = row >> 10, n = row & 1023;
            int col = n0 + wn + nf * 8 + 2 * t;
            int h   = col >> 6, cc = col & 63;
            size_t adr0 = ((size_t)(b * HH + h) * NN + n) * CC + cc;
            size_t adr1 = ((size_t)(b * HH + h) * NN + n + 8) * CC + cc;
            if (z == 0) {
                *(float2*)&g_qf[adr0] = make_float2(acc[mf][nf][0], acc[mf][nf][1]);
                *(float2*)&g_qf[adr1] = make_float2(acc[mf][nf][2], acc[mf][nf][3]);
            } else if (z == 1) {
                *(float2*)&g_kf[adr0] = make_float2(acc[mf][nf][0], acc[mf][nf][1]);
                *(float2*)&g_kf[adr1] = make_float2(acc[mf][nf][2], acc[mf][nf][3]);
            } else {
                __nv_bfloat16 h0, l0, h1, l1;
                split2(acc[mf][nf][0], h0, l0); split2(acc[mf][nf][1], h1, l1);
                *(uint32_t*)&g_v_hi[adr0] = pack_bf16x2(h0, h1);
                *(uint32_t*)&g_v_lo[adr0] = pack_bf16x2(l0, l1);
                split2(acc[mf][nf][2], h0, l0); split2(acc[mf][nf][3], h1, l1);
                *(uint32_t*)&g_v_hi[adr1] = pack_bf16x2(h0, h1);
                *(uint32_t*)&g_v_lo[adr1] = pack_bf16x2(l0, l1);
            }
        }
    }
}

// ---------------- 2) RoPE + split q,k -> hi/lo bf16 (head-major) ----------------
__global__ void __launch_bounds__(256) rope_split_kernel(const int* __restrict__ positions)
{
    int idx = blockIdx.x * 256 + threadIdx.x;        // BB*HH*NN*32 = 1M
    int i = idx & 31;
    int n = (idx >> 5) & 1023;
    int h = (idx >> 15) & 15;
    int b = idx >> 19;

    float pos = (float)positions[b * NN + n];
    float ts  = powf(10000.0f, (float)i / 32.0f);
    float ang = pos / ts;
    float sv, cv;
    sincosf(ang, &sv, &cv);

    size_t base = ((size_t)(b * HH + h) * NN + n) * CC;
    {
        float q1 = g_qf[base + i], q2 = g_qf[base + i + 32];
        float o1 = q1 * cv - q2 * sv;
        float o2 = q2 * cv + q1 * sv;
        __nv_bfloat16 hh, ll;
        split2(o1, hh, ll); g_q_hi[base + i] = hh;      g_q_lo[base + i] = ll;
        split2(o2, hh, ll); g_q_hi[base + i + 32] = hh; g_q_lo[base + i + 32] = ll;
    }
    {
        float k1 = g_kf[base + i], k2 = g_kf[base + i + 32];
        float o1 = k1 * cv - k2 * sv;
        float o2 = k2 * cv + k1 * sv;
        __nv_bfloat16 hh, ll;
        split2(o1, hh, ll); g_k_hi[base + i] = hh;      g_k_lo[base + i] = ll;
        split2(o2, hh, ll); g_k_hi[base + i + 32] = hh; g_k_lo[base + i + 32] = ll;
    }
}

// ---------------- 3) bias[b,h,q,k] = sum_f pair[b,q,k,f] * Wb[f,h] (bf16 out) --------
__global__ __launch_bounds__(256) void bias_kernel(
    const float* __restrict__ pair,
    const float* __restrict__ Wb,
    const int* __restrict__ seg)
{
    const int k0 = blockIdx.x * 32;
    const int q  = blockIdx.y;
    const int b  = blockIdx.z;
    if (k0 > q) return;
    const int segq = seg[b * NN + q];
    const int khi  = min(k0 + 31, q);
    if (seg[b * NN + khi] != segq) return;

    __shared__ float sp[64 * 33];
    __shared__ float sWb[64 * 16];
    const int tid = threadIdx.x;

    const float* psrc = &pair[(((size_t)b * NN + q) * NN + k0) * FZ];
    #pragma unroll
    for (int p = 0; p < 2; p++) {
        int l  = tid + p * 256;
        int kk = l / 16;
        int f4 = (l % 16) * 4;
        float4 v = *(const float4*)&psrc[(size_t)kk * FZ + f4];
        sp[(f4 + 0) * 33 + kk] = v.x;
        sp[(f4 + 1) * 33 + kk] = v.y;
        sp[(f4 + 2) * 33 + kk] = v.z;
        sp[(f4 + 3) * 33 + kk] = v.w;
    }
    *(float4*)&sWb[tid * 4] = *(const float4*)&Wb[tid * 4];
    __syncthreads();

    const int kk = tid % 32;
    const int h0 = tid / 32;
    float a0 = 0.f, a1 = 0.f;
    #pragma unroll
    for (int f = 0; f < 64; f++) {
        float v = sp[f * 33 + kk];
        a0 = fmaf(v, sWb[f * 16 + h0],     a0);
        a1 = fmaf(v, sWb[f * 16 + h0 + 8], a1);
    }
    g_bias[(((size_t)b * HH + h0)     * NN + q) * NN + k0 + kk] = __float2bfloat16(a0);
    g_bias[(((size_t)b * HH + h0 + 8) * NN + q) * NN + k0 + kk] = __float2bfloat16(a1);
}

// ---------------- 4) flash attention: cp.async pipelined, pre-split operands ---------
#define AQT (128 * PADB)                  // 18432 per Q piece
#define AKT (64 * PADB)                   // 9216 per K/V piece
#define AST (4 * AKT)                     // 36864 per stage
#define O_ST0  (2 * AQT)                  // stage 0 base
#define O_SEG  (2 * AQT + 2 * AST)        // seg[2][64] ints
#define O_LIST (O_SEG + 512)              // tile list (16) + count
#define ATTN_SMEM (O_LIST + 128)

__device__ __forceinline__ void attn_issue(uint32_t stbase, int bh, int k0, int tid)
{
    #pragma unroll
    for (int it = 0; it < 8; it++) {
        int idx  = tid + it * 256;
        int a    = idx >> 9;
        int idx2 = idx & 511;
        int row  = idx2 >> 3;
        int c16  = idx2 & 7;
        size_t e = ((size_t)bh * NN + k0 + row) * CC + c16 * 8;
        const __nv_bfloat16* src;
        if (a == 0)      src = &g_k_hi[e];
        else if (a == 1) src = &g_k_lo[e];
        else if (a == 2) src = &g_v_hi[e];
        else             src = &g_v_lo[e];
        cp_async16(stbase + (uint32_t)(a * AKT + row * PADB + c16 * 16), src);
    }
}

__global__ void __launch_bounds__(256, 1) attn_mma_kernel(
    const int* __restrict__ seg, float* __restrict__ out)
{
    extern __shared__ char smem[];
    const uint32_t sb = smem_to_u32(smem);
    int* tile_list = (int*)(smem + O_LIST);

    const int tid  = threadIdx.x;
    const int lane = tid & 31;
    const int w    = tid >> 5;
    const int g    = lane >> 2;
    const int t    = lane & 3;
    const int qt   = 7 - blockIdx.x;          // heavy tiles first
    const int h    = blockIdx.y;
    const int b    = blockIdx.z;
    const int q0   = qt * 128;
    const int bh   = b * HH + h;
    const float sm_scale = 0.125f;

    const int r0g = q0 + w * 16 + g;
    const int r1g = r0g + 8;
    const int seg_q0 = seg[b * NN + q0];
    const int myseg0 = seg[b * NN + r0g];
    const int myseg1 = seg[b * NN + r1g];
    const int jmax   = 2 * qt + 1;

    // valid tile list
    if (tid < 32) {
        bool valid = (lane <= jmax) && (seg[b * NN + lane * 64 + 63] >= seg_q0);
        uint32_t m = __ballot_sync(0xffffffffu, valid);
        if (valid) tile_list[1 + __popc(m & ((1u << lane) - 1u))] = lane;
        if (lane == 0) tile_list[0] = __popc(m);
    }
    __syncthreads();
    const int T = tile_list[0];

    // prologue: Q (hi/lo) + first tile + its seg in one group
    {
        #pragma unroll
        for (int it = 0; it < 8; it++) {
            int idx  = tid + it * 256;
            int a    = idx >> 10;
            int idx2 = idx & 1023;
            int row  = idx2 >> 3;
            int c16  = idx2 & 7;
            size_t e = ((size_t)bh * NN + q0 + row) * CC + c16 * 8;
            const __nv_bfloat16* src = a ? &g_q_lo[e] : &g_q_hi[e];
            cp_async16(sb + (uint32_t)(a * AQT + row * PADB + c16 * 16), src);
        }
        int k0 = tile_list[1] * 64;
        attn_issue(sb + O_ST0, bh, k0, tid);
        if (tid < 16) cp_async16(sb + O_SEG + tid * 16, &seg[b * NN + k0 + tid * 4]);
        CP_COMMIT();
    }

    float O[8][4];
    #pragma unroll
    for (int nf = 0; nf < 8; nf++)
        #pragma unroll
        for (int u = 0; u < 4; u++) O[nf][u] = 0.f;
    float m0r = -1e30f, m1r = -1e30f, l0r = 0.f, l1r = 0.f;

    const uint32_t aRow  = (uint32_t)(lane & 15);
    const uint32_t aColH = (uint32_t)(lane >> 4) * 16;
    const uint32_t bTile = (uint32_t)(lane >> 3);
    const uint32_t bRow  = (bTile >> 1) * 8 + (uint32_t)(lane & 7);
    const uint32_t bColH = (bTile & 1) * 16;
    const uint32_t vRow  = (bTile & 1) * 8 + (uint32_t)(lane & 7);
    const uint32_t vColH = (uint32_t)(lane >> 4) * 16;

    const __nv_bfloat16* bias0 = &g_bias[((size_t)bh * NN + r0g) * NN];
    const __nv_bfloat16* bias1 = &g_bias[((size_t)bh * NN + r1g) * NN];

    uint32_t qh[4][4], ql[4][4];

    #pragma unroll 1
    for (int i = 0; i < T; i++) {
        const int st = i & 1;
        const uint32_t stb = sb + O_ST0 + (uint32_t)st * AST;
        if (i + 1 < T) {
            int k0n = tile_list[1 + i + 1] * 64;
            attn_issue(sb + O_ST0 + (uint32_t)(st ^ 1) * AST, bh, k0n, tid);
            if (tid < 16)
                cp_async16(sb + O_SEG + (uint32_t)(st ^ 1) * 256 + tid * 16,
                           &seg[b * NN + k0n + tid * 4]);
            CP_COMMIT();
            cp_wait<1>();
        } else {
            cp_wait<0>();
        }
        __syncthreads();

        if (i == 0) {   // hoist Q fragments (Q smem ready with first group)
            #pragma unroll
            for (int ks = 0; ks < 4; ks++) {
                uint32_t qaddr = sb + (uint32_t)(w * 16 + aRow) * PADB
                               + (uint32_t)(ks * 32) + aColH;
                ldmatrix_x4(qh[ks][0], qh[ks][1], qh[ks][2], qh[ks][3], qaddr);
                ldmatrix_x4(ql[ks][0], ql[ks][1], ql[ks][2], ql[ks][3], qaddr + AQT);
            }
        }

        const int k0 = tile_list[1 + i] * 64;
        const int* seg_ks = (const int*)(smem + O_SEG + st * 256);

        // ---- S = Q K^T (3-pass split) ----
        float S[8][4];
        #pragma unroll
        for (int nf = 0; nf < 8; nf++)
            #pragma unroll
            for (int u = 0; u < 4; u++) S[nf][u] = 0.f;

        #pragma unroll
        for (int ks = 0; ks < 4; ks++) {
            const uint32_t kb = (uint32_t)(ks * 32);
            #pragma unroll
            for (int np = 0; np < 4; np++) {
                uint32_t kaddr = stb + (uint32_t)(np * 16 + bRow) * PADB + kb + bColH;
                uint32_t r0, r1, r2, r3;
                ldmatrix_x4(r0, r1, r2, r3, kaddr);              // K hi
                mma_bf16a(S[2 * np],     qh[ks], r0, r1);
                mma_bf16a(S[2 * np + 1], qh[ks], r2, r3);
                mma_bf16a(S[2 * np],     ql[ks], r0, r1);
                mma_bf16a(S[2 * np + 1], ql[ks], r2, r3);
                ldmatrix_x4(r0, r1, r2, r3, kaddr + AKT);        // K lo
                mma_bf16a(S[2 * np],     qh[ks], r0, r1);
                mma_bf16a(S[2 * np + 1], qh[ks], r2, r3);
            }
        }

        // ---- mask + bias + online softmax ----
        float mx0 = -1e30f, mx1 = -1e30f;
        #pragma unroll
        for (int nf = 0; nf < 8; nf++) {
            int cl = nf * 8 + 2 * t;
            int cg = k0 + cl;
            __nv_bfloat162 bb0 = *(const __nv_bfloat162*)&bias0[cg];
            __nv_bfloat162 bb1 = *(const __nv_bfloat162*)&bias1[cg];
            int sk0 = seg_ks[cl], sk1 = seg_ks[cl + 1];
            bool v00 = (cg     <= r0g) && (sk0 == myseg0);
            bool v01 = (cg + 1 <= r0g) && (sk1 == myseg0);
            bool v10 = (cg     <= r1g) && (sk0 == myseg1);
            bool v11 = (cg + 1 <= r1g) && (sk1 == myseg1);
            S[nf][0] = v00 ? fmaf(S[nf][0], sm_scale, __bfloat162float(bb0.x)) : -1e30f;
            S[nf][1] = v01 ? fmaf(S[nf][1], sm_scale, __bfloat162float(bb0.y)) : -1e30f;
            S[nf][2] = v10 ? fmaf(S[nf][2], sm_scale, __bfloat162float(bb1.x)) : -1e30f;
            S[nf][3] = v11 ? fmaf(S[nf][3], sm_scale, __bfloat162float(bb1.y)) : -1e30f;
            mx0 = fmaxf(mx0, fmaxf(S[nf][0], S[nf][1]));
            mx1 = fmaxf(mx1, fmaxf(S[nf][2], S[nf][3]));
        }
        mx0 = fmaxf(mx0, __shfl_xor_sync(0xffffffffu, mx0, 1));
        mx0 = fmaxf(mx0, __shfl_xor_sync(0xffffffffu, mx0, 2));
        mx1 = fmaxf(mx1, __shfl_xor_sync(0xffffffffu, mx1, 1));
        mx1 = fmaxf(mx1, __shfl_xor_sync(0xffffffffu, mx1, 2));

        float mn0 = fmaxf(m0r, mx0), mn1 = fmaxf(m1r, mx1);
        float al0 = __expf(m0r - mn0), al1 = __expf(m1r - mn1);
        m0r = mn0; m1r = mn1;

        float sum0 = 0.f, sum1 = 0.f;
        #pragma unroll
        for (int nf = 0; nf < 8; nf++) {
            float p0 = (S[nf][0] > -1e29f) ? __expf(S[nf][0] - mn0) : 0.f;
            float p1 = (S[nf][1] > -1e29f) ? __expf(S[nf][1] - mn0) : 0.f;
            float p2 = (S[nf][2] > -1e29f) ? __expf(S[nf][2] - mn1) : 0.f;
            float p3 = (S[nf][3] > -1e29f) ? __expf(S[nf][3] - mn1) : 0.f;
            S[nf][0] = p0; S[nf][1] = p1; S[nf][2] = p2; S[nf][3] = p3;
            sum0 += p0 + p1; sum1 += p2 + p3;
        }
        sum0 += __shfl_xor_sync(0xffffffffu, sum0, 1);
        sum0 += __shfl_xor_sync(0xffffffffu, sum0, 2);
        sum1 += __shfl_xor_sync(0xffffffffu, sum1, 1);
        sum1 += __shfl_xor_sync(0xffffffffu, sum1, 2);
        l0r = l0r * al0 + sum0;
        l1r = l1r * al1 + sum1;

        #pragma unroll
        for (int nf = 0; nf < 8; nf++) {
            O[nf][0] *= al0; O[nf][1] *= al0;
            O[nf][2] *= al1; O[nf][3] *= al1;
        }

        // ---- O += P V (3-pass split, V via ldmatrix.trans) ----
        #pragma unroll
        for (int kf = 0; kf < 4; kf++) {
            uint32_t ah[4], al[4];
            {
                __nv_bfloat16 h0, l0, h1, l1;
                split2(S[2 * kf][0], h0, l0); split2(S[2 * kf][1], h1, l1);
                ah[0] = pack_bf16x2(h0, h1);  al[0] = pack_bf16x2(l0, l1);
                split2(S[2 * kf][2], h0, l0); split2(S[2 * kf][3], h1, l1);
                ah[1] = pack_bf16x2(h0, h1);  al[1] = pack_bf16x2(l0, l1);
                split2(S[2 * kf + 1][0], h0, l0); split2(S[2 * kf + 1][1], h1, l1);
                ah[2] = pack_bf16x2(h0, h1);  al[2] = pack_bf16x2(l0, l1);
                split2(S[2 * kf + 1][2], h0, l0); split2(S[2 * kf + 1][3], h1, l1);
                ah[3] = pack_bf16x2(h0, h1);  al[3] = pack_bf16x2(l0, l1);
            }
            #pragma unroll
            for (int cf = 0; cf < 4; cf++) {
                uint32_t vaddr = stb + 2u * AKT + (uint32_t)(kf * 16 + vRow) * PADB
                               + (uint32_t)(cf * 32) + vColH;
                uint32_t r0, r1, r2, r3;
                ldmatrix_x4_trans(r0, r1, r2, r3, vaddr);        // V hi
                mma_bf16a(O[2 * cf],     ah, r0, r1);
                mma_bf16a(O[2 * cf + 1], ah, r2, r3);
                mma_bf16a(O[2 * cf],     al, r0, r1);
                mma_bf16a(O[2 * cf + 1], al, r2, r3);
                ldmatrix_x4_trans(r0, r1, r2, r3, vaddr + AKT);  // V lo
                mma_bf16a(O[2 * cf],     ah, r0, r1);
                mma_bf16a(O[2 * cf + 1], ah, r2, r3);
            }
        }
        __syncthreads();
    }

    // ---- finalize ----
    float inv0 = 1.f / l0r;
    float inv1 = 1.f / l1r;
    size_t base0 = (((size_t)(b * NN + r0g)) * HH + h) * CC;
    size_t base1 = (((size_t)(b * NN + r1g)) * HH + h) * CC;
    #pragma unroll
    for (int nf = 0; nf < 8; nf++) {
        int col = nf * 8 + 2 * t;
        *(float2*)&out[base0 + col] = make_float2(O[nf][0] * inv0, O[nf][1] * inv0);
        *(float2*)&out[base1 + col] = make_float2(O[nf][2] * inv1, O[nf][3] * inv1);
    }
}

// ---------------- launcher ----------------
extern "C" void kernel_launch(void* const* d_in, const int* in_sizes, int n_in,
                              void* d_out, int out_size)
{
    const float* s    = (const float*)d_in[0];
    const float* pair = (const float*)d_in[1];
    const int*   segs = (const int*)d_in[2];
    const int*   pos  = (const int*)d_in[3];
    const float* Wq   = (const float*)d_in[4];
    const float* Wk   = (const float*)d_in[5];
    const float* Wv   = (const float*)d_in[6];
    const float* Wb   = (const float*)d_in[7];
    float* out = (float*)d_out;

    prep_s_kernel<<<2048, 256>>>(s);
    prep_w_kernel<<<dim3(32, 32, 3), dim3(32, 8)>>>(Wq, Wk, Wv);

    cudaFuncSetAttribute(qkv_mma_kernel, cudaFuncAttributeMaxDynamicSharedMemorySize,
                         QKV_SMEM);
    qkv_mma_kernel<<<dim3(8, 16, 3), 256, QKV_SMEM>>>();

    rope_split_kernel<<<4096, 256>>>(pos);

    bias_kernel<<<dim3(NN / 32, NN, BB), 256>>>(pair, Wb, segs);

    cudaFuncSetAttribute(attn_mma_kernel, cudaFuncAttributeMaxDynamicSharedMemorySize,
                         ATTN_SMEM);
    attn_mma_kernel<<<dim3(8, HH, BB), 256, ATTN_SMEM>>>(segs, out);
}

// round 8
// speedup vs baseline: 2.1070x; 1.1264x over previous
#include <cuda_runtime.h>
#include <cuda_bf16.h>
#include <math.h>
#include <stdint.h>

#define BB 2
#define NN 1024
#define FSZ 1024
#define FZ 64
#define HH 16
#define CC 64

// ---------------- scratch (device globals: no runtime allocation) ----------------
__device__ float          g_qf[BB*HH*NN*CC];                 // fp32 q, head-major
__device__ float          g_kf[BB*HH*NN*CC];                 // fp32 k, head-major
__device__ __nv_bfloat16  g_q_hi[BB*HH*NN*CC];
__device__ __nv_bfloat16  g_q_lo[BB*HH*NN*CC];
__device__ __nv_bfloat16  g_k_hi[BB*HH*NN*CC];
__device__ __nv_bfloat16  g_k_lo[BB*HH*NN*CC];
__device__ __nv_bfloat16  g_v_hi[BB*HH*NN*CC];
__device__ __nv_bfloat16  g_v_lo[BB*HH*NN*CC];
__device__ __nv_bfloat16  g_s_hi[BB*NN*FSZ];
__device__ __nv_bfloat16  g_s_lo[BB*NN*FSZ];
__device__ __nv_bfloat16  g_wt_hi[3*FSZ*HH*CC];              // [z][n][k]
__device__ __nv_bfloat16  g_wt_lo[3*FSZ*HH*CC];
__device__ __nv_bfloat16  g_bias[(size_t)BB*HH*NN*NN];       // (b,h,q,k)

// ================= helpers =================
__device__ __forceinline__ uint32_t smem_to_u32(const void* p) {
    uint32_t a;
    asm("{ .reg .u64 t; cvta.to.shared.u64 t, %1; cvt.u32.u64 %0, t; }" : "=r"(a) : "l"(p));
    return a;
}
__device__ __forceinline__ uint32_t pack_bf16x2(__nv_bfloat16 a, __nv_bfloat16 b) {
    __nv_bfloat162 t(a, b);
    return *reinterpret_cast<uint32_t*>(&t);
}
__device__ __forceinline__ void split2(float x, __nv_bfloat16& h, __nv_bfloat16& l) {
    h = __float2bfloat16(x);
    l = __float2bfloat16(x - __bfloat162float(h));
}
__device__ __forceinline__ void ldmatrix_x4(uint32_t& r0, uint32_t& r1, uint32_t& r2,
                                            uint32_t& r3, uint32_t addr) {
    asm volatile("ldmatrix.sync.aligned.m8n8.x4.shared.b16 {%0,%1,%2,%3}, [%4];"
                 : "=r"(r0), "=r"(r1), "=r"(r2), "=r"(r3) : "r"(addr));
}
__device__ __forceinline__ void ldmatrix_x4_trans(uint32_t& r0, uint32_t& r1, uint32_t& r2,
                                                  uint32_t& r3, uint32_t addr) {
    asm volatile("ldmatrix.sync.aligned.m8n8.x4.trans.shared.b16 {%0,%1,%2,%3}, [%4];"
                 : "=r"(r0), "=r"(r1), "=r"(r2), "=r"(r3) : "r"(addr));
}
__device__ __forceinline__ void mma_bf16(float* c, uint32_t a0, uint32_t a1, uint32_t a2,
                                         uint32_t a3, uint32_t b0, uint32_t b1) {
    asm volatile(
        "mma.sync.aligned.m16n8k16.row.col.f32.bf16.bf16.f32 "
        "{%0,%1,%2,%3}, {%4,%5,%6,%7}, {%8,%9}, {%0,%1,%2,%3};"
        : "+f"(c[0]), "+f"(c[1]), "+f"(c[2]), "+f"(c[3])
        : "r"(a0), "r"(a1), "r"(a2), "r"(a3), "r"(b0), "r"(b1));
}
__device__ __forceinline__ void mma_bf16a(float* c, const uint32_t* a, uint32_t b0, uint32_t b1) {
    mma_bf16(c, a[0], a[1], a[2], a[3], b0, b1);
}
__device__ __forceinline__ void cp_async16(uint32_t dst, const void* src) {
    asm volatile(
        "{ .reg .u64 g; cvta.to.global.u64 g, %1; cp.async.cg.shared.global [%0], [g], 16; }"
        :: "r"(dst), "l"(src) : "memory");
}
#define CP_COMMIT() asm volatile("cp.async.commit_group;" ::: "memory")
template<int N> __device__ __forceinline__ void cp_wait() {
    asm volatile("cp.async.wait_group %0;" :: "n"(N) : "memory");
}

#define PADB 144                  // padded row stride in bytes (72 bf16)

// ---------------- 0a) split s -> hi/lo bf16 ----------------
__global__ void __launch_bounds__(256) prep_s_kernel(const float* __restrict__ s)
{
    int idx = blockIdx.x * 256 + threadIdx.x;        // 0..524287
    float4 v = *(const float4*)&s[(size_t)idx * 4];
    __nv_bfloat16 h0, l0, h1, l1, h2, l2, h3, l3;
    split2(v.x, h0, l0); split2(v.y, h1, l1);
    split2(v.z, h2, l2); split2(v.w, h3, l3);
    uint2 hv, lv;
    hv.x = pack_bf16x2(h0, h1); hv.y = pack_bf16x2(h2, h3);
    lv.x = pack_bf16x2(l0, l1); lv.y = pack_bf16x2(l2, l3);
    *(uint2*)&g_s_hi[(size_t)idx * 4] = hv;
    *(uint2*)&g_s_lo[(size_t)idx * 4] = lv;
}

// ---------------- 0b) transpose + split W -> Wt hi/lo [z][n][k] ----------------
__global__ void __launch_bounds__(256) prep_w_kernel(
    const float* __restrict__ Wq, const float* __restrict__ Wk, const float* __restrict__ Wv)
{
    const float* W = (blockIdx.z == 0) ? Wq : (blockIdx.z == 1) ? Wk : Wv;
    __shared__ float t[32][33];
    int k0 = blockIdx.y * 32, n0 = blockIdx.x * 32;
    #pragma unroll
    for (int i = 0; i < 4; i++) {
        int ky = threadIdx.y + i * 8;
        t[ky][threadIdx.x] = W[(size_t)(k0 + ky) * (HH * CC) + n0 + threadIdx.x];
    }
    __syncthreads();
    #pragma unroll
    for (int i = 0; i < 4; i++) {
        int ny = threadIdx.y + i * 8;
        float x = t[threadIdx.x][ny];
        __nv_bfloat16 h, l;
        split2(x, h, l);
        size_t adr = ((size_t)blockIdx.z * FSZ + n0 + ny) * FSZ + k0 + threadIdx.x;
        g_wt_hi[adr] = h;
        g_wt_lo[adr] = l;
    }
}

// ---------------- 1) QKV projection: cp.async double-buffered bf16 mma ----------------
#define QTILEB (128 * PADB)               // 18432 B per piece
#define QBUF   (4 * QTILEB)               // 73728 B per chunk buffer
#define QKV_SMEM (2 * QBUF)               // 147456

__device__ __forceinline__ void qkv_issue(uint32_t buf, int z, int m0, int n0, int k0, int tid)
{
    #pragma unroll
    for (int it = 0; it < 16; it++) {
        int idx  = tid + it * 256;
        int a    = idx >> 10;
        int idx2 = idx & 1023;
        int row  = idx2 >> 3;
        int c16  = idx2 & 7;
        const __nv_bfloat16* src;
        if (a == 0)      src = &g_s_hi[(size_t)(m0 + row) * FSZ + k0 + c16 * 8];
        else if (a == 1) src = &g_s_lo[(size_t)(m0 + row) * FSZ + k0 + c16 * 8];
        else if (a == 2) src = &g_wt_hi[((size_t)z * FSZ + n0 + row) * FSZ + k0 + c16 * 8];
        else             src = &g_wt_lo[((size_t)z * FSZ + n0 + row) * FSZ + k0 + c16 * 8];
        cp_async16(buf + (uint32_t)(a * QTILEB + row * PADB + c16 * 16), src);
    }
}

__global__ void __launch_bounds__(256, 1) qkv_mma_kernel()
{
    extern __shared__ char smem[];
    const uint32_t sb = smem_to_u32(smem);
    const int tid  = threadIdx.x;
    const int lane = tid & 31;
    const int wid  = tid >> 5;
    const int g    = lane >> 2;
    const int t    = lane & 3;
    const int z    = blockIdx.z;
    const int m0   = blockIdx.y * 128;
    const int n0   = blockIdx.x * 128;
    const int wm   = (wid >> 1) * 32;
    const int wn   = (wid & 1) * 64;

    float acc[2][8][4];
    #pragma unroll
    for (int i = 0; i < 2; i++)
        #pragma unroll
        for (int j = 0; j < 8; j++)
            #pragma unroll
            for (int u = 0; u < 4; u++) acc[i][j][u] = 0.f;

    const uint32_t aRow  = (uint32_t)(lane & 15);
    const uint32_t aColH = (uint32_t)(lane >> 4) * 16;
    const uint32_t bTile = (uint32_t)(lane >> 3);
    const uint32_t bRow  = (bTile >> 1) * 8 + (uint32_t)(lane & 7);
    const uint32_t bColH = (bTile & 1) * 16;

    qkv_issue(sb, z, m0, n0, 0, tid);
    CP_COMMIT();

    #pragma unroll 1
    for (int c = 0; c < 16; c++) {
        const uint32_t buf = sb + (uint32_t)(c & 1) * QBUF;
        if (c + 1 < 16) {
            qkv_issue(sb + (uint32_t)((c + 1) & 1) * QBUF, z, m0, n0, (c + 1) * 64, tid);
            CP_COMMIT();
            cp_wait<1>();
        } else {
            cp_wait<0>();
        }
        __syncthreads();

        #pragma unroll
        for (int pass = 0; pass < 3; pass++) {
            const uint32_t Ao = buf + (pass == 2 ? QTILEB : 0u);
            const uint32_t Bo = buf + 2u * QTILEB + (pass == 1 ? QTILEB : 0u);
            #pragma unroll
            for (int ks = 0; ks < 4; ks++) {
                const uint32_t kb = (uint32_t)(ks * 32);
                uint32_t af[2][4];
                #pragma unroll
                for (int mf = 0; mf < 2; mf++) {
                    uint32_t addr = Ao + (uint32_t)(wm + mf * 16 + aRow) * PADB + kb + aColH;
                    ldmatrix_x4(af[mf][0], af[mf][1], af[mf][2], af[mf][3], addr);
                }
                uint32_t bf[8][2];
                #pragma unroll
                for (int nf = 0; nf < 8; nf += 2) {
                    uint32_t addr = Bo + (uint32_t)(wn + nf * 8 + bRow) * PADB + kb + bColH;
                    uint32_t r0, r1, r2, r3;
                    ldmatrix_x4(r0, r1, r2, r3, addr);
                    bf[nf][0] = r0;     bf[nf][1] = r1;
                    bf[nf + 1][0] = r2; bf[nf + 1][1] = r3;
                }
                #pragma unroll
                for (int mf = 0; mf < 2; mf++)
                    #pragma unroll
                    for (int nf = 0; nf < 8; nf++)
                        mma_bf16(acc[mf][nf], af[mf][0], af[mf][1], af[mf][2], af[mf][3],
                                 bf[nf][0], bf[nf][1]);
            }
        }
        __syncthreads();
    }

    // epilogue: head-major writes
    #pragma unroll
    for (int mf = 0; mf < 2; mf++) {
        #pragma unroll
        for (int nf = 0; nf < 8; nf++) {
            int row = m0 + wm + mf * 16 + g;
            int b   = row >> 10, n = row & 1023;
            int col = n0 + wn + nf * 8 + 2 * t;
            int h   = col >> 6, cc = col & 63;
            size_t adr0 = ((size_t)(b * HH + h) * NN + n) * CC + cc;
            size_t adr1 = ((size_t)(b * HH + h) * NN + n + 8) * CC + cc;
            if (z == 0) {
                *(float2*)&g_qf[adr0] = make_float2(acc[mf][nf][0], acc[mf][nf][1]);
                *(float2*)&g_qf[adr1] = make_float2(acc[mf][nf][2], acc[mf][nf][3]);
            } else if (z == 1) {
                *(float2*)&g_kf[adr0] = make_float2(acc[mf][nf][0], acc[mf][nf][1]);
                *(float2*)&g_kf[adr1] = make_float2(acc[mf][nf][2], acc[mf][nf][3]);
            } else {
                __nv_bfloat16 h0, l0, h1, l1;
                split2(acc[mf][nf][0], h0, l0); split2(acc[mf][nf][1], h1, l1);
                *(uint32_t*)&g_v_hi[adr0] = pack_bf16x2(h0, h1);
                *(uint32_t*)&g_v_lo[adr0] = pack_bf16x2(l0, l1);
                split2(acc[mf][nf][2], h0, l0); split2(acc[mf][nf][3], h1, l1);
                *(uint32_t*)&g_v_hi[adr1] = pack_bf16x2(h0, h1);
                *(uint32_t*)&g_v_lo[adr1] = pack_bf16x2(l0, l1);
            }
        }
    }
}

// ---------------- 2) RoPE + split q,k -> hi/lo bf16 (head-major) ----------------
__global__ void __launch_bounds__(256) rope_split_kernel(const int* __restrict__ positions)
{
    int idx = blockIdx.x * 256 + threadIdx.x;        // BB*HH*NN*32 = 1M
    int i = idx & 31;
    int n = (idx >> 5) & 1023;
    int h = (idx >> 15) & 15;
    int b = idx >> 19;

    float pos = (float)positions[b * NN + n];
    float ts  = powf(10000.0f, (float)i / 32.0f);
    float ang = pos / ts;
    float sv, cv;
    sincosf(ang, &sv, &cv);

    size_t base = ((size_t)(b * HH + h) * NN + n) * CC;
    {
        float q1 = g_qf[base + i], q2 = g_qf[base + i + 32];
        float o1 = q1 * cv - q2 * sv;
        float o2 = q2 * cv + q1 * sv;
        __nv_bfloat16 hh, ll;
        split2(o1, hh, ll); g_q_hi[base + i] = hh;      g_q_lo[base + i] = ll;
        split2(o2, hh, ll); g_q_hi[base + i + 32] = hh; g_q_lo[base + i + 32] = ll;
    }
    {
        float k1 = g_kf[base + i], k2 = g_kf[base + i + 32];
        float o1 = k1 * cv - k2 * sv;
        float o2 = k2 * cv + k1 * sv;
        __nv_bfloat16 hh, ll;
        split2(o1, hh, ll); g_k_hi[base + i] = hh;      g_k_lo[base + i] = ll;
        split2(o2, hh, ll); g_k_hi[base + i + 32] = hh; g_k_lo[base + i + 32] = ll;
    }
}

// ---------------- 3) bias via streaming split-bf16 mma over contiguous k range -------
// bias[b,h,q,k] = sum_f pair[b,q,k,f] * Wb[f,h].  A = Wb^T (m=16 heads, hoisted to
// regs), B = pair rows (n=k).  Valid k range per q is contiguous (sorted segments +
// causal): [lower_bound(seg,segq), q].  One block per (b,q), 128-k chunks.
#define BPAIRT (128 * PADB)               // 18432 per pair piece (hi or lo)
#define O_WBH  (2 * BPAIRT)
#define O_WBL  (O_WBH + 16 * PADB)
#define BIAS_SMEM (O_WBL + 16 * PADB)     // 41472

__global__ void __launch_bounds__(256) bias_mma_kernel(
    const float* __restrict__ pair,
    const float* __restrict__ Wb,
    const int* __restrict__ seg)
{
    __shared__ char smem[BIAS_SMEM];
    const uint32_t sb = smem_to_u32(smem);
    const int tid  = threadIdx.x;
    const int lane = tid & 31;
    const int w    = tid >> 5;
    const int g    = lane >> 2;
    const int t    = lane & 3;
    const int bx   = blockIdx.x;
    const int b    = bx >> 10;
    const int q    = 1023 - (bx & 1023);       // heavy rows first
    const int segq = seg[b * NN + q];

    // stage Wb^T hi/lo (16 h rows x 64 f cols)
    if (tid < 64) {
        int f = tid;
        #pragma unroll
        for (int h = 0; h < 16; h++) {
            float x = Wb[f * HH + h];
            __nv_bfloat16 hh, ll;
            split2(x, hh, ll);
            *(__nv_bfloat16*)(smem + O_WBH + h * PADB + f * 2) = hh;
            *(__nv_bfloat16*)(smem + O_WBL + h * PADB + f * 2) = ll;
        }
    }

    // lower_bound for segment start (seg sorted along n)
    int lo = 0, hi = q;
    while (lo < hi) {
        int mid = (lo + hi) >> 1;
        if (seg[b * NN + mid] < segq) lo = mid + 1; else hi = mid;
    }
    const int kstart = lo & ~127;
    __syncthreads();

    // hoist Wb^T A-fragments (whole K=64: 4 k-steps, hi+lo)
    const uint32_t aRow  = (uint32_t)(lane & 15);
    const uint32_t aColH = (uint32_t)(lane >> 4) * 16;
    uint32_t ah[4][4], alr[4][4];
    #pragma unroll
    for (int ks = 0; ks < 4; ks++) {
        uint32_t addr = sb + O_WBH + aRow * PADB + (uint32_t)(ks * 32) + aColH;
        ldmatrix_x4(ah[ks][0],  ah[ks][1],  ah[ks][2],  ah[ks][3],  addr);
        ldmatrix_x4(alr[ks][0], alr[ks][1], alr[ks][2], alr[ks][3], addr + 16 * PADB);
    }

    const uint32_t bTile = (uint32_t)(lane >> 3);
    const uint32_t bRow  = (bTile >> 1) * 8 + (uint32_t)(lane & 7);
    const uint32_t bColH = (bTile & 1) * 16;
    const float* psrc = &pair[((size_t)(b * NN + q)) * NN * FZ];

    #pragma unroll 1
    for (int k0 = kstart; k0 <= q; k0 += 128) {
        __syncthreads();
        // load pair chunk (128 k x 64 f fp32) -> hi/lo bf16 smem
        #pragma unroll
        for (int it = 0; it < 8; it++) {
            int idx = tid + it * 256;
            int r   = idx >> 4;
            int c4  = (idx & 15) << 2;
            int row = k0 + r; if (row > 1023) row = 1023;     // safe in-slab read
            float4 v = *(const float4*)&psrc[(size_t)row * FZ + c4];
            __nv_bfloat16 hx, lx, hy, ly, hz, lz, hw, lw;
            split2(v.x, hx, lx); split2(v.y, hy, ly);
            split2(v.z, hz, lz); split2(v.w, hw, lw);
            uint32_t off = (uint32_t)(r * PADB + c4 * 2);
            *(uint32_t*)(smem + off)              = pack_bf16x2(hx, hy);
            *(uint32_t*)(smem + off + 4)          = pack_bf16x2(hz, hw);
            *(uint32_t*)(smem + BPAIRT + off)     = pack_bf16x2(lx, ly);
            *(uint32_t*)(smem + BPAIRT + off + 4) = pack_bf16x2(lz, lw);
        }
        __syncthreads();

        // warp w computes 16 k rows; 3-pass split mma
        float S[2][4];
        #pragma unroll
        for (int nf = 0; nf < 2; nf++)
            #pragma unroll
            for (int u = 0; u < 4; u++) S[nf][u] = 0.f;
        #pragma unroll
        for (int ks = 0; ks < 4; ks++) {
            uint32_t baddr = sb + (uint32_t)(w * 16 + bRow) * PADB
                           + (uint32_t)(ks * 32) + bColH;
            uint32_t r0, r1, r2, r3;
            ldmatrix_x4(r0, r1, r2, r3, baddr);            // pair hi
            mma_bf16a(S[0], ah[ks],  r0, r1);
            mma_bf16a(S[1], ah[ks],  r2, r3);
            mma_bf16a(S[0], alr[ks], r0, r1);
            mma_bf16a(S[1], alr[ks], r2, r3);
            ldmatrix_x4(r0, r1, r2, r3, baddr + BPAIRT);   // pair lo
            mma_bf16a(S[0], ah[ks],  r0, r1);
            mma_bf16a(S[1], ah[ks],  r2, r3);
        }

        // store: thread holds (h=g, k=2t..2t+1) and (h=g+8, ...) per nf
        #pragma unroll
        for (int nf = 0; nf < 2; nf++) {
            int k = k0 + w * 16 + nf * 8 + 2 * t;
            if (k <= 1023) {
                __nv_bfloat16 x0 = __float2bfloat16(S[nf][0]);
                __nv_bfloat16 x1 = __float2bfloat16(S[nf][1]);
                __nv_bfloat16 x2 = __float2bfloat16(S[nf][2]);
                __nv_bfloat16 x3 = __float2bfloat16(S[nf][3]);
                *(uint32_t*)&g_bias[(((size_t)(b * HH + g))     * NN + q) * NN + k] =
                    pack_bf16x2(x0, x1);
                *(uint32_t*)&g_bias[(((size_t)(b * HH + g + 8)) * NN + q) * NN + k] =
                    pack_bf16x2(x2, x3);
            }
        }
    }
}

// ---------------- 4) flash attention: cp.async pipelined, pre-split operands ---------
#define AQT (128 * PADB)                  // 18432 per Q piece
#define AKT (64 * PADB)                   // 9216 per K/V piece
#define AST (4 * AKT)                     // 36864 per stage
#define O_ST0  (2 * AQT)                  // stage 0 base
#define O_SEG  (2 * AQT + 2 * AST)        // seg[2][64] ints
#define O_LIST (O_SEG + 512)              // tile list (16) + count
#define ATTN_SMEM (O_LIST + 128)

__device__ __forceinline__ void attn_issue(uint32_t stbase, int bh, int k0, int tid)
{
    #pragma unroll
    for (int it = 0; it < 8; it++) {
        int idx  = tid + it * 256;
        int a    = idx >> 9;
        int idx2 = idx & 511;
        int row  = idx2 >> 3;
        int c16  = idx2 & 7;
        size_t e = ((size_t)bh * NN + k0 + row) * CC + c16 * 8;
        const __nv_bfloat16* src;
        if (a == 0)      src = &g_k_hi[e];
        else if (a == 1) src = &g_k_lo[e];
        else if (a == 2) src = &g_v_hi[e];
        else             src = &g_v_lo[e];
        cp_async16(stbase + (uint32_t)(a * AKT + row * PADB + c16 * 16), src);
    }
}

__global__ void __launch_bounds__(256, 1) attn_mma_kernel(
    const int* __restrict__ seg, float* __restrict__ out)
{
    extern __shared__ char smem[];
    const uint32_t sb = smem_to_u32(smem);
    int* tile_list = (int*)(smem + O_LIST);

    const int tid  = threadIdx.x;
    const int lane = tid & 31;
    const int w    = tid >> 5;
    const int g    = lane >> 2;
    const int t    = lane & 3;
    const int qt   = 7 - blockIdx.x;          // heavy tiles first
    const int h    = blockIdx.y;
    const int b    = blockIdx.z;
    const int q0   = qt * 128;
    const int bh   = b * HH + h;
    const float sm_scale = 0.125f;

    const int r0g = q0 + w * 16 + g;
    const int r1g = r0g + 8;
    const int seg_q0 = seg[b * NN + q0];
    const int myseg0 = seg[b * NN + r0g];
    const int myseg1 = seg[b * NN + r1g];
    const int jmax   = 2 * qt + 1;

    // valid tile list
    if (tid < 32) {
        bool valid = (lane <= jmax) && (seg[b * NN + lane * 64 + 63] >= seg_q0);
        uint32_t m = __ballot_sync(0xffffffffu, valid);
        if (valid) tile_list[1 + __popc(m & ((1u << lane) - 1u))] = lane;
        if (lane == 0) tile_list[0] = __popc(m);
    }
    __syncthreads();
    const int T = tile_list[0];

    // prologue: Q (hi/lo) + first tile + its seg in one group
    {
        #pragma unroll
        for (int it = 0; it < 8; it++) {
            int idx  = tid + it * 256;
            int a    = idx >> 10;
            int idx2 = idx & 1023;
            int row  = idx2 >> 3;
            int c16  = idx2 & 7;
            size_t e = ((size_t)bh * NN + q0 + row) * CC + c16 * 8;
            const __nv_bfloat16* src = a ? &g_q_lo[e] : &g_q_hi[e];
            cp_async16(sb + (uint32_t)(a * AQT + row * PADB + c16 * 16), src);
        }
        int k0 = tile_list[1] * 64;
        attn_issue(sb + O_ST0, bh, k0, tid);
        if (tid < 16) cp_async16(sb + O_SEG + tid * 16, &seg[b * NN + k0 + tid * 4]);
        CP_COMMIT();
    }

    float O[8][4];
    #pragma unroll
    for (int nf = 0; nf < 8; nf++)
        #pragma unroll
        for (int u = 0; u < 4; u++) O[nf][u] = 0.f;
    float m0r = -1e30f, m1r = -1e30f, l0r = 0.f, l1r = 0.f;

    const uint32_t aRow  = (uint32_t)(lane & 15);
    const uint32_t aColH = (uint32_t)(lane >> 4) * 16;
    const uint32_t bTile = (uint32_t)(lane >> 3);
    const uint32_t bRow  = (bTile >> 1) * 8 + (uint32_t)(lane & 7);
    const uint32_t bColH = (bTile & 1) * 16;
    const uint32_t vRow  = (bTile & 1) * 8 + (uint32_t)(lane & 7);
    const uint32_t vColH = (uint32_t)(lane >> 4) * 16;

    const __nv_bfloat16* bias0 = &g_bias[((size_t)bh * NN + r0g) * NN];
    const __nv_bfloat16* bias1 = &g_bias[((size_t)bh * NN + r1g) * NN];

    uint32_t qh[4][4], ql[4][4];

    #pragma unroll 1
    for (int i = 0; i < T; i++) {
        const int st = i & 1;
        const uint32_t stb = sb + O_ST0 + (uint32_t)st * AST;
        if (i + 1 < T) {
            int k0n = tile_list[1 + i + 1] * 64;
            attn_issue(sb + O_ST0 + (uint32_t)(st ^ 1) * AST, bh, k0n, tid);
            if (tid < 16)
                cp_async16(sb + O_SEG + (uint32_t)(st ^ 1) * 256 + tid * 16,
                           &seg[b * NN + k0n + tid * 4]);
            CP_COMMIT();
            cp_wait<1>();
        } else {
            cp_wait<0>();
        }
        __syncthreads();

        if (i == 0) {   // hoist Q fragments (Q smem ready with first group)
            #pragma unroll
            for (int ks = 0; ks < 4; ks++) {
                uint32_t qaddr = sb + (uint32_t)(w * 16 + aRow) * PADB
                               + (uint32_t)(ks * 32) + aColH;
                ldmatrix_x4(qh[ks][0], qh[ks][1], qh[ks][2], qh[ks][3], qaddr);
                ldmatrix_x4(ql[ks][0], ql[ks][1], ql[ks][2], ql[ks][3], qaddr + AQT);
            }
        }

        const int k0 = tile_list[1 + i] * 64;
        const int* seg_ks = (const int*)(smem + O_SEG + st * 256);

        // ---- S = Q K^T (3-pass split) ----
        float S[8][4];
        #pragma unroll
        for (int nf = 0; nf < 8; nf++)
            #pragma unroll
            for (int u = 0; u < 4; u++) S[nf][u] = 0.f;

        #pragma unroll
        for (int ks = 0; ks < 4; ks++) {
            const uint32_t kb = (uint32_t)(ks * 32);
            #pragma unroll
            for (int np = 0; np < 4; np++) {
                uint32_t kaddr = stb + (uint32_t)(np * 16 + bRow) * PADB + kb + bColH;
                uint32_t r0, r1, r2, r3;
                ldmatrix_x4(r0, r1, r2, r3, kaddr);              // K hi
                mma_bf16a(S[2 * np],     qh[ks], r0, r1);
                mma_bf16a(S[2 * np + 1], qh[ks], r2, r3);
                mma_bf16a(S[2 * np],     ql[ks], r0, r1);
                mma_bf16a(S[2 * np + 1], ql[ks], r2, r3);
                ldmatrix_x4(r0, r1, r2, r3, kaddr + AKT);        // K lo
                mma_bf16a(S[2 * np],     qh[ks], r0, r1);
                mma_bf16a(S[2 * np + 1], qh[ks], r2, r3);
            }
        }

        // ---- mask + bias + online softmax ----
        float mx0 = -1e30f, mx1 = -1e30f;
        #pragma unroll
        for (int nf = 0; nf < 8; nf++) {
            int cl = nf * 8 + 2 * t;
            int cg = k0 + cl;
            __nv_bfloat162 bb0 = *(const __nv_bfloat162*)&bias0[cg];
            __nv_bfloat162 bb1 = *(const __nv_bfloat162*)&bias1[cg];
            int sk0 = seg_ks[cl], sk1 = seg_ks[cl + 1];
            bool v00 = (cg     <= r0g) && (sk0 == myseg0);
            bool v01 = (cg + 1 <= r0g) && (sk1 == myseg0);
            bool v10 = (cg     <= r1g) && (sk0 == myseg1);
            bool v11 = (cg + 1 <= r1g) && (sk1 == myseg1);
            S[nf][0] = v00 ? fmaf(S[nf][0], sm_scale, __bfloat162float(bb0.x)) : -1e30f;
            S[nf][1] = v01 ? fmaf(S[nf][1], sm_scale, __bfloat162float(bb0.y)) : -1e30f;
            S[nf][2] = v10 ? fmaf(S[nf][2], sm_scale, __bfloat162float(bb1.x)) : -1e30f;
            S[nf][3] = v11 ? fmaf(S[nf][3], sm_scale, __bfloat162float(bb1.y)) : -1e30f;
            mx0 = fmaxf(mx0, fmaxf(S[nf][0], S[nf][1]));
            mx1 = fmaxf(mx1, fmaxf(S[nf][2], S[nf][3]));
        }
        mx0 = fmaxf(mx0, __shfl_xor_sync(0xffffffffu, mx0, 1));
        mx0 = fmaxf(mx0, __shfl_xor_sync(0xffffffffu, mx0, 2));
        mx1 = fmaxf(mx1, __shfl_xor_sync(0xffffffffu, mx1, 1));
        mx1 = fmaxf(mx1, __shfl_xor_sync(0xffffffffu, mx1, 2));

        float mn0 = fmaxf(m0r, mx0), mn1 = fmaxf(m1r, mx1);
        float al0 = __expf(m0r - mn0), al1 = __expf(m1r - mn1);
        m0r = mn0; m1r = mn1;

        float sum0 = 0.f, sum1 = 0.f;
        #pragma unroll
        for (int nf = 0; nf < 8; nf++) {
            float p0 = (S[nf][0] > -1e29f) ? __expf(S[nf][0] - mn0) : 0.f;
            float p1 = (S[nf][1] > -1e29f) ? __expf(S[nf][1] - mn0) : 0.f;
            float p2 = (S[nf][2] > -1e29f) ? __expf(S[nf][2] - mn1) : 0.f;
            float p3 = (S[nf][3] > -1e29f) ? __expf(S[nf][3] - mn1) : 0.f;
            S[nf][0] = p0; S[nf][1] = p1; S[nf][2] = p2; S[nf][3] = p3;
            sum0 += p0 + p1; sum1 += p2 + p3;
        }
        sum0 += __shfl_xor_sync(0xffffffffu, sum0, 1);
        sum0 += __shfl_xor_sync(0xffffffffu, sum0, 2);
        sum1 += __shfl_xor_sync(0xffffffffu, sum1, 1);
        sum1 += __shfl_xor_sync(0xffffffffu, sum1, 2);
        l0r = l0r * al0 + sum0;
        l1r = l1r * al1 + sum1;

        #pragma unroll
        for (int nf = 0; nf < 8; nf++) {
            O[nf][0] *= al0; O[nf][1] *= al0;
            O[nf][2] *= al1; O[nf][3] *= al1;
        }

        // ---- O += P V (3-pass split, V via ldmatrix.trans) ----
        #pragma unroll
        for (int kf = 0; kf < 4; kf++) {
            uint32_t ah[4], al[4];
            {
                __nv_bfloat16 h0, l0, h1, l1;
                split2(S[2 * kf][0], h0, l0); split2(S[2 * kf][1], h1, l1);
                ah[0] = pack_bf16x2(h0, h1);  al[0] = pack_bf16x2(l0, l1);
                split2(S[2 * kf][2], h0, l0); split2(S[2 * kf][3], h1, l1);
                ah[1] = pack_bf16x2(h0, h1);  al[1] = pack_bf16x2(l0, l1);
                split2(S[2 * kf + 1][0], h0, l0); split2(S[2 * kf + 1][1], h1, l1);
                ah[2] = pack_bf16x2(h0, h1);  al[2] = pack_bf16x2(l0, l1);
                split2(S[2 * kf + 1][2], h0, l0); split2(S[2 * kf + 1][3], h1, l1);
                ah[3] = pack_bf16x2(h0, h1);  al[3] = pack_bf16x2(l0, l1);
            }
            #pragma unroll
            for (int cf = 0; cf < 4; cf++) {
                uint32_t vaddr = stb + 2u * AKT + (uint32_t)(kf * 16 + vRow) * PADB
                               + (uint32_t)(cf * 32) + vColH;
                uint32_t r0, r1, r2, r3;
                ldmatrix_x4_trans(r0, r1, r2, r3, vaddr);        // V hi
                mma_bf16a(O[2 * cf],     ah, r0, r1);
                mma_bf16a(O[2 * cf + 1], ah, r2, r3);
                mma_bf16a(O[2 * cf],     al, r0, r1);
                mma_bf16a(O[2 * cf + 1], al, r2, r3);
                ldmatrix_x4_trans(r0, r1, r2, r3, vaddr + AKT);  // V lo
                mma_bf16a(O[2 * cf],     ah, r0, r1);
                mma_bf16a(O[2 * cf + 1], ah, r2, r3);
            }
        }
        __syncthreads();
    }

    // ---- finalize ----
    float inv0 = 1.f / l0r;
    float inv1 = 1.f / l1r;
    size_t base0 = (((size_t)(b * NN + r0g)) * HH + h) * CC;
    size_t base1 = (((size_t)(b * NN + r1g)) * HH + h) * CC;
    #pragma unroll
    for (int nf = 0; nf < 8; nf++) {
        int col = nf * 8 + 2 * t;
        *(float2*)&out[base0 + col] = make_float2(O[nf][0] * inv0, O[nf][1] * inv0);
        *(float2*)&out[base1 + col] = make_float2(O[nf][2] * inv1, O[nf][3] * inv1);
    }
}

// ---------------- launcher ----------------
extern "C" void kernel_launch(void* const* d_in, const int* in_sizes, int n_in,
                              void* d_out, int out_size)
{
    const float* s    = (const float*)d_in[0];
    const float* pair = (const float*)d_in[1];
    const int*   segs = (const int*)d_in[2];
    const int*   pos  = (const int*)d_in[3];
    const float* Wq   = (const float*)d_in[4];
    const float* Wk   = (const float*)d_in[5];
    const float* Wv   = (const float*)d_in[6];
    const float* Wb   = (const float*)d_in[7];
    float* out = (float*)d_out;

    prep_s_kernel<<<2048, 256>>>(s);
    prep_w_kernel<<<dim3(32, 32, 3), dim3(32, 8)>>>(Wq, Wk, Wv);

    cudaFuncSetAttribute(qkv_mma_kernel, cudaFuncAttributeMaxDynamicSharedMemorySize,
                         QKV_SMEM);
    qkv_mma_kernel<<<dim3(8, 16, 3), 256, QKV_SMEM>>>();

    rope_split_kernel<<<4096, 256>>>(pos);

    bias_mma_kernel<<<BB * NN, 256>>>(pair, Wb, segs);

    cudaFuncSetAttribute(attn_mma_kernel, cudaFuncAttributeMaxDynamicSharedMemorySize,
                         ATTN_SMEM);
    attn_mma_kernel<<<dim3(8, HH, BB), 256, ATTN_SMEM>>>(segs, out);
}

// round 9
// speedup vs baseline: 2.1957x; 1.0421x over previous
#include <cuda_runtime.h>
#include <cuda_bf16.h>
#include <math.h>
#include <stdint.h>

#define BB 2
#define NN 1024
#define FSZ 1024
#define FZ 64
#define HH 16
#define CC 64

// ---------------- scratch (device globals: no runtime allocation) ----------------
__device__ float          g_qf[BB*HH*NN*CC];                 // fp32 q, head-major
__device__ float          g_kf[BB*HH*NN*CC];                 // fp32 k, head-major
__device__ __nv_bfloat16  g_q_hi[BB*HH*NN*CC];
__device__ __nv_bfloat16  g_q_lo[BB*HH*NN*CC];
__device__ __nv_bfloat16  g_k_hi[BB*HH*NN*CC];
__device__ __nv_bfloat16  g_k_lo[BB*HH*NN*CC];
__device__ __nv_bfloat16  g_v_hi[BB*HH*NN*CC];
__device__ __nv_bfloat16  g_v_lo[BB*HH*NN*CC];
__device__ __nv_bfloat16  g_s_hi[BB*NN*FSZ];
__device__ __nv_bfloat16  g_s_lo[BB*NN*FSZ];
__device__ __nv_bfloat16  g_wt_hi[3*FSZ*HH*CC];              // [z][n][k]
__device__ __nv_bfloat16  g_wt_lo[3*FSZ*HH*CC];
__device__ __nv_bfloat16  g_bias[(size_t)BB*HH*NN*NN];       // (b,h,q,k)

// ================= helpers =================
__device__ __forceinline__ uint32_t smem_to_u32(const void* p) {
    uint32_t a;
    asm("{ .reg .u64 t; cvta.to.shared.u64 t, %1; cvt.u32.u64 %0, t; }" : "=r"(a) : "l"(p));
    return a;
}
__device__ __forceinline__ uint32_t pack_bf16x2(__nv_bfloat16 a, __nv_bfloat16 b) {
    __nv_bfloat162 t(a, b);
    return *reinterpret_cast<uint32_t*>(&t);
}
__device__ __forceinline__ uint32_t cvt_bf16x2(float lo, float hi) {
    uint32_t r;
    asm("cvt.rn.bf16x2.f32 %0, %1, %2;" : "=r"(r) : "f"(hi), "f"(lo));
    return r;
}
__device__ __forceinline__ void split2(float x, __nv_bfloat16& h, __nv_bfloat16& l) {
    h = __float2bfloat16(x);
    l = __float2bfloat16(x - __bfloat162float(h));
}
__device__ __forceinline__ void ldmatrix_x4(uint32_t& r0, uint32_t& r1, uint32_t& r2,
                                            uint32_t& r3, uint32_t addr) {
    asm volatile("ldmatrix.sync.aligned.m8n8.x4.shared.b16 {%0,%1,%2,%3}, [%4];"
                 : "=r"(r0), "=r"(r1), "=r"(r2), "=r"(r3) : "r"(addr));
}
__device__ __forceinline__ void ldmatrix_x2(uint32_t& r0, uint32_t& r1, uint32_t addr) {
    asm volatile("ldmatrix.sync.aligned.m8n8.x2.shared.b16 {%0,%1}, [%2];"
                 : "=r"(r0), "=r"(r1) : "r"(addr));
}
__device__ __forceinline__ void ldmatrix_x4_trans(uint32_t& r0, uint32_t& r1, uint32_t& r2,
                                                  uint32_t& r3, uint32_t addr) {
    asm volatile("ldmatrix.sync.aligned.m8n8.x4.trans.shared.b16 {%0,%1,%2,%3}, [%4];"
                 : "=r"(r0), "=r"(r1), "=r"(r2), "=r"(r3) : "r"(addr));
}
__device__ __forceinline__ void mma_bf16(float* c, uint32_t a0, uint32_t a1, uint32_t a2,
                                         uint32_t a3, uint32_t b0, uint32_t b1) {
    asm volatile(
        "mma.sync.aligned.m16n8k16.row.col.f32.bf16.bf16.f32 "
        "{%0,%1,%2,%3}, {%4,%5,%6,%7}, {%8,%9}, {%0,%1,%2,%3};"
        : "+f"(c[0]), "+f"(c[1]), "+f"(c[2]), "+f"(c[3])
        : "r"(a0), "r"(a1), "r"(a2), "r"(a3), "r"(b0), "r"(b1));
}
__device__ __forceinline__ void mma_bf16a(float* c, const uint32_t* a, uint32_t b0, uint32_t b1) {
    mma_bf16(c, a[0], a[1], a[2], a[3], b0, b1);
}
__device__ __forceinline__ void cp_async16(uint32_t dst, const void* src) {
    asm volatile(
        "{ .reg .u64 g; cvta.to.global.u64 g, %1; cp.async.cg.shared.global [%0], [g], 16; }"
        :: "r"(dst), "l"(src) : "memory");
}
#define CP_COMMIT() asm volatile("cp.async.commit_group;" ::: "memory")
template<int N> __device__ __forceinline__ void cp_wait() {
    asm volatile("cp.async.wait_group %0;" :: "n"(N) : "memory");
}

#define PADB 144                  // padded row stride in bytes (72 bf16)

// ---------------- 0a) split s -> hi/lo bf16 ----------------
__global__ void __launch_bounds__(256) prep_s_kernel(const float* __restrict__ s)
{
    int idx = blockIdx.x * 256 + threadIdx.x;        // 0..524287
    float4 v = *(const float4*)&s[(size_t)idx * 4];
    __nv_bfloat16 h0, l0, h1, l1, h2, l2, h3, l3;
    split2(v.x, h0, l0); split2(v.y, h1, l1);
    split2(v.z, h2, l2); split2(v.w, h3, l3);
    uint2 hv, lv;
    hv.x = pack_bf16x2(h0, h1); hv.y = pack_bf16x2(h2, h3);
    lv.x = pack_bf16x2(l0, l1); lv.y = pack_bf16x2(l2, l3);
    *(uint2*)&g_s_hi[(size_t)idx * 4] = hv;
    *(uint2*)&g_s_lo[(size_t)idx * 4] = lv;
}

// ---------------- 0b) transpose + split W -> Wt hi/lo [z][n][k] ----------------
__global__ void __launch_bounds__(256) prep_w_kernel(
    const float* __restrict__ Wq, const float* __restrict__ Wk, const float* __restrict__ Wv)
{
    const float* W = (blockIdx.z == 0) ? Wq : (blockIdx.z == 1) ? Wk : Wv;
    __shared__ float t[32][33];
    int k0 = blockIdx.y * 32, n0 = blockIdx.x * 32;
    #pragma unroll
    for (int i = 0; i < 4; i++) {
        int ky = threadIdx.y + i * 8;
        t[ky][threadIdx.x] = W[(size_t)(k0 + ky) * (HH * CC) + n0 + threadIdx.x];
    }
    __syncthreads();
    #pragma unroll
    for (int i = 0; i < 4; i++) {
        int ny = threadIdx.y + i * 8;
        float x = t[threadIdx.x][ny];
        __nv_bfloat16 h, l;
        split2(x, h, l);
        size_t adr = ((size_t)blockIdx.z * FSZ + n0 + ny) * FSZ + k0 + threadIdx.x;
        g_wt_hi[adr] = h;
        g_wt_lo[adr] = l;
    }
}

// ---------------- 1) QKV projection: cp.async double-buffered bf16 mma ----------------
#define QTILEB (128 * PADB)               // 18432 B per piece
#define QBUF   (4 * QTILEB)               // 73728 B per chunk buffer
#define QKV_SMEM (2 * QBUF)               // 147456

__device__ __forceinline__ void qkv_issue(uint32_t buf, int z, int m0, int n0, int k0, int tid)
{
    #pragma unroll
    for (int it = 0; it < 16; it++) {
        int idx  = tid + it * 256;
        int a    = idx >> 10;
        int idx2 = idx & 1023;
        int row  = idx2 >> 3;
        int c16  = idx2 & 7;
        const __nv_bfloat16* src;
        if (a == 0)      src = &g_s_hi[(size_t)(m0 + row) * FSZ + k0 + c16 * 8];
        else if (a == 1) src = &g_s_lo[(size_t)(m0 + row) * FSZ + k0 + c16 * 8];
        else if (a == 2) src = &g_wt_hi[((size_t)z * FSZ + n0 + row) * FSZ + k0 + c16 * 8];
        else             src = &g_wt_lo[((size_t)z * FSZ + n0 + row) * FSZ + k0 + c16 * 8];
        cp_async16(buf + (uint32_t)(a * QTILEB + row * PADB + c16 * 16), src);
    }
}

__global__ void __launch_bounds__(256, 1) qkv_mma_kernel()
{
    extern __shared__ char smem[];
    const uint32_t sb = smem_to_u32(smem);
    const int tid  = threadIdx.x;
    const int lane = tid & 31;
    const int wid  = tid >> 5;
    const int g    = lane >> 2;
    const int t    = lane & 3;
    const int z    = blockIdx.z;
    const int m0   = blockIdx.y * 128;
    const int n0   = blockIdx.x * 128;
    const int wm   = (wid >> 1) * 32;
    const int wn   = (wid & 1) * 64;

    float acc[2][8][4];
    #pragma unroll
    for (int i = 0; i < 2; i++)
        #pragma unroll
        for (int j = 0; j < 8; j++)
            #pragma unroll
            for (int u = 0; u < 4; u++) acc[i][j][u] = 0.f;

    const uint32_t aRow  = (uint32_t)(lane & 15);
    const uint32_t aColH = (uint32_t)(lane >> 4) * 16;
    const uint32_t bTile = (uint32_t)(lane >> 3);
    const uint32_t bRow  = (bTile >> 1) * 8 + (uint32_t)(lane & 7);
    const uint32_t bColH = (bTile & 1) * 16;

    qkv_issue(sb, z, m0, n0, 0, tid);
    CP_COMMIT();

    #pragma unroll 1
    for (int c = 0; c < 16; c++) {
        const uint32_t buf = sb + (uint32_t)(c & 1) * QBUF;
        if (c + 1 < 16) {
            qkv_issue(sb + (uint32_t)((c + 1) & 1) * QBUF, z, m0, n0, (c + 1) * 64, tid);
            CP_COMMIT();
            cp_wait<1>();
        } else {
            cp_wait<0>();
        }
        __syncthreads();

        #pragma unroll
        for (int pass = 0; pass < 3; pass++) {
            const uint32_t Ao = buf + (pass == 2 ? QTILEB : 0u);
            const uint32_t Bo = buf + 2u * QTILEB + (pass == 1 ? QTILEB : 0u);
            #pragma unroll
            for (int ks = 0; ks < 4; ks++) {
                const uint32_t kb = (uint32_t)(ks * 32);
                uint32_t af[2][4];
                #pragma unroll
                for (int mf = 0; mf < 2; mf++) {
                    uint32_t addr = Ao + (uint32_t)(wm + mf * 16 + aRow) * PADB + kb + aColH;
                    ldmatrix_x4(af[mf][0], af[mf][1], af[mf][2], af[mf][3], addr);
                }
                uint32_t bf[8][2];
                #pragma unroll
                for (int nf = 0; nf < 8; nf += 2) {
                    uint32_t addr = Bo + (uint32_t)(wn + nf * 8 + bRow) * PADB + kb + bColH;
                    uint32_t r0, r1, r2, r3;
                    ldmatrix_x4(r0, r1, r2, r3, addr);
                    bf[nf][0] = r0;     bf[nf][1] = r1;
                    bf[nf + 1][0] = r2; bf[nf + 1][1] = r3;
                }
                #pragma unroll
                for (int mf = 0; mf < 2; mf++)
                    #pragma unroll
                    for (int nf = 0; nf < 8; nf++)
                        mma_bf16(acc[mf][nf], af[mf][0], af[mf][1], af[mf][2], af[mf][3],
                                 bf[nf][0], bf[nf][1]);
            }
        }
        __syncthreads();
    }

    // epilogue: head-major writes
    #pragma unroll
    for (int mf = 0; mf < 2; mf++) {
        #pragma unroll
        for (int nf = 0; nf < 8; nf++) {
            int row = m0 + wm + mf * 16 + g;
            int b   = row >> 10, n = row & 1023;
            int col = n0 + wn + nf * 8 + 2 * t;
            int h   = col >> 6, cc = col & 63;
            size_t adr0 = ((size_t)(b * HH + h) * NN + n) * CC + cc;
            size_t adr1 = ((size_t)(b * HH + h) * NN + n + 8) * CC + cc;
            if (z == 0) {
                *(float2*)&g_qf[adr0] = make_float2(acc[mf][nf][0], acc[mf][nf][1]);
                *(float2*)&g_qf[adr1] = make_float2(acc[mf][nf][2], acc[mf][nf][3]);
            } else if (z == 1) {
                *(float2*)&g_kf[adr0] = make_float2(acc[mf][nf][0], acc[mf][nf][1]);
                *(float2*)&g_kf[adr1] = make_float2(acc[mf][nf][2], acc[mf][nf][3]);
            } else {
                __nv_bfloat16 h0, l0, h1, l1;
                split2(acc[mf][nf][0], h0, l0); split2(acc[mf][nf][1], h1, l1);
                *(uint32_t*)&g_v_hi[adr0] = pack_bf16x2(h0, h1);
                *(uint32_t*)&g_v_lo[adr0] = pack_bf16x2(l0, l1);
                split2(acc[mf][nf][2], h0, l0); split2(acc[mf][nf][3], h1, l1);
                *(uint32_t*)&g_v_hi[adr1] = pack_bf16x2(h0, h1);
                *(uint32_t*)&g_v_lo[adr1] = pack_bf16x2(l0, l1);
            }
        }
    }
}

// ---------------- 2) RoPE + split q,k -> hi/lo bf16 (head-major) ----------------
__global__ void __launch_bounds__(256) rope_split_kernel(const int* __restrict__ positions)
{
    int idx = blockIdx.x * 256 + threadIdx.x;        // BB*HH*NN*32 = 1M
    int i = idx & 31;
    int n = (idx >> 5) & 1023;
    int h = (idx >> 15) & 15;
    int b = idx >> 19;

    float pos = (float)positions[b * NN + n];
    float ts  = powf(10000.0f, (float)i / 32.0f);
    float ang = pos / ts;
    float sv, cv;
    sincosf(ang, &sv, &cv);

    size_t base = ((size_t)(b * HH + h) * NN + n) * CC;
    {
        float q1 = g_qf[base + i], q2 = g_qf[base + i + 32];
        float o1 = q1 * cv - q2 * sv;
        float o2 = q2 * cv + q1 * sv;
        __nv_bfloat16 hh, ll;
        split2(o1, hh, ll); g_q_hi[base + i] = hh;      g_q_lo[base + i] = ll;
        split2(o2, hh, ll); g_q_hi[base + i + 32] = hh; g_q_lo[base + i + 32] = ll;
    }
    {
        float k1 = g_kf[base + i], k2 = g_kf[base + i + 32];
        float o1 = k1 * cv - k2 * sv;
        float o2 = k2 * cv + k1 * sv;
        __nv_bfloat16 hh, ll;
        split2(o1, hh, ll); g_k_hi[base + i] = hh;      g_k_lo[base + i] = ll;
        split2(o2, hh, ll); g_k_hi[base + i + 32] = hh; g_k_lo[base + i + 32] = ll;
    }
}

// ---------------- 3) bias: single-converted-operand bf16 mma, 64-k chunks ------------
// bias[b,h,q,k] = sum_f pair[b,q,k,f] * Wb[f,h].  A = Wb^T (exact: hi+lo hoisted to
// regs), B = pair rows converted hi-only via packed cvt.  Valid k range contiguous:
// [lower_bound(seg,segq), q].  One block per (b,q).  Warp w owns k rows w*8..w*8+7.
#define BCHK (64 * PADB)                  // 9216 B pair chunk (bf16 hi)
#define BO_WBH BCHK
#define BO_WBL (BO_WBH + 16 * PADB)
#define BIAS_SMEM (BO_WBL + 16 * PADB)    // 13824

__global__ void __launch_bounds__(256) bias_mma_kernel(
    const float* __restrict__ pair,
    const float* __restrict__ Wb,
    const int* __restrict__ seg)
{
    __shared__ char smem[BIAS_SMEM];
    const uint32_t sb = smem_to_u32(smem);
    const int tid  = threadIdx.x;
    const int lane = tid & 31;
    const int w    = tid >> 5;
    const int g    = lane >> 2;
    const int t    = lane & 3;
    const int bx   = blockIdx.x;
    const int b    = bx >> 10;
    const int q    = 1023 - (bx & 1023);       // heavy rows first
    const int segq = seg[b * NN + q];

    // stage Wb^T hi/lo (16 h rows x 64 f cols)
    if (tid < 64) {
        int f = tid;
        #pragma unroll
        for (int h = 0; h < 16; h++) {
            float x = Wb[f * HH + h];
            __nv_bfloat16 hh, ll;
            split2(x, hh, ll);
            *(__nv_bfloat16*)(smem + BO_WBH + h * PADB + f * 2) = hh;
            *(__nv_bfloat16*)(smem + BO_WBL + h * PADB + f * 2) = ll;
        }
    }

    // lower_bound for segment start (seg sorted along n)
    int lo = 0, hi = q;
    while (lo < hi) {
        int mid = (lo + hi) >> 1;
        if (seg[b * NN + mid] < segq) lo = mid + 1; else hi = mid;
    }
    const int kstart = lo & ~63;
    __syncthreads();

    // hoist Wb^T A-fragments (K=64: 4 k-steps, hi+lo)
    const uint32_t aRow  = (uint32_t)(lane & 15);
    const uint32_t aColH = (uint32_t)(lane >> 4) * 16;
    uint32_t ah[4][4], alr[4][4];
    #pragma unroll
    for (int ks = 0; ks < 4; ks++) {
        uint32_t addr = sb + BO_WBH + aRow * PADB + (uint32_t)(ks * 32) + aColH;
        ldmatrix_x4(ah[ks][0],  ah[ks][1],  ah[ks][2],  ah[ks][3],  addr);
        ldmatrix_x4(alr[ks][0], alr[ks][1], alr[ks][2], alr[ks][3], addr + 16 * PADB);
    }

    // B-frag lane addressing (x2: 16 lanes give addresses; 2 k-halves of 8x8)
    const uint32_t bRow  = (uint32_t)(lane & 7);
    const uint32_t bColH = ((uint32_t)(lane >> 3) & 1) * 16;
    const float* psrc = &pair[((size_t)(b * NN + q)) * NN * FZ];

    #pragma unroll 1
    for (int k0 = kstart; k0 <= q; k0 += 64) {
        __syncthreads();
        // load pair chunk (64 k x 64 f fp32) -> hi bf16 smem (packed cvt)
        #pragma unroll
        for (int it = 0; it < 4; it++) {
            int idx = tid + it * 256;
            int r   = idx >> 4;
            int c4  = (idx & 15) << 2;
            int row = k0 + r; if (row > 1023) row = 1023;     // safe in-slab read
            float4 v = *(const float4*)&psrc[(size_t)row * FZ + c4];
            uint2 u;
            u.x = cvt_bf16x2(v.x, v.y);
            u.y = cvt_bf16x2(v.z, v.w);
            *(uint2*)(smem + r * PADB + c4 * 2) = u;
        }
        __syncthreads();

        // warp w: 8 k rows, 2-pass (A exact x B hi)
        float S[4] = {0.f, 0.f, 0.f, 0.f};
        #pragma unroll
        for (int ks = 0; ks < 4; ks++) {
            uint32_t baddr = sb + (uint32_t)(w * 8 + bRow) * PADB
                           + (uint32_t)(ks * 32) + bColH;
            uint32_t r0, r1;
            ldmatrix_x2(r0, r1, baddr);
            mma_bf16a(S, ah[ks],  r0, r1);
            mma_bf16a(S, alr[ks], r0, r1);
        }

        // store: thread holds (h=g, k=k0+w*8+2t..+1) and (h=g+8, same k)
        int k = k0 + w * 8 + 2 * t;
        if (k <= 1022) {
            __nv_bfloat16 x0 = __float2bfloat16(S[0]);
            __nv_bfloat16 x1 = __float2bfloat16(S[1]);
            __nv_bfloat16 x2 = __float2bfloat16(S[2]);
            __nv_bfloat16 x3 = __float2bfloat16(S[3]);
            *(uint32_t*)&g_bias[(((size_t)(b * HH + g))     * NN + q) * NN + k] =
                pack_bf16x2(x0, x1);
            *(uint32_t*)&g_bias[(((size_t)(b * HH + g + 8)) * NN + q) * NN + k] =
                pack_bf16x2(x2, x3);
        }
    }
}

// ---------------- 4) flash attention: cp.async pipelined, pre-split operands ---------
#define AQT (128 * PADB)                  // 18432 per Q piece
#define AKT (64 * PADB)                   // 9216 per K/V piece
#define AST (4 * AKT)                     // 36864 per stage
#define O_ST0  (2 * AQT)                  // stage 0 base
#define O_SEG  (2 * AQT + 2 * AST)        // seg[2][64] ints
#define O_LIST (O_SEG + 512)              // tile list (16) + count
#define ATTN_SMEM (O_LIST + 128)

__device__ __forceinline__ void attn_issue(uint32_t stbase, int bh, int k0, int tid)
{
    #pragma unroll
    for (int it = 0; it < 8; it++) {
        int idx  = tid + it * 256;
        int a    = idx >> 9;
        int idx2 = idx & 511;
        int row  = idx2 >> 3;
        int c16  = idx2 & 7;
        size_t e = ((size_t)bh * NN + k0 + row) * CC + c16 * 8;
        const __nv_bfloat16* src;
        if (a == 0)      src = &g_k_hi[e];
        else if (a == 1) src = &g_k_lo[e];
        else if (a == 2) src = &g_v_hi[e];
        else             src = &g_v_lo[e];
        cp_async16(stbase + (uint32_t)(a * AKT + row * PADB + c16 * 16), src);
    }
}

__global__ void __launch_bounds__(256, 1) attn_mma_kernel(
    const int* __restrict__ seg, float* __restrict__ out)
{
    extern __shared__ char smem[];
    const uint32_t sb = smem_to_u32(smem);
    int* tile_list = (int*)(smem + O_LIST);

    const int tid  = threadIdx.x;
    const int lane = tid & 31;
    const int w    = tid >> 5;
    const int g    = lane >> 2;
    const int t    = lane & 3;
    const int qt   = 7 - blockIdx.x;          // heavy tiles first
    const int h    = blockIdx.y;
    const int b    = blockIdx.z;
    const int q0   = qt * 128;
    const int bh   = b * HH + h;
    const float sm_scale = 0.125f;

    const int r0g = q0 + w * 16 + g;
    const int r1g = r0g + 8;
    const int seg_q0 = seg[b * NN + q0];
    const int myseg0 = seg[b * NN + r0g];
    const int myseg1 = seg[b * NN + r1g];
    const int jmax   = 2 * qt + 1;

    // valid tile list
    if (tid < 32) {
        bool valid = (lane <= jmax) && (seg[b * NN + lane * 64 + 63] >= seg_q0);
        uint32_t m = __ballot_sync(0xffffffffu, valid);
        if (valid) tile_list[1 + __popc(m & ((1u << lane) - 1u))] = lane;
        if (lane == 0) tile_list[0] = __popc(m);
    }
    __syncthreads();
    const int T = tile_list[0];

    // prologue: Q (hi/lo) + first tile + its seg in one group
    {
        #pragma unroll
        for (int it = 0; it < 8; it++) {
            int idx  = tid + it * 256;
            int a    = idx >> 10;
            int idx2 = idx & 1023;
            int row  = idx2 >> 3;
            int c16  = idx2 & 7;
            size_t e = ((size_t)bh * NN + q0 + row) * CC + c16 * 8;
            const __nv_bfloat16* src = a ? &g_q_lo[e] : &g_q_hi[e];
            cp_async16(sb + (uint32_t)(a * AQT + row * PADB + c16 * 16), src);
        }
        int k0 = tile_list[1] * 64;
        attn_issue(sb + O_ST0, bh, k0, tid);
        if (tid < 16) cp_async16(sb + O_SEG + tid * 16, &seg[b * NN + k0 + tid * 4]);
        CP_COMMIT();
    }

    float O[8][4];
    #pragma unroll
    for (int nf = 0; nf < 8; nf++)
        #pragma unroll
        for (int u = 0; u < 4; u++) O[nf][u] = 0.f;
    float m0r = -1e30f, m1r = -1e30f, l0r = 0.f, l1r = 0.f;

    const uint32_t aRow  = (uint32_t)(lane & 15);
    const uint32_t aColH = (uint32_t)(lane >> 4) * 16;
    const uint32_t bTile = (uint32_t)(lane >> 3);
    const uint32_t bRow  = (bTile >> 1) * 8 + (uint32_t)(lane & 7);
    const uint32_t bColH = (bTile & 1) * 16;
    const uint32_t vRow  = (bTile & 1) * 8 + (uint32_t)(lane & 7);
    const uint32_t vColH = (uint32_t)(lane >> 4) * 16;

    const __nv_bfloat16* bias0 = &g_bias[((size_t)bh * NN + r0g) * NN];
    const __nv_bfloat16* bias1 = &g_bias[((size_t)bh * NN + r1g) * NN];

    uint32_t qh[4][4], ql[4][4];

    #pragma unroll 1
    for (int i = 0; i < T; i++) {
        const int st = i & 1;
        const uint32_t stb = sb + O_ST0 + (uint32_t)st * AST;
        if (i + 1 < T) {
            int k0n = tile_list[1 + i + 1] * 64;
            attn_issue(sb + O_ST0 + (uint32_t)(st ^ 1) * AST, bh, k0n, tid);
            if (tid < 16)
                cp_async16(sb + O_SEG + (uint32_t)(st ^ 1) * 256 + tid * 16,
                           &seg[b * NN + k0n + tid * 4]);
            CP_COMMIT();
            cp_wait<1>();
        } else {
            cp_wait<0>();
        }
        __syncthreads();

        if (i == 0) {   // hoist Q fragments (Q smem ready with first group)
            #pragma unroll
            for (int ks = 0; ks < 4; ks++) {
                uint32_t qaddr = sb + (uint32_t)(w * 16 + aRow) * PADB
                               + (uint32_t)(ks * 32) + aColH;
                ldmatrix_x4(qh[ks][0], qh[ks][1], qh[ks][2], qh[ks][3], qaddr);
                ldmatrix_x4(ql[ks][0], ql[ks][1], ql[ks][2], ql[ks][3], qaddr + AQT);
            }
        }

        const int k0 = tile_list[1 + i] * 64;
        const int* seg_ks = (const int*)(smem + O_SEG + st * 256);

        // ---- S = Q K^T (3-pass split) ----
        float S[8][4];
        #pragma unroll
        for (int nf = 0; nf < 8; nf++)
            #pragma unroll
            for (int u = 0; u < 4; u++) S[nf][u] = 0.f;

        #pragma unroll
        for (int ks = 0; ks < 4; ks++) {
            const uint32_t kb = (uint32_t)(ks * 32);
            #pragma unroll
            for (int np = 0; np < 4; np++) {
                uint32_t kaddr = stb + (uint32_t)(np * 16 + bRow) * PADB + kb + bColH;
                uint32_t r0, r1, r2, r3;
                ldmatrix_x4(r0, r1, r2, r3, kaddr);              // K hi
                mma_bf16a(S[2 * np],     qh[ks], r0, r1);
                mma_bf16a(S[2 * np + 1], qh[ks], r2, r3);
                mma_bf16a(S[2 * np],     ql[ks], r0, r1);
                mma_bf16a(S[2 * np + 1], ql[ks], r2, r3);
                ldmatrix_x4(r0, r1, r2, r3, kaddr + AKT);        // K lo
                mma_bf16a(S[2 * np],     qh[ks], r0, r1);
                mma_bf16a(S[2 * np + 1], qh[ks], r2, r3);
            }
        }

        // ---- mask + bias + online softmax ----
        float mx0 = -1e30f, mx1 = -1e30f;
        #pragma unroll
        for (int nf = 0; nf < 8; nf++) {
            int cl = nf * 8 + 2 * t;
            int cg = k0 + cl;
            __nv_bfloat162 bb0 = *(const __nv_bfloat162*)&bias0[cg];
            __nv_bfloat162 bb1 = *(const __nv_bfloat162*)&bias1[cg];
            int sk0 = seg_ks[cl], sk1 = seg_ks[cl + 1];
            bool v00 = (cg     <= r0g) && (sk0 == myseg0);
            bool v01 = (cg + 1 <= r0g) && (sk1 == myseg0);
            bool v10 = (cg     <= r1g) && (sk0 == myseg1);
            bool v11 = (cg + 1 <= r1g) && (sk1 == myseg1);
            S[nf][0] = v00 ? fmaf(S[nf][0], sm_scale, __bfloat162float(bb0.x)) : -1e30f;
            S[nf][1] = v01 ? fmaf(S[nf][1], sm_scale, __bfloat162float(bb0.y)) : -1e30f;
            S[nf][2] = v10 ? fmaf(S[nf][2], sm_scale, __bfloat162float(bb1.x)) : -1e30f;
            S[nf][3] = v11 ? fmaf(S[nf][3], sm_scale, __bfloat162float(bb1.y)) : -1e30f;
            mx0 = fmaxf(mx0, fmaxf(S[nf][0], S[nf][1]));
            mx1 = fmaxf(mx1, fmaxf(S[nf][2], S[nf][3]));
        }
        mx0 = fmaxf(mx0, __shfl_xor_sync(0xffffffffu, mx0, 1));
        mx0 = fmaxf(mx0, __shfl_xor_sync(0xffffffffu, mx0, 2));
        mx1 = fmaxf(mx1, __shfl_xor_sync(0xffffffffu, mx1, 1));
        mx1 = fmaxf(mx1, __shfl_xor_sync(0xffffffffu, mx1, 2));

        float mn0 = fmaxf(m0r, mx0), mn1 = fmaxf(m1r, mx1);
        float al0 = __expf(m0r - mn0), al1 = __expf(m1r - mn1);
        m0r = mn0; m1r = mn1;

        float sum0 = 0.f, sum1 = 0.f;
        #pragma unroll
        for (int nf = 0; nf < 8; nf++) {
            float p0 = (S[nf][0] > -1e29f) ? __expf(S[nf][0] - mn0) : 0.f;
            float p1 = (S[nf][1] > -1e29f) ? __expf(S[nf][1] - mn0) : 0.f;
            float p2 = (S[nf][2] > -1e29f) ? __expf(S[nf][2] - mn1) : 0.f;
            float p3 = (S[nf][3] > -1e29f) ? __expf(S[nf][3] - mn1) : 0.f;
            S[nf][0] = p0; S[nf][1] = p1; S[nf][2] = p2; S[nf][3] = p3;
            sum0 += p0 + p1; sum1 += p2 + p3;
        }
        sum0 += __shfl_xor_sync(0xffffffffu, sum0, 1);
        sum0 += __shfl_xor_sync(0xffffffffu, sum0, 2);
        sum1 += __shfl_xor_sync(0xffffffffu, sum1, 1);
        sum1 += __shfl_xor_sync(0xffffffffu, sum1, 2);
        l0r = l0r * al0 + sum0;
        l1r = l1r * al1 + sum1;

        #pragma unroll
        for (int nf = 0; nf < 8; nf++) {
            O[nf][0] *= al0; O[nf][1] *= al0;
            O[nf][2] *= al1; O[nf][3] *= al1;
        }

        // ---- O += P V (3-pass split, V via ldmatrix.trans) ----
        #pragma unroll
        for (int kf = 0; kf < 4; kf++) {
            uint32_t ah[4], al[4];
            {
                __nv_bfloat16 h0, l0, h1, l1;
                split2(S[2 * kf][0], h0, l0); split2(S[2 * kf][1], h1, l1);
                ah[0] = pack_bf16x2(h0, h1);  al[0] = pack_bf16x2(l0, l1);
                split2(S[2 * kf][2], h0, l0); split2(S[2 * kf][3], h1, l1);
                ah[1] = pack_bf16x2(h0, h1);  al[1] = pack_bf16x2(l0, l1);
                split2(S[2 * kf + 1][0], h0, l0); split2(S[2 * kf + 1][1], h1, l1);
                ah[2] = pack_bf16x2(h0, h1);  al[2] = pack_bf16x2(l0, l1);
                split2(S[2 * kf + 1][2], h0, l0); split2(S[2 * kf + 1][3], h1, l1);
                ah[3] = pack_bf16x2(h0, h1);  al[3] = pack_bf16x2(l0, l1);
            }
            #pragma unroll
            for (int cf = 0; cf < 4; cf++) {
                uint32_t vaddr = stb + 2u * AKT + (uint32_t)(kf * 16 + vRow) * PADB
                               + (uint32_t)(cf * 32) + vColH;
                uint32_t r0, r1, r2, r3;
                ldmatrix_x4_trans(r0, r1, r2, r3, vaddr);        // V hi
                mma_bf16a(O[2 * cf],     ah, r0, r1);
                mma_bf16a(O[2 * cf + 1], ah, r2, r3);
                mma_bf16a(O[2 * cf],     al, r0, r1);
                mma_bf16a(O[2 * cf + 1], al, r2, r3);
                ldmatrix_x4_trans(r0, r1, r2, r3, vaddr + AKT);  // V lo
                mma_bf16a(O[2 * cf],     ah, r0, r1);
                mma_bf16a(O[2 * cf + 1], ah, r2, r3);
            }
        }
        __syncthreads();
    }

    // ---- finalize ----
    float inv0 = 1.f / l0r;
    float inv1 = 1.f / l1r;
    size_t base0 = (((size_t)(b * NN + r0g)) * HH + h) * CC;
    size_t base1 = (((size_t)(b * NN + r1g)) * HH + h) * CC;
    #pragma unroll
    for (int nf = 0; nf < 8; nf++) {
        int col = nf * 8 + 2 * t;
        *(float2*)&out[base0 + col] = make_float2(O[nf][0] * inv0, O[nf][1] * inv0);
        *(float2*)&out[base1 + col] = make_float2(O[nf][2] * inv1, O[nf][3] * inv1);
    }
}

// ---------------- launcher ----------------
extern "C" void kernel_launch(void* const* d_in, const int* in_sizes, int n_in,
                              void* d_out, int out_size)
{
    const float* s    = (const float*)d_in[0];
    const float* pair = (const float*)d_in[1];
    const int*   segs = (const int*)d_in[2];
    const int*   pos  = (const int*)d_in[3];
    const float* Wq   = (const float*)d_in[4];
    const float* Wk   = (const float*)d_in[5];
    const float* Wv   = (const float*)d_in[6];
    const float* Wb   = (const float*)d_in[7];
    float* out = (float*)d_out;

    prep_s_kernel<<<2048, 256>>>(s);
    prep_w_kernel<<<dim3(32, 32, 3), dim3(32, 8)>>>(Wq, Wk, Wv);

    cudaFuncSetAttribute(qkv_mma_kernel, cudaFuncAttributeMaxDynamicSharedMemorySize,
                         QKV_SMEM);
    qkv_mma_kernel<<<dim3(8, 16, 3), 256, QKV_SMEM>>>();

    rope_split_kernel<<<4096, 256>>>(pos);

    bias_mma_kernel<<<BB * NN, 256>>>(pair, Wb, segs);

    cudaFuncSetAttribute(attn_mma_kernel, cudaFuncAttributeMaxDynamicSharedMemorySize,
                         ATTN_SMEM);
    attn_mma_kernel<<<dim3(8, HH, BB), 256, ATTN_SMEM>>>(segs, out);
}

// round 10
// speedup vs baseline: 2.2344x; 1.0177x over previous
#include <cuda_runtime.h>
#include <cuda_bf16.h>
#include <math.h>
#include <stdint.h>

#define BB 2
#define NN 1024
#define FSZ 1024
#define FZ 64
#define HH 16
#define CC 64

// ---------------- scratch (device globals: no runtime allocation) ----------------
__device__ __nv_bfloat16  g_q_hi[BB*HH*NN*CC];
__device__ __nv_bfloat16  g_q_lo[BB*HH*NN*CC];
__device__ __nv_bfloat16  g_k_hi[BB*HH*NN*CC];
__device__ __nv_bfloat16  g_k_lo[BB*HH*NN*CC];
__device__ __nv_bfloat16  g_v_hi[BB*HH*NN*CC];
__device__ __nv_bfloat16  g_v_lo[BB*HH*NN*CC];
__device__ __nv_bfloat16  g_s_hi[BB*NN*FSZ];
__device__ __nv_bfloat16  g_s_lo[BB*NN*FSZ];
__device__ __nv_bfloat16  g_wt_hi[3*FSZ*HH*CC];              // [z][n][k]
__device__ __nv_bfloat16  g_wt_lo[3*FSZ*HH*CC];
__device__ __nv_bfloat16  g_bias[(size_t)BB*HH*NN*NN];       // (b,h,q,k)

// ================= helpers =================
__device__ __forceinline__ uint32_t smem_to_u32(const void* p) {
    uint32_t a;
    asm("{ .reg .u64 t; cvta.to.shared.u64 t, %1; cvt.u32.u64 %0, t; }" : "=r"(a) : "l"(p));
    return a;
}
__device__ __forceinline__ uint32_t pack_bf16x2(__nv_bfloat16 a, __nv_bfloat16 b) {
    __nv_bfloat162 t(a, b);
    return *reinterpret_cast<uint32_t*>(&t);
}
__device__ __forceinline__ uint32_t cvt_bf16x2(float lo, float hi) {
    uint32_t r;
    asm("cvt.rn.bf16x2.f32 %0, %1, %2;" : "=r"(r) : "f"(hi), "f"(lo));
    return r;
}
__device__ __forceinline__ void split2(float x, __nv_bfloat16& h, __nv_bfloat16& l) {
    h = __float2bfloat16(x);
    l = __float2bfloat16(x - __bfloat162float(h));
}
__device__ __forceinline__ void ldmatrix_x4(uint32_t& r0, uint32_t& r1, uint32_t& r2,
                                            uint32_t& r3, uint32_t addr) {
    asm volatile("ldmatrix.sync.aligned.m8n8.x4.shared.b16 {%0,%1,%2,%3}, [%4];"
                 : "=r"(r0), "=r"(r1), "=r"(r2), "=r"(r3) : "r"(addr));
}
__device__ __forceinline__ void ldmatrix_x2(uint32_t& r0, uint32_t& r1, uint32_t addr) {
    asm volatile("ldmatrix.sync.aligned.m8n8.x2.shared.b16 {%0,%1}, [%2];"
                 : "=r"(r0), "=r"(r1) : "r"(addr));
}
__device__ __forceinline__ void ldmatrix_x4_trans(uint32_t& r0, uint32_t& r1, uint32_t& r2,
                                                  uint32_t& r3, uint32_t addr) {
    asm volatile("ldmatrix.sync.aligned.m8n8.x4.trans.shared.b16 {%0,%1,%2,%3}, [%4];"
                 : "=r"(r0), "=r"(r1), "=r"(r2), "=r"(r3) : "r"(addr));
}
__device__ __forceinline__ void mma_bf16(float* c, uint32_t a0, uint32_t a1, uint32_t a2,
                                         uint32_t a3, uint32_t b0, uint32_t b1) {
    asm volatile(
        "mma.sync.aligned.m16n8k16.row.col.f32.bf16.bf16.f32 "
        "{%0,%1,%2,%3}, {%4,%5,%6,%7}, {%8,%9}, {%0,%1,%2,%3};"
        : "+f"(c[0]), "+f"(c[1]), "+f"(c[2]), "+f"(c[3])
        : "r"(a0), "r"(a1), "r"(a2), "r"(a3), "r"(b0), "r"(b1));
}
__device__ __forceinline__ void mma_bf16a(float* c, const uint32_t* a, uint32_t b0, uint32_t b1) {
    mma_bf16(c, a[0], a[1], a[2], a[3], b0, b1);
}
__device__ __forceinline__ void cp_async16(uint32_t dst, const void* src) {
    asm volatile(
        "{ .reg .u64 g; cvta.to.global.u64 g, %1; cp.async.cg.shared.global [%0], [g], 16; }"
        :: "r"(dst), "l"(src) : "memory");
}
#define CP_COMMIT() asm volatile("cp.async.commit_group;" ::: "memory")
template<int N> __device__ __forceinline__ void cp_wait() {
    asm volatile("cp.async.wait_group %0;" :: "n"(N) : "memory");
}

#define PADB 144                  // padded row stride in bytes (72 bf16)

// ---------------- 0) merged prep: split s, transpose+split W ----------------
__global__ void __launch_bounds__(256) prep_kernel(
    const float* __restrict__ s,
    const float* __restrict__ Wq, const float* __restrict__ Wk, const float* __restrict__ Wv)
{
    __shared__ float tbuf[32][33];
    const int bid = blockIdx.x;
    const int tid = threadIdx.x;
    if (bid < 2048) {
        int idx = bid * 256 + tid;        // 0..524287
        float4 v = *(const float4*)&s[(size_t)idx * 4];
        __nv_bfloat16 h0, l0, h1, l1, h2, l2, h3, l3;
        split2(v.x, h0, l0); split2(v.y, h1, l1);
        split2(v.z, h2, l2); split2(v.w, h3, l3);
        uint2 hv, lv;
        hv.x = pack_bf16x2(h0, h1); hv.y = pack_bf16x2(h2, h3);
        lv.x = pack_bf16x2(l0, l1); lv.y = pack_bf16x2(l2, l3);
        *(uint2*)&g_s_hi[(size_t)idx * 4] = hv;
        *(uint2*)&g_s_lo[(size_t)idx * 4] = lv;
    } else {
        int b2  = bid - 2048;             // 0..3071
        int z   = b2 >> 10;
        int rem = b2 & 1023;
        int k0  = (rem >> 5) * 32;
        int n0  = (rem & 31) * 32;
        const float* W = (z == 0) ? Wq : (z == 1) ? Wk : Wv;
        int tx = tid & 31, ty = tid >> 5;
        #pragma unroll
        for (int i = 0; i < 4; i++) {
            int ky = ty + i * 8;
            tbuf[ky][tx] = W[(size_t)(k0 + ky) * (HH * CC) + n0 + tx];
        }
        __syncthreads();
        #pragma unroll
        for (int i = 0; i < 4; i++) {
            int ny = ty + i * 8;
            float x = tbuf[tx][ny];
            __nv_bfloat16 h, l;
            split2(x, h, l);
            size_t adr = ((size_t)z * FSZ + n0 + ny) * FSZ + k0 + tx;
            g_wt_hi[adr] = h;
            g_wt_lo[adr] = l;
        }
    }
}

// ---------------- 1) QKV projection + fused RoPE/split epilogue ----------------
#define QTILEB (128 * PADB)               // 18432 B per piece
#define QBUF   (4 * QTILEB)               // 73728 B per chunk buffer
#define QKV_SMEM (2 * QBUF)               // 147456

__device__ __forceinline__ void qkv_issue(uint32_t buf, int z, int m0, int n0, int k0, int tid)
{
    #pragma unroll
    for (int it = 0; it < 16; it++) {
        int idx  = tid + it * 256;
        int a    = idx >> 10;
        int idx2 = idx & 1023;
        int row  = idx2 >> 3;
        int c16  = idx2 & 7;
        const __nv_bfloat16* src;
        if (a == 0)      src = &g_s_hi[(size_t)(m0 + row) * FSZ + k0 + c16 * 8];
        else if (a == 1) src = &g_s_lo[(size_t)(m0 + row) * FSZ + k0 + c16 * 8];
        else if (a == 2) src = &g_wt_hi[((size_t)z * FSZ + n0 + row) * FSZ + k0 + c16 * 8];
        else             src = &g_wt_lo[((size_t)z * FSZ + n0 + row) * FSZ + k0 + c16 * 8];
        cp_async16(buf + (uint32_t)(a * QTILEB + row * PADB + c16 * 16), src);
    }
}

__global__ void __launch_bounds__(256, 1) qkv_mma_kernel(const int* __restrict__ positions)
{
    extern __shared__ char smem[];
    const uint32_t sb = smem_to_u32(smem);
    const int tid  = threadIdx.x;
    const int lane = tid & 31;
    const int wid  = tid >> 5;
    const int g    = lane >> 2;
    const int t    = lane & 3;
    const int z    = blockIdx.z;
    const int m0   = blockIdx.y * 128;
    const int n0   = blockIdx.x * 128;
    const int wm   = (wid >> 1) * 32;
    const int wn   = (wid & 1) * 64;

    float acc[2][8][4];
    #pragma unroll
    for (int i = 0; i < 2; i++)
        #pragma unroll
        for (int j = 0; j < 8; j++)
            #pragma unroll
            for (int u = 0; u < 4; u++) acc[i][j][u] = 0.f;

    const uint32_t aRow  = (uint32_t)(lane & 15);
    const uint32_t aColH = (uint32_t)(lane >> 4) * 16;
    const uint32_t bTile = (uint32_t)(lane >> 3);
    const uint32_t bRow  = (bTile >> 1) * 8 + (uint32_t)(lane & 7);
    const uint32_t bColH = (bTile & 1) * 16;

    qkv_issue(sb, z, m0, n0, 0, tid);
    CP_COMMIT();

    #pragma unroll 1
    for (int c = 0; c < 16; c++) {
        const uint32_t buf = sb + (uint32_t)(c & 1) * QBUF;
        if (c + 1 < 16) {
            qkv_issue(sb + (uint32_t)((c + 1) & 1) * QBUF, z, m0, n0, (c + 1) * 64, tid);
            CP_COMMIT();
            cp_wait<1>();
        } else {
            cp_wait<0>();
        }
        __syncthreads();

        #pragma unroll
        for (int pass = 0; pass < 3; pass++) {
            const uint32_t Ao = buf + (pass == 2 ? QTILEB : 0u);
            const uint32_t Bo = buf + 2u * QTILEB + (pass == 1 ? QTILEB : 0u);
            #pragma unroll
            for (int ks = 0; ks < 4; ks++) {
                const uint32_t kb = (uint32_t)(ks * 32);
                uint32_t af[2][4];
                #pragma unroll
                for (int mf = 0; mf < 2; mf++) {
                    uint32_t addr = Ao + (uint32_t)(wm + mf * 16 + aRow) * PADB + kb + aColH;
                    ldmatrix_x4(af[mf][0], af[mf][1], af[mf][2], af[mf][3], addr);
                }
                uint32_t bf[8][2];
                #pragma unroll
                for (int nf = 0; nf < 8; nf += 2) {
                    uint32_t addr = Bo + (uint32_t)(wn + nf * 8 + bRow) * PADB + kb + bColH;
                    uint32_t r0, r1, r2, r3;
                    ldmatrix_x4(r0, r1, r2, r3, addr);
                    bf[nf][0] = r0;     bf[nf][1] = r1;
                    bf[nf + 1][0] = r2; bf[nf + 1][1] = r3;
                }
                #pragma unroll
                for (int mf = 0; mf < 2; mf++)
                    #pragma unroll
                    for (int nf = 0; nf < 8; nf++)
                        mma_bf16(acc[mf][nf], af[mf][0], af[mf][1], af[mf][2], af[mf][3],
                                 bf[nf][0], bf[nf][1]);
            }
        }
        __syncthreads();
    }

    // ---- epilogue ----
    if (z <= 1) {
        // fused RoPE + hi/lo split; pair (c, c+32) lives in (nf, nf+4) of same thread
        __nv_bfloat16* dhi = z ? g_k_hi : g_q_hi;
        __nv_bfloat16* dlo = z ? g_k_lo : g_q_lo;
        const int h = ((n0 + wn) >> 6) & 15;
        float tsv[8];
        #pragma unroll
        for (int nf = 0; nf < 4; nf++)
            #pragma unroll
            for (int j = 0; j < 2; j++) {
                int i = nf * 8 + 2 * t + j;
                tsv[nf * 2 + j] = powf(10000.0f, (float)i / 32.0f);
            }
        #pragma unroll
        for (int mf = 0; mf < 2; mf++) {
            #pragma unroll
            for (int rh = 0; rh < 2; rh++) {
                int row = m0 + wm + mf * 16 + g + rh * 8;
                int b   = row >> 10, n = row & 1023;
                float pos = (float)positions[b * NN + n];
                size_t base = ((size_t)(b * HH + h) * NN + n) * CC;
                #pragma unroll
                for (int nf = 0; nf < 4; nf++) {
                    float o1[2], o2[2];
                    #pragma unroll
                    for (int j = 0; j < 2; j++) {
                        float ang = pos / tsv[nf * 2 + j];
                        float sv, cv;
                        sincosf(ang, &sv, &cv);
                        float x1 = acc[mf][nf][rh * 2 + j];
                        float x2 = acc[mf][nf + 4][rh * 2 + j];
                        o1[j] = x1 * cv - x2 * sv;
                        o2[j] = x2 * cv + x1 * sv;
                    }
                    int cc = nf * 8 + 2 * t;
                    __nv_bfloat16 h0, l0, h1, l1;
                    split2(o1[0], h0, l0); split2(o1[1], h1, l1);
                    *(uint32_t*)&dhi[base + cc]      = pack_bf16x2(h0, h1);
                    *(uint32_t*)&dlo[base + cc]      = pack_bf16x2(l0, l1);
                    split2(o2[0], h0, l0); split2(o2[1], h1, l1);
                    *(uint32_t*)&dhi[base + cc + 32] = pack_bf16x2(h0, h1);
                    *(uint32_t*)&dlo[base + cc + 32] = pack_bf16x2(l0, l1);
                }
            }
        }
    } else {
        #pragma unroll
        for (int mf = 0; mf < 2; mf++) {
            #pragma unroll
            for (int nf = 0; nf < 8; nf++) {
                int row = m0 + wm + mf * 16 + g;
                int b   = row >> 10, n = row & 1023;
                int col = n0 + wn + nf * 8 + 2 * t;
                int h   = col >> 6, cc = col & 63;
                size_t adr0 = ((size_t)(b * HH + h) * NN + n) * CC + cc;
                size_t adr1 = ((size_t)(b * HH + h) * NN + n + 8) * CC + cc;
                __nv_bfloat16 h0, l0, h1, l1;
                split2(acc[mf][nf][0], h0, l0); split2(acc[mf][nf][1], h1, l1);
                *(uint32_t*)&g_v_hi[adr0] = pack_bf16x2(h0, h1);
                *(uint32_t*)&g_v_lo[adr0] = pack_bf16x2(l0, l1);
                split2(acc[mf][nf][2], h0, l0); split2(acc[mf][nf][3], h1, l1);
                *(uint32_t*)&g_v_hi[adr1] = pack_bf16x2(h0, h1);
                *(uint32_t*)&g_v_lo[adr1] = pack_bf16x2(l0, l1);
            }
        }
    }
}

// ---------------- 3) bias: single-converted-operand bf16 mma, 64-k chunks ------------
#define BCHK (64 * PADB)                  // 9216 B pair chunk (bf16 hi)
#define BO_WBH BCHK
#define BO_WBL (BO_WBH + 16 * PADB)
#define BIAS_SMEM (BO_WBL + 16 * PADB)    // 13824

__global__ void __launch_bounds__(256) bias_mma_kernel(
    const float* __restrict__ pair,
    const float* __restrict__ Wb,
    const int* __restrict__ seg)
{
    __shared__ char smem[BIAS_SMEM];
    const uint32_t sb = smem_to_u32(smem);
    const int tid  = threadIdx.x;
    const int lane = tid & 31;
    const int w    = tid >> 5;
    const int g    = lane >> 2;
    const int t    = lane & 3;
    const int bx   = blockIdx.x;
    const int b    = bx >> 10;
    const int q    = 1023 - (bx & 1023);       // heavy rows first
    const int segq = seg[b * NN + q];

    if (tid < 64) {
        int f = tid;
        #pragma unroll
        for (int h = 0; h < 16; h++) {
            float x = Wb[f * HH + h];
            __nv_bfloat16 hh, ll;
            split2(x, hh, ll);
            *(__nv_bfloat16*)(smem + BO_WBH + h * PADB + f * 2) = hh;
            *(__nv_bfloat16*)(smem + BO_WBL + h * PADB + f * 2) = ll;
        }
    }

    int lo = 0, hi = q;
    while (lo < hi) {
        int mid = (lo + hi) >> 1;
        if (seg[b * NN + mid] < segq) lo = mid + 1; else hi = mid;
    }
    const int kstart = lo & ~63;
    __syncthreads();

    const uint32_t aRow  = (uint32_t)(lane & 15);
    const uint32_t aColH = (uint32_t)(lane >> 4) * 16;
    uint32_t ah[4][4], alr[4][4];
    #pragma unroll
    for (int ks = 0; ks < 4; ks++) {
        uint32_t addr = sb + BO_WBH + aRow * PADB + (uint32_t)(ks * 32) + aColH;
        ldmatrix_x4(ah[ks][0],  ah[ks][1],  ah[ks][2],  ah[ks][3],  addr);
        ldmatrix_x4(alr[ks][0], alr[ks][1], alr[ks][2], alr[ks][3], addr + 16 * PADB);
    }

    const uint32_t bRow  = (uint32_t)(lane & 7);
    const uint32_t bColH = ((uint32_t)(lane >> 3) & 1) * 16;
    const float* psrc = &pair[((size_t)(b * NN + q)) * NN * FZ];

    #pragma unroll 1
    for (int k0 = kstart; k0 <= q; k0 += 64) {
        __syncthreads();
        #pragma unroll
        for (int it = 0; it < 4; it++) {
            int idx = tid + it * 256;
            int r   = idx >> 4;
            int c4  = (idx & 15) << 2;
            int row = k0 + r; if (row > 1023) row = 1023;
            float4 v = *(const float4*)&psrc[(size_t)row * FZ + c4];
            uint2 u;
            u.x = cvt_bf16x2(v.x, v.y);
            u.y = cvt_bf16x2(v.z, v.w);
            *(uint2*)(smem + r * PADB + c4 * 2) = u;
        }
        __syncthreads();

        float S[4] = {0.f, 0.f, 0.f, 0.f};
        #pragma unroll
        for (int ks = 0; ks < 4; ks++) {
            uint32_t baddr = sb + (uint32_t)(w * 8 + bRow) * PADB
                           + (uint32_t)(ks * 32) + bColH;
            uint32_t r0, r1;
            ldmatrix_x2(r0, r1, baddr);
            mma_bf16a(S, ah[ks],  r0, r1);
            mma_bf16a(S, alr[ks], r0, r1);
        }

        int k = k0 + w * 8 + 2 * t;
        if (k <= 1022) {
            __nv_bfloat16 x0 = __float2bfloat16(S[0]);
            __nv_bfloat16 x1 = __float2bfloat16(S[1]);
            __nv_bfloat16 x2 = __float2bfloat16(S[2]);
            __nv_bfloat16 x3 = __float2bfloat16(S[3]);
            *(uint32_t*)&g_bias[(((size_t)(b * HH + g))     * NN + q) * NN + k] =
                pack_bf16x2(x0, x1);
            *(uint32_t*)&g_bias[(((size_t)(b * HH + g + 8)) * NN + q) * NN + k] =
                pack_bf16x2(x2, x3);
        }
    }
}

// ---------------- 4) flash attention: cp.async pipelined, pre-split operands ---------
#define AQT (128 * PADB)                  // 18432 per Q piece
#define AKT (64 * PADB)                   // 9216 per K/V piece
#define AST (4 * AKT)                     // 36864 per stage
#define O_ST0  (2 * AQT)                  // stage 0 base
#define O_SEG  (2 * AQT + 2 * AST)        // seg[2][64] ints
#define O_LIST (O_SEG + 512)              // tile list (16) + count
#define ATTN_SMEM (O_LIST + 128)

__device__ __forceinline__ void attn_issue(uint32_t stbase, int bh, int k0, int tid)
{
    #pragma unroll
    for (int it = 0; it < 8; it++) {
        int idx  = tid + it * 256;
        int a    = idx >> 9;
        int idx2 = idx & 511;
        int row  = idx2 >> 3;
        int c16  = idx2 & 7;
        size_t e = ((size_t)bh * NN + k0 + row) * CC + c16 * 8;
        const __nv_bfloat16* src;
        if (a == 0)      src = &g_k_hi[e];
        else if (a == 1) src = &g_k_lo[e];
        else if (a == 2) src = &g_v_hi[e];
        else             src = &g_v_lo[e];
        cp_async16(stbase + (uint32_t)(a * AKT + row * PADB + c16 * 16), src);
    }
}

__global__ void __launch_bounds__(256, 1) attn_mma_kernel(
    const int* __restrict__ seg, float* __restrict__ out)
{
    extern __shared__ char smem[];
    const uint32_t sb = smem_to_u32(smem);
    int* tile_list = (int*)(smem + O_LIST);

    const int tid  = threadIdx.x;
    const int lane = tid & 31;
    const int w    = tid >> 5;
    const int g    = lane >> 2;
    const int t    = lane & 3;
    const int qt   = 7 - blockIdx.x;          // heavy tiles first
    const int h    = blockIdx.y;
    const int b    = blockIdx.z;
    const int q0   = qt * 128;
    const int bh   = b * HH + h;
    const float sm_scale = 0.125f;

    const int r0g = q0 + w * 16 + g;
    const int r1g = r0g + 8;
    const int seg_q0 = seg[b * NN + q0];
    const int myseg0 = seg[b * NN + r0g];
    const int myseg1 = seg[b * NN + r1g];
    const int jmax   = 2 * qt + 1;

    if (tid < 32) {
        bool valid = (lane <= jmax) && (seg[b * NN + lane * 64 + 63] >= seg_q0);
        uint32_t m = __ballot_sync(0xffffffffu, valid);
        if (valid) tile_list[1 + __popc(m & ((1u << lane) - 1u))] = lane;
        if (lane == 0) tile_list[0] = __popc(m);
    }
    __syncthreads();
    const int T = tile_list[0];

    {
        #pragma unroll
        for (int it = 0; it < 8; it++) {
            int idx  = tid + it * 256;
            int a    = idx >> 10;
            int idx2 = idx & 1023;
            int row  = idx2 >> 3;
            int c16  = idx2 & 7;
            size_t e = ((size_t)bh * NN + q0 + row) * CC + c16 * 8;
            const __nv_bfloat16* src = a ? &g_q_lo[e] : &g_q_hi[e];
            cp_async16(sb + (uint32_t)(a * AQT + row * PADB + c16 * 16), src);
        }
        int k0 = tile_list[1] * 64;
        attn_issue(sb + O_ST0, bh, k0, tid);
        if (tid < 16) cp_async16(sb + O_SEG + tid * 16, &seg[b * NN + k0 + tid * 4]);
        CP_COMMIT();
    }

    float O[8][4];
    #pragma unroll
    for (int nf = 0; nf < 8; nf++)
        #pragma unroll
        for (int u = 0; u < 4; u++) O[nf][u] = 0.f;
    float m0r = -1e30f, m1r = -1e30f, l0r = 0.f, l1r = 0.f;

    const uint32_t aRow  = (uint32_t)(lane & 15);
    const uint32_t aColH = (uint32_t)(lane >> 4) * 16;
    const uint32_t bTile = (uint32_t)(lane >> 3);
    const uint32_t bRow  = (bTile >> 1) * 8 + (uint32_t)(lane & 7);
    const uint32_t bColH = (bTile & 1) * 16;
    const uint32_t vRow  = (bTile & 1) * 8 + (uint32_t)(lane & 7);
    const uint32_t vColH = (uint32_t)(lane >> 4) * 16;

    const __nv_bfloat16* bias0 = &g_bias[((size_t)bh * NN + r0g) * NN];
    const __nv_bfloat16* bias1 = &g_bias[((size_t)bh * NN + r1g) * NN];

    uint32_t qh[4][4], ql[4][4];

    #pragma unroll 1
    for (int i = 0; i < T; i++) {
        const int st = i & 1;
        const uint32_t stb = sb + O_ST0 + (uint32_t)st * AST;
        if (i + 1 < T) {
            int k0n = tile_list[1 + i + 1] * 64;
            attn_issue(sb + O_ST0 + (uint32_t)(st ^ 1) * AST, bh, k0n, tid);
            if (tid < 16)
                cp_async16(sb + O_SEG + (uint32_t)(st ^ 1) * 256 + tid * 16,
                           &seg[b * NN + k0n + tid * 4]);
            CP_COMMIT();
            cp_wait<1>();
        } else {
            cp_wait<0>();
        }
        __syncthreads();

        if (i == 0) {
            #pragma unroll
            for (int ks = 0; ks < 4; ks++) {
                uint32_t qaddr = sb + (uint32_t)(w * 16 + aRow) * PADB
                               + (uint32_t)(ks * 32) + aColH;
                ldmatrix_x4(qh[ks][0], qh[ks][1], qh[ks][2], qh[ks][3], qaddr);
                ldmatrix_x4(ql[ks][0], ql[ks][1], ql[ks][2], ql[ks][3], qaddr + AQT);
            }
        }

        const int k0 = tile_list[1 + i] * 64;
        const int* seg_ks = (const int*)(smem + O_SEG + st * 256);

        float S[8][4];
        #pragma unroll
        for (int nf = 0; nf < 8; nf++)
            #pragma unroll
            for (int u = 0; u < 4; u++) S[nf][u] = 0.f;

        #pragma unroll
        for (int ks = 0; ks < 4; ks++) {
            const uint32_t kb = (uint32_t)(ks * 32);
            #pragma unroll
            for (int np = 0; np < 4; np++) {
                uint32_t kaddr = stb + (uint32_t)(np * 16 + bRow) * PADB + kb + bColH;
                uint32_t r0, r1, r2, r3;
                ldmatrix_x4(r0, r1, r2, r3, kaddr);              // K hi
                mma_bf16a(S[2 * np],     qh[ks], r0, r1);
                mma_bf16a(S[2 * np + 1], qh[ks], r2, r3);
                mma_bf16a(S[2 * np],     ql[ks], r0, r1);
                mma_bf16a(S[2 * np + 1], ql[ks], r2, r3);
                ldmatrix_x4(r0, r1, r2, r3, kaddr + AKT);        // K lo
                mma_bf16a(S[2 * np],     qh[ks], r0, r1);
                mma_bf16a(S[2 * np + 1], qh[ks], r2, r3);
            }
        }

        float mx0 = -1e30f, mx1 = -1e30f;
        #pragma unroll
        for (int nf = 0; nf < 8; nf++) {
            int cl = nf * 8 + 2 * t;
            int cg = k0 + cl;
            __nv_bfloat162 bb0 = *(const __nv_bfloat162*)&bias0[cg];
            __nv_bfloat162 bb1 = *(const __nv_bfloat162*)&bias1[cg];
            int sk0 = seg_ks[cl], sk1 = seg_ks[cl + 1];
            bool v00 = (cg     <= r0g) && (sk0 == myseg0);
            bool v01 = (cg + 1 <= r0g) && (sk1 == myseg0);
            bool v10 = (cg     <= r1g) && (sk0 == myseg1);
            bool v11 = (cg + 1 <= r1g) && (sk1 == myseg1);
            S[nf][0] = v00 ? fmaf(S[nf][0], sm_scale, __bfloat162float(bb0.x)) : -1e30f;
            S[nf][1] = v01 ? fmaf(S[nf][1], sm_scale, __bfloat162float(bb0.y)) : -1e30f;
            S[nf][2] = v10 ? fmaf(S[nf][2], sm_scale, __bfloat162float(bb1.x)) : -1e30f;
            S[nf][3] = v11 ? fmaf(S[nf][3], sm_scale, __bfloat162float(bb1.y)) : -1e30f;
            mx0 = fmaxf(mx0, fmaxf(S[nf][0], S[nf][1]));
            mx1 = fmaxf(mx1, fmaxf(S[nf][2], S[nf][3]));
        }
        mx0 = fmaxf(mx0, __shfl_xor_sync(0xffffffffu, mx0, 1));
        mx0 = fmaxf(mx0, __shfl_xor_sync(0xffffffffu, mx0, 2));
        mx1 = fmaxf(mx1, __shfl_xor_sync(0xffffffffu, mx1, 1));
        mx1 = fmaxf(mx1, __shfl_xor_sync(0xffffffffu, mx1, 2));

        float mn0 = fmaxf(m0r, mx0), mn1 = fmaxf(m1r, mx1);
        float al0 = __expf(m0r - mn0), al1 = __expf(m1r - mn1);
        m0r = mn0; m1r = mn1;

        float sum0 = 0.f, sum1 = 0.f;
        #pragma unroll
        for (int nf = 0; nf < 8; nf++) {
            float p0 = (S[nf][0] > -1e29f) ? __expf(S[nf][0] - mn0) : 0.f;
            float p1 = (S[nf][1] > -1e29f) ? __expf(S[nf][1] - mn0) : 0.f;
            float p2 = (S[nf][2] > -1e29f) ? __expf(S[nf][2] - mn1) : 0.f;
            float p3 = (S[nf][3] > -1e29f) ? __expf(S[nf][3] - mn1) : 0.f;
            S[nf][0] = p0; S[nf][1] = p1; S[nf][2] = p2; S[nf][3] = p3;
            sum0 += p0 + p1; sum1 += p2 + p3;
        }
        sum0 += __shfl_xor_sync(0xffffffffu, sum0, 1);
        sum0 += __shfl_xor_sync(0xffffffffu, sum0, 2);
        sum1 += __shfl_xor_sync(0xffffffffu, sum1, 1);
        sum1 += __shfl_xor_sync(0xffffffffu, sum1, 2);
        l0r = l0r * al0 + sum0;
        l1r = l1r * al1 + sum1;

        #pragma unroll
        for (int nf = 0; nf < 8; nf++) {
            O[nf][0] *= al0; O[nf][1] *= al0;
            O[nf][2] *= al1; O[nf][3] *= al1;
        }

        #pragma unroll
        for (int kf = 0; kf < 4; kf++) {
            uint32_t ah[4], al[4];
            {
                __nv_bfloat16 h0, l0, h1, l1;
                split2(S[2 * kf][0], h0, l0); split2(S[2 * kf][1], h1, l1);
                ah[0] = pack_bf16x2(h0, h1);  al[0] = pack_bf16x2(l0, l1);
                split2(S[2 * kf][2], h0, l0); split2(S[2 * kf][3], h1, l1);
                ah[1] = pack_bf16x2(h0, h1);  al[1] = pack_bf16x2(l0, l1);
                split2(S[2 * kf + 1][0], h0, l0); split2(S[2 * kf + 1][1], h1, l1);
                ah[2] = pack_bf16x2(h0, h1);  al[2] = pack_bf16x2(l0, l1);
                split2(S[2 * kf + 1][2], h0, l0); split2(S[2 * kf + 1][3], h1, l1);
                ah[3] = pack_bf16x2(h0, h1);  al[3] = pack_bf16x2(l0, l1);
            }
            #pragma unroll
            for (int cf = 0; cf < 4; cf++) {
                uint32_t vaddr = stb + 2u * AKT + (uint32_t)(kf * 16 + vRow) * PADB
                               + (uint32_t)(cf * 32) + vColH;
                uint32_t r0, r1, r2, r3;
                ldmatrix_x4_trans(r0, r1, r2, r3, vaddr);        // V hi
                mma_bf16a(O[2 * cf],     ah, r0, r1);
                mma_bf16a(O[2 * cf + 1], ah, r2, r3);
                mma_bf16a(O[2 * cf],     al, r0, r1);
                mma_bf16a(O[2 * cf + 1], al, r2, r3);
                ldmatrix_x4_trans(r0, r1, r2, r3, vaddr + AKT);  // V lo
                mma_bf16a(O[2 * cf],     ah, r0, r1);
                mma_bf16a(O[2 * cf + 1], ah, r2, r3);
            }
        }
        __syncthreads();
    }

    float inv0 = 1.f / l0r;
    float inv1 = 1.f / l1r;
    size_t base0 = (((size_t)(b * NN + r0g)) * HH + h) * CC;
    size_t base1 = (((size_t)(b * NN + r1g)) * HH + h) * CC;
    #pragma unroll
    for (int nf = 0; nf < 8; nf++) {
        int col = nf * 8 + 2 * t;
        *(float2*)&out[base0 + col] = make_float2(O[nf][0] * inv0, O[nf][1] * inv0);
        *(float2*)&out[base1 + col] = make_float2(O[nf][2] * inv1, O[nf][3] * inv1);
    }
}

// ---------------- launcher: bias runs concurrently with prep+qkv ----------------
extern "C" void kernel_launch(void* const* d_in, const int* in_sizes, int n_in,
                              void* d_out, int out_size)
{
    const float* s    = (const float*)d_in[0];
    const float* pair = (const float*)d_in[1];
    const int*   segs = (const int*)d_in[2];
    const int*   pos  = (const int*)d_in[3];
    const float* Wq   = (const float*)d_in[4];
    const float* Wk   = (const float*)d_in[5];
    const float* Wv   = (const float*)d_in[6];
    const float* Wb   = (const float*)d_in[7];
    float* out = (float*)d_out;

    static cudaStream_t sB = nullptr;
    static cudaEvent_t  eF = nullptr, eJ = nullptr;
    if (!sB) {
        cudaStreamCreateWithFlags(&sB, cudaStreamNonBlocking);
        cudaEventCreateWithFlags(&eF, cudaEventDisableTiming);
        cudaEventCreateWithFlags(&eJ, cudaEventDisableTiming);
    }

    cudaFuncSetAttribute(qkv_mma_kernel, cudaFuncAttributeMaxDynamicSharedMemorySize,
                         QKV_SMEM);
    cudaFuncSetAttribute(attn_mma_kernel, cudaFuncAttributeMaxDynamicSharedMemorySize,
                         ATTN_SMEM);

    // fork: bias (depends only on pair/Wb/seg) runs on sB concurrently
    cudaEventRecord(eF, 0);
    cudaStreamWaitEvent(sB, eF, 0);
    bias_mma_kernel<<<BB * NN, 256, 0, sB>>>(pair, Wb, segs);
    cudaEventRecord(eJ, sB);

    // main branch: prep -> qkv (rope fused)
    prep_kernel<<<5120, 256>>>(s, Wq, Wk, Wv);
    qkv_mma_kernel<<<dim3(8, 16, 3), 256, QKV_SMEM>>>(pos);

    // join, then attention
    cudaStreamWaitEvent(0, eJ, 0);
    attn_mma_kernel<<<dim3(8, HH, BB), 256, ATTN_SMEM>>>(segs, out);
}

// round 11
// speedup vs baseline: 2.2794x; 1.0201x over previous
#include <cuda_runtime.h>
#include <cuda_bf16.h>
#include <math.h>
#include <stdint.h>

#define BB 2
#define NN 1024
#define FSZ 1024
#define FZ 64
#define HH 16
#define CC 64

// ---------------- scratch (device globals: no runtime allocation) ----------------
__device__ __nv_bfloat16  g_q_hi[BB*HH*NN*CC];
__device__ __nv_bfloat16  g_q_lo[BB*HH*NN*CC];
__device__ __nv_bfloat16  g_k_hi[BB*HH*NN*CC];
__device__ __nv_bfloat16  g_k_lo[BB*HH*NN*CC];
__device__ __nv_bfloat16  g_v_hi[BB*HH*NN*CC];
__device__ __nv_bfloat16  g_v_lo[BB*HH*NN*CC];
__device__ __nv_bfloat16  g_s_hi[BB*NN*FSZ];
__device__ __nv_bfloat16  g_s_lo[BB*NN*FSZ];
__device__ __nv_bfloat16  g_wt_hi[3*FSZ*HH*CC];              // [z][n][k]
__device__ __nv_bfloat16  g_wt_lo[3*FSZ*HH*CC];
__device__ __nv_bfloat16  g_bias[(size_t)BB*HH*NN*NN];       // (b,h,q,k)

// ================= helpers =================
__device__ __forceinline__ uint32_t smem_to_u32(const void* p) {
    uint32_t a;
    asm("{ .reg .u64 t; cvta.to.shared.u64 t, %1; cvt.u32.u64 %0, t; }" : "=r"(a) : "l"(p));
    return a;
}
__device__ __forceinline__ uint32_t pack_bf16x2(__nv_bfloat16 a, __nv_bfloat16 b) {
    __nv_bfloat162 t(a, b);
    return *reinterpret_cast<uint32_t*>(&t);
}
__device__ __forceinline__ uint32_t cvt_bf16x2(float lo, float hi) {
    uint32_t r;
    asm("cvt.rn.bf16x2.f32 %0, %1, %2;" : "=r"(r) : "f"(hi), "f"(lo));
    return r;
}
__device__ __forceinline__ void split2(float x, __nv_bfloat16& h, __nv_bfloat16& l) {
    h = __float2bfloat16(x);
    l = __float2bfloat16(x - __bfloat162float(h));
}
__device__ __forceinline__ void ldmatrix_x4(uint32_t& r0, uint32_t& r1, uint32_t& r2,
                                            uint32_t& r3, uint32_t addr) {
    asm volatile("ldmatrix.sync.aligned.m8n8.x4.shared.b16 {%0,%1,%2,%3}, [%4];"
                 : "=r"(r0), "=r"(r1), "=r"(r2), "=r"(r3) : "r"(addr));
}
__device__ __forceinline__ void ldmatrix_x2(uint32_t& r0, uint32_t& r1, uint32_t addr) {
    asm volatile("ldmatrix.sync.aligned.m8n8.x2.shared.b16 {%0,%1}, [%2];"
                 : "=r"(r0), "=r"(r1) : "r"(addr));
}
__device__ __forceinline__ void ldmatrix_x4_trans(uint32_t& r0, uint32_t& r1, uint32_t& r2,
                                                  uint32_t& r3, uint32_t addr) {
    asm volatile("ldmatrix.sync.aligned.m8n8.x4.trans.shared.b16 {%0,%1,%2,%3}, [%4];"
                 : "=r"(r0), "=r"(r1), "=r"(r2), "=r"(r3) : "r"(addr));
}
__device__ __forceinline__ void mma_bf16(float* c, uint32_t a0, uint32_t a1, uint32_t a2,
                                         uint32_t a3, uint32_t b0, uint32_t b1) {
    asm volatile(
        "mma.sync.aligned.m16n8k16.row.col.f32.bf16.bf16.f32 "
        "{%0,%1,%2,%3}, {%4,%5,%6,%7}, {%8,%9}, {%0,%1,%2,%3};"
        : "+f"(c[0]), "+f"(c[1]), "+f"(c[2]), "+f"(c[3])
        : "r"(a0), "r"(a1), "r"(a2), "r"(a3), "r"(b0), "r"(b1));
}
__device__ __forceinline__ void mma_bf16a(float* c, const uint32_t* a, uint32_t b0, uint32_t b1) {
    mma_bf16(c, a[0], a[1], a[2], a[3], b0, b1);
}
__device__ __forceinline__ void cp_async16(uint32_t dst, const void* src) {
    asm volatile(
        "{ .reg .u64 g; cvta.to.global.u64 g, %1; cp.async.cg.shared.global [%0], [g], 16; }"
        :: "r"(dst), "l"(src) : "memory");
}
#define CP_COMMIT() asm volatile("cp.async.commit_group;" ::: "memory")
template<int N> __device__ __forceinline__ void cp_wait() {
    asm volatile("cp.async.wait_group %0;" :: "n"(N) : "memory");
}

#define PADB 144                  // padded row stride in bytes (72 bf16)

// ---------------- 0) merged prep: split s, transpose+split W ----------------
__global__ void __launch_bounds__(256) prep_kernel(
    const float* __restrict__ s,
    const float* __restrict__ Wq, const float* __restrict__ Wk, const float* __restrict__ Wv)
{
    __shared__ float tbuf[32][33];
    const int bid = blockIdx.x;
    const int tid = threadIdx.x;
    if (bid < 2048) {
        int idx = bid * 256 + tid;        // 0..524287
        float4 v = *(const float4*)&s[(size_t)idx * 4];
        __nv_bfloat16 h0, l0, h1, l1, h2, l2, h3, l3;
        split2(v.x, h0, l0); split2(v.y, h1, l1);
        split2(v.z, h2, l2); split2(v.w, h3, l3);
        uint2 hv, lv;
        hv.x = pack_bf16x2(h0, h1); hv.y = pack_bf16x2(h2, h3);
        lv.x = pack_bf16x2(l0, l1); lv.y = pack_bf16x2(l2, l3);
        *(uint2*)&g_s_hi[(size_t)idx * 4] = hv;
        *(uint2*)&g_s_lo[(size_t)idx * 4] = lv;
    } else {
        int b2  = bid - 2048;             // 0..3071
        int z   = b2 >> 10;
        int rem = b2 & 1023;
        int k0  = (rem >> 5) * 32;
        int n0  = (rem & 31) * 32;
        const float* W = (z == 0) ? Wq : (z == 1) ? Wk : Wv;
        int tx = tid & 31, ty = tid >> 5;
        #pragma unroll
        for (int i = 0; i < 4; i++) {
            int ky = ty + i * 8;
            tbuf[ky][tx] = W[(size_t)(k0 + ky) * (HH * CC) + n0 + tx];
        }
        __syncthreads();
        #pragma unroll
        for (int i = 0; i < 4; i++) {
            int ny = ty + i * 8;
            float x = tbuf[tx][ny];
            __nv_bfloat16 h, l;
            split2(x, h, l);
            size_t adr = ((size_t)z * FSZ + n0 + ny) * FSZ + k0 + tx;
            g_wt_hi[adr] = h;
            g_wt_lo[adr] = l;
        }
    }
}

// ---------------- 1) QKV projection (16 warps) + fused RoPE/split epilogue -----------
#define QTILEB (128 * PADB)               // 18432 B per piece
#define QBUF   (4 * QTILEB)               // 73728 B per chunk buffer
#define QKV_SMEM (2 * QBUF)               // 147456

__device__ __forceinline__ void qkv_issue(uint32_t buf, int z, int m0, int n0, int k0, int tid)
{
    #pragma unroll
    for (int it = 0; it < 8; it++) {
        int idx  = tid + it * 512;
        int a    = idx >> 10;
        int idx2 = idx & 1023;
        int row  = idx2 >> 3;
        int c16  = idx2 & 7;
        const __nv_bfloat16* src;
        if (a == 0)      src = &g_s_hi[(size_t)(m0 + row) * FSZ + k0 + c16 * 8];
        else if (a == 1) src = &g_s_lo[(size_t)(m0 + row) * FSZ + k0 + c16 * 8];
        else if (a == 2) src = &g_wt_hi[((size_t)z * FSZ + n0 + row) * FSZ + k0 + c16 * 8];
        else             src = &g_wt_lo[((size_t)z * FSZ + n0 + row) * FSZ + k0 + c16 * 8];
        cp_async16(buf + (uint32_t)(a * QTILEB + row * PADB + c16 * 16), src);
    }
}

__global__ void __launch_bounds__(512, 1) qkv_mma_kernel(const int* __restrict__ positions)
{
    extern __shared__ char smem[];
    const uint32_t sb = smem_to_u32(smem);
    const int tid  = threadIdx.x;
    const int lane = tid & 31;
    const int wid  = tid >> 5;        // 0..15
    const int g    = lane >> 2;
    const int t    = lane & 3;
    const int z    = blockIdx.z;
    const int m0   = blockIdx.y * 128;
    const int n0   = blockIdx.x * 128;
    const int wm   = (wid >> 1) * 16; // 8 m-strips of 16
    const int wn   = (wid & 1) * 64;  // 2 n-halves of 64 (full head per warp)

    float acc[8][4];
    #pragma unroll
    for (int j = 0; j < 8; j++)
        #pragma unroll
        for (int u = 0; u < 4; u++) acc[j][u] = 0.f;

    const uint32_t aRow  = (uint32_t)(lane & 15);
    const uint32_t aColH = (uint32_t)(lane >> 4) * 16;
    const uint32_t bTile = (uint32_t)(lane >> 3);
    const uint32_t bRow  = (bTile >> 1) * 8 + (uint32_t)(lane & 7);
    const uint32_t bColH = (bTile & 1) * 16;

    qkv_issue(sb, z, m0, n0, 0, tid);
    CP_COMMIT();

    #pragma unroll 1
    for (int c = 0; c < 16; c++) {
        const uint32_t buf = sb + (uint32_t)(c & 1) * QBUF;
        if (c + 1 < 16) {
            qkv_issue(sb + (uint32_t)((c + 1) & 1) * QBUF, z, m0, n0, (c + 1) * 64, tid);
            CP_COMMIT();
            cp_wait<1>();
        } else {
            cp_wait<0>();
        }
        __syncthreads();

        #pragma unroll
        for (int pass = 0; pass < 3; pass++) {
            const uint32_t Ao = buf + (pass == 2 ? QTILEB : 0u);
            const uint32_t Bo = buf + 2u * QTILEB + (pass == 1 ? QTILEB : 0u);
            #pragma unroll
            for (int ks = 0; ks < 4; ks++) {
                const uint32_t kb = (uint32_t)(ks * 32);
                uint32_t af[4];
                {
                    uint32_t addr = Ao + (uint32_t)(wm + aRow) * PADB + kb + aColH;
                    ldmatrix_x4(af[0], af[1], af[2], af[3], addr);
                }
                uint32_t bf[8][2];
                #pragma unroll
                for (int nf = 0; nf < 8; nf += 2) {
                    uint32_t addr = Bo + (uint32_t)(wn + nf * 8 + bRow) * PADB + kb + bColH;
                    uint32_t r0, r1, r2, r3;
                    ldmatrix_x4(r0, r1, r2, r3, addr);
                    bf[nf][0] = r0;     bf[nf][1] = r1;
                    bf[nf + 1][0] = r2; bf[nf + 1][1] = r3;
                }
                #pragma unroll
                for (int nf = 0; nf < 8; nf++)
                    mma_bf16(acc[nf], af[0], af[1], af[2], af[3], bf[nf][0], bf[nf][1]);
            }
        }
        __syncthreads();
    }

    // ---- epilogue ----
    if (z <= 1) {
        // fused RoPE + hi/lo split; pair (c, c+32) lives in (nf, nf+4) of same thread
        __nv_bfloat16* dhi = z ? g_k_hi : g_q_hi;
        __nv_bfloat16* dlo = z ? g_k_lo : g_q_lo;
        const int h = ((n0 + wn) >> 6) & 15;
        float tsv[8];
        #pragma unroll
        for (int nf = 0; nf < 4; nf++)
            #pragma unroll
            for (int j = 0; j < 2; j++) {
                int i = nf * 8 + 2 * t + j;
                tsv[nf * 2 + j] = powf(10000.0f, (float)i / 32.0f);
            }
        #pragma unroll
        for (int rh = 0; rh < 2; rh++) {
            int row = m0 + wm + g + rh * 8;
            int b   = row >> 10, n = row & 1023;
            float pos = (float)positions[b * NN + n];
            size_t base = ((size_t)(b * HH + h) * NN + n) * CC;
            #pragma unroll
            for (int nf = 0; nf < 4; nf++) {
                float o1[2], o2[2];
                #pragma unroll
                for (int j = 0; j < 2; j++) {
                    float ang = pos / tsv[nf * 2 + j];
                    float sv, cv;
                    sincosf(ang, &sv, &cv);
                    float x1 = acc[nf][rh * 2 + j];
                    float x2 = acc[nf + 4][rh * 2 + j];
                    o1[j] = x1 * cv - x2 * sv;
                    o2[j] = x2 * cv + x1 * sv;
                }
                int cc = nf * 8 + 2 * t;
                __nv_bfloat16 h0, l0, h1, l1;
                split2(o1[0], h0, l0); split2(o1[1], h1, l1);
                *(uint32_t*)&dhi[base + cc]      = pack_bf16x2(h0, h1);
                *(uint32_t*)&dlo[base + cc]      = pack_bf16x2(l0, l1);
                split2(o2[0], h0, l0); split2(o2[1], h1, l1);
                *(uint32_t*)&dhi[base + cc + 32] = pack_bf16x2(h0, h1);
                *(uint32_t*)&dlo[base + cc + 32] = pack_bf16x2(l0, l1);
            }
        }
    } else {
        #pragma unroll
        for (int nf = 0; nf < 8; nf++) {
            int row = m0 + wm + g;
            int b   = row >> 10, n = row & 1023;
            int col = n0 + wn + nf * 8 + 2 * t;
            int h   = col >> 6, cc = col & 63;
            size_t adr0 = ((size_t)(b * HH + h) * NN + n) * CC + cc;
            size_t adr1 = ((size_t)(b * HH + h) * NN + n + 8) * CC + cc;
            __nv_bfloat16 h0, l0, h1, l1;
            split2(acc[nf][0], h0, l0); split2(acc[nf][1], h1, l1);
            *(uint32_t*)&g_v_hi[adr0] = pack_bf16x2(h0, h1);
            *(uint32_t*)&g_v_lo[adr0] = pack_bf16x2(l0, l1);
            split2(acc[nf][2], h0, l0); split2(acc[nf][3], h1, l1);
            *(uint32_t*)&g_v_hi[adr1] = pack_bf16x2(h0, h1);
            *(uint32_t*)&g_v_lo[adr1] = pack_bf16x2(l0, l1);
        }
    }
}

// ---------------- 3) bias: single-converted-operand bf16 mma, 64-k chunks ------------
#define BCHK (64 * PADB)                  // 9216 B pair chunk (bf16 hi)
#define BO_WBH BCHK
#define BO_WBL (BO_WBH + 16 * PADB)
#define BIAS_SMEM (BO_WBL + 16 * PADB)    // 13824

__global__ void __launch_bounds__(256) bias_mma_kernel(
    const float* __restrict__ pair,
    const float* __restrict__ Wb,
    const int* __restrict__ seg)
{
    __shared__ char smem[BIAS_SMEM];
    const uint32_t sb = smem_to_u32(smem);
    const int tid  = threadIdx.x;
    const int lane = tid & 31;
    const int w    = tid >> 5;
    const int g    = lane >> 2;
    const int t    = lane & 3;
    const int bx   = blockIdx.x;
    const int b    = bx >> 10;
    const int q    = 1023 - (bx & 1023);       // heavy rows first
    const int segq = seg[b * NN + q];

    if (tid < 64) {
        int f = tid;
        #pragma unroll
        for (int h = 0; h < 16; h++) {
            float x = Wb[f * HH + h];
            __nv_bfloat16 hh, ll;
            split2(x, hh, ll);
            *(__nv_bfloat16*)(smem + BO_WBH + h * PADB + f * 2) = hh;
            *(__nv_bfloat16*)(smem + BO_WBL + h * PADB + f * 2) = ll;
        }
    }

    int lo = 0, hi = q;
    while (lo < hi) {
        int mid = (lo + hi) >> 1;
        if (seg[b * NN + mid] < segq) lo = mid + 1; else hi = mid;
    }
    const int kstart = lo & ~63;
    __syncthreads();

    const uint32_t aRow  = (uint32_t)(lane & 15);
    const uint32_t aColH = (uint32_t)(lane >> 4) * 16;
    uint32_t ah[4][4], alr[4][4];
    #pragma unroll
    for (int ks = 0; ks < 4; ks++) {
        uint32_t addr = sb + BO_WBH + aRow * PADB + (uint32_t)(ks * 32) + aColH;
        ldmatrix_x4(ah[ks][0],  ah[ks][1],  ah[ks][2],  ah[ks][3],  addr);
        ldmatrix_x4(alr[ks][0], alr[ks][1], alr[ks][2], alr[ks][3], addr + 16 * PADB);
    }

    const uint32_t bRow  = (uint32_t)(lane & 7);
    const uint32_t bColH = ((uint32_t)(lane >> 3) & 1) * 16;
    const float* psrc = &pair[((size_t)(b * NN + q)) * NN * FZ];

    #pragma unroll 1
    for (int k0 = kstart; k0 <= q; k0 += 64) {
        __syncthreads();
        #pragma unroll
        for (int it = 0; it < 4; it++) {
            int idx = tid + it * 256;
            int r   = idx >> 4;
            int c4  = (idx & 15) << 2;
            int row = k0 + r; if (row > 1023) row = 1023;
            float4 v = *(const float4*)&psrc[(size_t)row * FZ + c4];
            uint2 u;
            u.x = cvt_bf16x2(v.x, v.y);
            u.y = cvt_bf16x2(v.z, v.w);
            *(uint2*)(smem + r * PADB + c4 * 2) = u;
        }
        __syncthreads();

        float S[4] = {0.f, 0.f, 0.f, 0.f};
        #pragma unroll
        for (int ks = 0; ks < 4; ks++) {
            uint32_t baddr = sb + (uint32_t)(w * 8 + bRow) * PADB
                           + (uint32_t)(ks * 32) + bColH;
            uint32_t r0, r1;
            ldmatrix_x2(r0, r1, baddr);
            mma_bf16a(S, ah[ks],  r0, r1);
            mma_bf16a(S, alr[ks], r0, r1);
        }

        int k = k0 + w * 8 + 2 * t;
        if (k <= 1022) {
            __nv_bfloat16 x0 = __float2bfloat16(S[0]);
            __nv_bfloat16 x1 = __float2bfloat16(S[1]);
            __nv_bfloat16 x2 = __float2bfloat16(S[2]);
            __nv_bfloat16 x3 = __float2bfloat16(S[3]);
            *(uint32_t*)&g_bias[(((size_t)(b * HH + g))     * NN + q) * NN + k] =
                pack_bf16x2(x0, x1);
            *(uint32_t*)&g_bias[(((size_t)(b * HH + g + 8)) * NN + q) * NN + k] =
                pack_bf16x2(x2, x3);
        }
    }
}

// ---------------- 4) flash attention: cp.async pipelined, pre-split operands ---------
#define AQT (128 * PADB)                  // 18432 per Q piece
#define AKT (64 * PADB)                   // 9216 per K/V piece
#define AST (4 * AKT)                     // 36864 per stage
#define O_ST0  (2 * AQT)                  // stage 0 base
#define O_SEG  (2 * AQT + 2 * AST)        // seg[2][64] ints
#define O_LIST (O_SEG + 512)              // tile list (16) + count
#define ATTN_SMEM (O_LIST + 128)

__device__ __forceinline__ void attn_issue(uint32_t stbase, int bh, int k0, int tid)
{
    #pragma unroll
    for (int it = 0; it < 8; it++) {
        int idx  = tid + it * 256;
        int a    = idx >> 9;
        int idx2 = idx & 511;
        int row  = idx2 >> 3;
        int c16  = idx2 & 7;
        size_t e = ((size_t)bh * NN + k0 + row) * CC + c16 * 8;
        const __nv_bfloat16* src;
        if (a == 0)      src = &g_k_hi[e];
        else if (a == 1) src = &g_k_lo[e];
        else if (a == 2) src = &g_v_hi[e];
        else             src = &g_v_lo[e];
        cp_async16(stbase + (uint32_t)(a * AKT + row * PADB + c16 * 16), src);
    }
}

__global__ void __launch_bounds__(256, 1) attn_mma_kernel(
    const int* __restrict__ seg, float* __restrict__ out)
{
    extern __shared__ char smem[];
    const uint32_t sb = smem_to_u32(smem);
    int* tile_list = (int*)(smem + O_LIST);

    const int tid  = threadIdx.x;
    const int lane = tid & 31;
    const int w    = tid >> 5;
    const int g    = lane >> 2;
    const int t    = lane & 3;
    const int qt   = 7 - blockIdx.x;          // heavy tiles first
    const int h    = blockIdx.y;
    const int b    = blockIdx.z;
    const int q0   = qt * 128;
    const int bh   = b * HH + h;
    const float sm_scale = 0.125f;

    const int r0g = q0 + w * 16 + g;
    const int r1g = r0g + 8;
    const int seg_q0 = seg[b * NN + q0];
    const int myseg0 = seg[b * NN + r0g];
    const int myseg1 = seg[b * NN + r1g];
    const int jmax   = 2 * qt + 1;

    if (tid < 32) {
        bool valid = (lane <= jmax) && (seg[b * NN + lane * 64 + 63] >= seg_q0);
        uint32_t m = __ballot_sync(0xffffffffu, valid);
        if (valid) tile_list[1 + __popc(m & ((1u << lane) - 1u))] = lane;
        if (lane == 0) tile_list[0] = __popc(m);
    }
    __syncthreads();
    const int T = tile_list[0];

    {
        #pragma unroll
        for (int it = 0; it < 8; it++) {
            int idx  = tid + it * 256;
            int a    = idx >> 10;
            int idx2 = idx & 1023;
            int row  = idx2 >> 3;
            int c16  = idx2 & 7;
            size_t e = ((size_t)bh * NN + q0 + row) * CC + c16 * 8;
            const __nv_bfloat16* src = a ? &g_q_lo[e] : &g_q_hi[e];
            cp_async16(sb + (uint32_t)(a * AQT + row * PADB + c16 * 16), src);
        }
        int k0 = tile_list[1] * 64;
        attn_issue(sb + O_ST0, bh, k0, tid);
        if (tid < 16) cp_async16(sb + O_SEG + tid * 16, &seg[b * NN + k0 + tid * 4]);
        CP_COMMIT();
    }

    float O[8][4];
    #pragma unroll
    for (int nf = 0; nf < 8; nf++)
        #pragma unroll
        for (int u = 0; u < 4; u++) O[nf][u] = 0.f;
    float m0r = -1e30f, m1r = -1e30f, l0r = 0.f, l1r = 0.f;

    const uint32_t aRow  = (uint32_t)(lane & 15);
    const uint32_t aColH = (uint32_t)(lane >> 4) * 16;
    const uint32_t bTile = (uint32_t)(lane >> 3);
    const uint32_t bRow  = (bTile >> 1) * 8 + (uint32_t)(lane & 7);
    const uint32_t bColH = (bTile & 1) * 16;
    const uint32_t vRow  = (bTile & 1) * 8 + (uint32_t)(lane & 7);
    const uint32_t vColH = (uint32_t)(lane >> 4) * 16;

    const __nv_bfloat16* bias0 = &g_bias[((size_t)bh * NN + r0g) * NN];
    const __nv_bfloat16* bias1 = &g_bias[((size_t)bh * NN + r1g) * NN];

    uint32_t qh[4][4], ql[4][4];

    #pragma unroll 1
    for (int i = 0; i < T; i++) {
        const int st = i & 1;
        const uint32_t stb = sb + O_ST0 + (uint32_t)st * AST;
        if (i + 1 < T) {
            int k0n = tile_list[1 + i + 1] * 64;
            attn_issue(sb + O_ST0 + (uint32_t)(st ^ 1) * AST, bh, k0n, tid);
            if (tid < 16)
                cp_async16(sb + O_SEG + (uint32_t)(st ^ 1) * 256 + tid * 16,
                           &seg[b * NN + k0n + tid * 4]);
            CP_COMMIT();
            cp_wait<1>();
        } else {
            cp_wait<0>();
        }
        __syncthreads();

        if (i == 0) {
            #pragma unroll
            for (int ks = 0; ks < 4; ks++) {
                uint32_t qaddr = sb + (uint32_t)(w * 16 + aRow) * PADB
                               + (uint32_t)(ks * 32) + aColH;
                ldmatrix_x4(qh[ks][0], qh[ks][1], qh[ks][2], qh[ks][3], qaddr);
                ldmatrix_x4(ql[ks][0], ql[ks][1], ql[ks][2], ql[ks][3], qaddr + AQT);
            }
        }

        const int k0 = tile_list[1 + i] * 64;
        const int* seg_ks = (const int*)(smem + O_SEG + st * 256);

        float S[8][4];
        #pragma unroll
        for (int nf = 0; nf < 8; nf++)
            #pragma unroll
            for (int u = 0; u < 4; u++) S[nf][u] = 0.f;

        #pragma unroll
        for (int ks = 0; ks < 4; ks++) {
            const uint32_t kb = (uint32_t)(ks * 32);
            #pragma unroll
            for (int np = 0; np < 4; np++) {
                uint32_t kaddr = stb + (uint32_t)(np * 16 + bRow) * PADB + kb + bColH;
                uint32_t r0, r1, r2, r3;
                ldmatrix_x4(r0, r1, r2, r3, kaddr);              // K hi
                mma_bf16a(S[2 * np],     qh[ks], r0, r1);
                mma_bf16a(S[2 * np + 1], qh[ks], r2, r3);
                mma_bf16a(S[2 * np],     ql[ks], r0, r1);
                mma_bf16a(S[2 * np + 1], ql[ks], r2, r3);
                ldmatrix_x4(r0, r1, r2, r3, kaddr + AKT);        // K lo
                mma_bf16a(S[2 * np],     qh[ks], r0, r1);
                mma_bf16a(S[2 * np + 1], qh[ks], r2, r3);
            }
        }

        float mx0 = -1e30f, mx1 = -1e30f;
        #pragma unroll
        for (int nf = 0; nf < 8; nf++) {
            int cl = nf * 8 + 2 * t;
            int cg = k0 + cl;
            __nv_bfloat162 bb0 = *(const __nv_bfloat162*)&bias0[cg];
            __nv_bfloat162 bb1 = *(const __nv_bfloat162*)&bias1[cg];
            int sk0 = seg_ks[cl], sk1 = seg_ks[cl + 1];
            bool v00 = (cg     <= r0g) && (sk0 == myseg0);
            bool v01 = (cg + 1 <= r0g) && (sk1 == myseg0);
            bool v10 = (cg     <= r1g) && (sk0 == myseg1);
            bool v11 = (cg + 1 <= r1g) && (sk1 == myseg1);
            S[nf][0] = v00 ? fmaf(S[nf][0], sm_scale, __bfloat162float(bb0.x)) : -1e30f;
            S[nf][1] = v01 ? fmaf(S[nf][1], sm_scale, __bfloat162float(bb0.y)) : -1e30f;
            S[nf][2] = v10 ? fmaf(S[nf][2], sm_scale, __bfloat162float(bb1.x)) : -1e30f;
            S[nf][3] = v11 ? fmaf(S[nf][3], sm_scale, __bfloat162float(bb1.y)) : -1e30f;
            mx0 = fmaxf(mx0, fmaxf(S[nf][0], S[nf][1]));
            mx1 = fmaxf(mx1, fmaxf(S[nf][2], S[nf][3]));
        }
        mx0 = fmaxf(mx0, __shfl_xor_sync(0xffffffffu, mx0, 1));
        mx0 = fmaxf(mx0, __shfl_xor_sync(0xffffffffu, mx0, 2));
        mx1 = fmaxf(mx1, __shfl_xor_sync(0xffffffffu, mx1, 1));
        mx1 = fmaxf(mx1, __shfl_xor_sync(0xffffffffu, mx1, 2));

        float mn0 = fmaxf(m0r, mx0), mn1 = fmaxf(m1r, mx1);
        float al0 = __expf(m0r - mn0), al1 = __expf(m1r - mn1);
        m0r = mn0; m1r = mn1;

        float sum0 = 0.f, sum1 = 0.f;
        #pragma unroll
        for (int nf = 0; nf < 8; nf++) {
            float p0 = (S[nf][0] > -1e29f) ? __expf(S[nf][0] - mn0) : 0.f;
            float p1 = (S[nf][1] > -1e29f) ? __expf(S[nf][1] - mn0) : 0.f;
            float p2 = (S[nf][2] > -1e29f) ? __expf(S[nf][2] - mn1) : 0.f;
            float p3 = (S[nf][3] > -1e29f) ? __expf(S[nf][3] - mn1) : 0.f;
            S[nf][0] = p0; S[nf][1] = p1; S[nf][2] = p2; S[nf][3] = p3;
            sum0 += p0 + p1; sum1 += p2 + p3;
        }
        sum0 += __shfl_xor_sync(0xffffffffu, sum0, 1);
        sum0 += __shfl_xor_sync(0xffffffffu, sum0, 2);
        sum1 += __shfl_xor_sync(0xffffffffu, sum1, 1);
        sum1 += __shfl_xor_sync(0xffffffffu, sum1, 2);
        l0r = l0r * al0 + sum0;
        l1r = l1r * al1 + sum1;

        #pragma unroll
        for (int nf = 0; nf < 8; nf++) {
            O[nf][0] *= al0; O[nf][1] *= al0;
            O[nf][2] *= al1; O[nf][3] *= al1;
        }

        #pragma unroll
        for (int kf = 0; kf < 4; kf++) {
            uint32_t ah[4], al[4];
            {
                __nv_bfloat16 h0, l0, h1, l1;
                split2(S[2 * kf][0], h0, l0); split2(S[2 * kf][1], h1, l1);
                ah[0] = pack_bf16x2(h0, h1);  al[0] = pack_bf16x2(l0, l1);
                split2(S[2 * kf][2], h0, l0); split2(S[2 * kf][3], h1, l1);
                ah[1] = pack_bf16x2(h0, h1);  al[1] = pack_bf16x2(l0, l1);
                split2(S[2 * kf + 1][0], h0, l0); split2(S[2 * kf + 1][1], h1, l1);
                ah[2] = pack_bf16x2(h0, h1);  al[2] = pack_bf16x2(l0, l1);
                split2(S[2 * kf + 1][2], h0, l0); split2(S[2 * kf + 1][3], h1, l1);
                ah[3] = pack_bf16x2(h0, h1);  al[3] = pack_bf16x2(l0, l1);
            }
            #pragma unroll
            for (int cf = 0; cf < 4; cf++) {
                uint32_t vaddr = stb + 2u * AKT + (uint32_t)(kf * 16 + vRow) * PADB
                               + (uint32_t)(cf * 32) + vColH;
                uint32_t r0, r1, r2, r3;
                ldmatrix_x4_trans(r0, r1, r2, r3, vaddr);        // V hi
                mma_bf16a(O[2 * cf],     ah, r0, r1);
                mma_bf16a(O[2 * cf + 1], ah, r2, r3);
                mma_bf16a(O[2 * cf],     al, r0, r1);
                mma_bf16a(O[2 * cf + 1], al, r2, r3);
                ldmatrix_x4_trans(r0, r1, r2, r3, vaddr + AKT);  // V lo
                mma_bf16a(O[2 * cf],     ah, r0, r1);
                mma_bf16a(O[2 * cf + 1], ah, r2, r3);
            }
        }
        __syncthreads();
    }

    float inv0 = 1.f / l0r;
    float inv1 = 1.f / l1r;
    size_t base0 = (((size_t)(b * NN + r0g)) * HH + h) * CC;
    size_t base1 = (((size_t)(b * NN + r1g)) * HH + h) * CC;
    #pragma unroll
    for (int nf = 0; nf < 8; nf++) {
        int col = nf * 8 + 2 * t;
        *(float2*)&out[base0 + col] = make_float2(O[nf][0] * inv0, O[nf][1] * inv0);
        *(float2*)&out[base1 + col] = make_float2(O[nf][2] * inv1, O[nf][3] * inv1);
    }
}

// ---------------- launcher: bias runs concurrently with prep+qkv ----------------
extern "C" void kernel_launch(void* const* d_in, const int* in_sizes, int n_in,
                              void* d_out, int out_size)
{
    const float* s    = (const float*)d_in[0];
    const float* pair = (const float*)d_in[1];
    const int*   segs = (const int*)d_in[2];
    const int*   pos  = (const int*)d_in[3];
    const float* Wq   = (const float*)d_in[4];
    const float* Wk   = (const float*)d_in[5];
    const float* Wv   = (const float*)d_in[6];
    const float* Wb   = (const float*)d_in[7];
    float* out = (float*)d_out;

    static cudaStream_t sB = nullptr;
    static cudaEvent_t  eF = nullptr, eJ = nullptr;
    if (!sB) {
        cudaStreamCreateWithFlags(&sB, cudaStreamNonBlocking);
        cudaEventCreateWithFlags(&eF, cudaEventDisableTiming);
        cudaEventCreateWithFlags(&eJ, cudaEventDisableTiming);
    }

    cudaFuncSetAttribute(qkv_mma_kernel, cudaFuncAttributeMaxDynamicSharedMemorySize,
                         QKV_SMEM);
    cudaFuncSetAttribute(attn_mma_kernel, cudaFuncAttributeMaxDynamicSharedMemorySize,
                         ATTN_SMEM);

    // fork: bias (depends only on pair/Wb/seg) runs on sB concurrently
    cudaEventRecord(eF, 0);
    cudaStreamWaitEvent(sB, eF, 0);
    bias_mma_kernel<<<BB * NN, 256, 0, sB>>>(pair, Wb, segs);
    cudaEventRecord(eJ, sB);

    // main branch: prep -> qkv (rope fused, 16 warps)
    prep_kernel<<<5120, 256>>>(s, Wq, Wk, Wv);
    qkv_mma_kernel<<<dim3(8, 16, 3), 512, QKV_SMEM>>>(pos);

    // join, then attention
    cudaStreamWaitEvent(0, eJ, 0);
    attn_mma_kernel<<<dim3(8, HH, BB), 256, ATTN_SMEM>>>(segs, out);
}

// round 12
// speedup vs baseline: 2.6379x; 1.1573x over previous
#include <cuda_runtime.h>
#include <cuda_bf16.h>
#include <cuda_fp16.h>
#include <math.h>
#include <stdint.h>

#define BB 2
#define NN 1024
#define FSZ 1024
#define FZ 64
#define HH 16
#define CC 64

// ---------------- scratch (device globals: no runtime allocation) ----------------
__device__ __nv_bfloat16  g_q_hi[BB*HH*NN*CC];
__device__ __nv_bfloat16  g_q_lo[BB*HH*NN*CC];
__device__ __nv_bfloat16  g_k_hi[BB*HH*NN*CC];
__device__ __nv_bfloat16  g_k_lo[BB*HH*NN*CC];
__device__ __nv_bfloat16  g_v_hi[BB*HH*NN*CC];
__device__ __nv_bfloat16  g_v_lo[BB*HH*NN*CC];
__device__ __half         g_s_hi[BB*NN*FSZ];
__device__ __half         g_s_lo[BB*NN*FSZ];
__device__ __half         g_wt_hi[3*FSZ*HH*CC];              // [z][n][k], fp16 hi only
__device__ __nv_bfloat16  g_bias[(size_t)BB*HH*NN*NN];       // (b,h,q,k)

// ================= helpers =================
__device__ __forceinline__ uint32_t smem_to_u32(const void* p) {
    uint32_t a;
    asm("{ .reg .u64 t; cvta.to.shared.u64 t, %1; cvt.u32.u64 %0, t; }" : "=r"(a) : "l"(p));
    return a;
}
__device__ __forceinline__ uint32_t pack_bf16x2(__nv_bfloat16 a, __nv_bfloat16 b) {
    __nv_bfloat162 t(a, b);
    return *reinterpret_cast<uint32_t*>(&t);
}
__device__ __forceinline__ uint32_t pack_h16x2(__half a, __half b) {
    __half2 t(a, b);
    return *reinterpret_cast<uint32_t*>(&t);
}
__device__ __forceinline__ uint32_t cvt_bf16x2(float lo, float hi) {
    uint32_t r;
    asm("cvt.rn.bf16x2.f32 %0, %1, %2;" : "=r"(r) : "f"(hi), "f"(lo));
    return r;
}
__device__ __forceinline__ void split2(float x, __nv_bfloat16& h, __nv_bfloat16& l) {
    h = __float2bfloat16(x);
    l = __float2bfloat16(x - __bfloat162float(h));
}
__device__ __forceinline__ void split2h(float x, __half& h, __half& l) {
    h = __float2half_rn(x);
    l = __float2half_rn(x - __half2float(h));
}
__device__ __forceinline__ void ldmatrix_x4(uint32_t& r0, uint32_t& r1, uint32_t& r2,
                                            uint32_t& r3, uint32_t addr) {
    asm volatile("ldmatrix.sync.aligned.m8n8.x4.shared.b16 {%0,%1,%2,%3}, [%4];"
                 : "=r"(r0), "=r"(r1), "=r"(r2), "=r"(r3) : "r"(addr));
}
__device__ __forceinline__ void ldmatrix_x2(uint32_t& r0, uint32_t& r1, uint32_t addr) {
    asm volatile("ldmatrix.sync.aligned.m8n8.x2.shared.b16 {%0,%1}, [%2];"
                 : "=r"(r0), "=r"(r1) : "r"(addr));
}
__device__ __forceinline__ void ldmatrix_x4_trans(uint32_t& r0, uint32_t& r1, uint32_t& r2,
                                                  uint32_t& r3, uint32_t addr) {
    asm volatile("ldmatrix.sync.aligned.m8n8.x4.trans.shared.b16 {%0,%1,%2,%3}, [%4];"
                 : "=r"(r0), "=r"(r1), "=r"(r2), "=r"(r3) : "r"(addr));
}
__device__ __forceinline__ void mma_bf16(float* c, uint32_t a0, uint32_t a1, uint32_t a2,
                                         uint32_t a3, uint32_t b0, uint32_t b1) {
    asm volatile(
        "mma.sync.aligned.m16n8k16.row.col.f32.bf16.bf16.f32 "
        "{%0,%1,%2,%3}, {%4,%5,%6,%7}, {%8,%9}, {%0,%1,%2,%3};"
        : "+f"(c[0]), "+f"(c[1]), "+f"(c[2]), "+f"(c[3])
        : "r"(a0), "r"(a1), "r"(a2), "r"(a3), "r"(b0), "r"(b1));
}
__device__ __forceinline__ void mma_f16(float* c, uint32_t a0, uint32_t a1, uint32_t a2,
                                        uint32_t a3, uint32_t b0, uint32_t b1) {
    asm volatile(
        "mma.sync.aligned.m16n8k16.row.col.f32.f16.f16.f32 "
        "{%0,%1,%2,%3}, {%4,%5,%6,%7}, {%8,%9}, {%0,%1,%2,%3};"
        : "+f"(c[0]), "+f"(c[1]), "+f"(c[2]), "+f"(c[3])
        : "r"(a0), "r"(a1), "r"(a2), "r"(a3), "r"(b0), "r"(b1));
}
__device__ __forceinline__ void mma_bf16a(float* c, const uint32_t* a, uint32_t b0, uint32_t b1) {
    mma_bf16(c, a[0], a[1], a[2], a[3], b0, b1);
}
__device__ __forceinline__ void cp_async16(uint32_t dst, const void* src) {
    asm volatile(
        "{ .reg .u64 g; cvta.to.global.u64 g, %1; cp.async.cg.shared.global [%0], [g], 16; }"
        :: "r"(dst), "l"(src) : "memory");
}
#define CP_COMMIT() asm volatile("cp.async.commit_group;" ::: "memory")
template<int N> __device__ __forceinline__ void cp_wait() {
    asm volatile("cp.async.wait_group %0;" :: "n"(N) : "memory");
}

#define PADB 144                  // padded row stride in bytes (72 halfwords)

// ---------------- 0) merged prep: split s (fp16 hi/lo), transpose W (fp16 hi) --------
__global__ void __launch_bounds__(256) prep_kernel(
    const float* __restrict__ s,
    const float* __restrict__ Wq, const float* __restrict__ Wk, const float* __restrict__ Wv)
{
    __shared__ float tbuf[32][33];
    const int bid = blockIdx.x;
    const int tid = threadIdx.x;
    if (bid < 2048) {
        int idx = bid * 256 + tid;        // 0..524287
        float4 v = *(const float4*)&s[(size_t)idx * 4];
        __half h0, l0, h1, l1, h2, l2, h3, l3;
        split2h(v.x, h0, l0); split2h(v.y, h1, l1);
        split2h(v.z, h2, l2); split2h(v.w, h3, l3);
        uint2 hv, lv;
        hv.x = pack_h16x2(h0, h1); hv.y = pack_h16x2(h2, h3);
        lv.x = pack_h16x2(l0, l1); lv.y = pack_h16x2(l2, l3);
        *(uint2*)&g_s_hi[(size_t)idx * 4] = hv;
        *(uint2*)&g_s_lo[(size_t)idx * 4] = lv;
    } else {
        int b2  = bid - 2048;             // 0..3071
        int z   = b2 >> 10;
        int rem = b2 & 1023;
        int k0  = (rem >> 5) * 32;
        int n0  = (rem & 31) * 32;
        const float* W = (z == 0) ? Wq : (z == 1) ? Wk : Wv;
        int tx = tid & 31, ty = tid >> 5;
        #pragma unroll
        for (int i = 0; i < 4; i++) {
            int ky = ty + i * 8;
            tbuf[ky][tx] = W[(size_t)(k0 + ky) * (HH * CC) + n0 + tx];
        }
        __syncthreads();
        #pragma unroll
        for (int i = 0; i < 4; i++) {
            int ny = ty + i * 8;
            size_t adr = ((size_t)z * FSZ + n0 + ny) * FSZ + k0 + tx;
            g_wt_hi[adr] = __float2half_rn(tbuf[tx][ny]);
        }
    }
}

// ---------------- 1) QKV projection: 2-pass fp16, cp.async double-buffered -----------
#define QTILEB (128 * PADB)               // 18432 B per piece
#define QBUF   (3 * QTILEB)               // 55296 B per chunk buffer (A_hi, A_lo, B_hi)
#define QKV_SMEM (2 * QBUF)               // 110592

__device__ __forceinline__ void qkv_issue(uint32_t buf, int z, int m0, int n0, int k0, int tid)
{
    #pragma unroll
    for (int it = 0; it < 6; it++) {
        int idx  = tid + it * 512;        // 0..3071
        int a    = idx >> 10;             // 0..2
        int idx2 = idx & 1023;
        int row  = idx2 >> 3;
        int c16  = idx2 & 7;
        const __half* src;
        if (a == 0)      src = &g_s_hi[(size_t)(m0 + row) * FSZ + k0 + c16 * 8];
        else if (a == 1) src = &g_s_lo[(size_t)(m0 + row) * FSZ + k0 + c16 * 8];
        else             src = &g_wt_hi[((size_t)z * FSZ + n0 + row) * FSZ + k0 + c16 * 8];
        cp_async16(buf + (uint32_t)(a * QTILEB + row * PADB + c16 * 16), src);
    }
}

__global__ void __launch_bounds__(512, 1) qkv_mma_kernel(const int* __restrict__ positions)
{
    extern __shared__ char smem[];
    const uint32_t sb = smem_to_u32(smem);
    const int tid  = threadIdx.x;
    const int lane = tid & 31;
    const int wid  = tid >> 5;        // 0..15
    const int g    = lane >> 2;
    const int t    = lane & 3;
    const int z    = blockIdx.z;
    const int m0   = blockIdx.y * 128;
    const int n0   = blockIdx.x * 128;
    const int wm   = (wid >> 1) * 16; // 8 m-strips of 16
    const int wn   = (wid & 1) * 64;  // 2 n-halves of 64 (full head per warp)

    float acc[8][4];
    #pragma unroll
    for (int j = 0; j < 8; j++)
        #pragma unroll
        for (int u = 0; u < 4; u++) acc[j][u] = 0.f;

    const uint32_t aRow  = (uint32_t)(lane & 15);
    const uint32_t aColH = (uint32_t)(lane >> 4) * 16;
    const uint32_t bTile = (uint32_t)(lane >> 3);
    const uint32_t bRow  = (bTile >> 1) * 8 + (uint32_t)(lane & 7);
    const uint32_t bColH = (bTile & 1) * 16;

    qkv_issue(sb, z, m0, n0, 0, tid);
    CP_COMMIT();

    #pragma unroll 1
    for (int c = 0; c < 16; c++) {
        const uint32_t buf = sb + (uint32_t)(c & 1) * QBUF;
        if (c + 1 < 16) {
            qkv_issue(sb + (uint32_t)((c + 1) & 1) * QBUF, z, m0, n0, (c + 1) * 64, tid);
            CP_COMMIT();
            cp_wait<1>();
        } else {
            cp_wait<0>();
        }
        __syncthreads();

        #pragma unroll
        for (int pass = 0; pass < 2; pass++) {
            const uint32_t Ao = buf + (pass == 1 ? QTILEB : 0u);
            const uint32_t Bo = buf + 2u * QTILEB;
            #pragma unroll
            for (int ks = 0; ks < 4; ks++) {
                const uint32_t kb = (uint32_t)(ks * 32);
                uint32_t af[4];
                {
                    uint32_t addr = Ao + (uint32_t)(wm + aRow) * PADB + kb + aColH;
                    ldmatrix_x4(af[0], af[1], af[2], af[3], addr);
                }
                uint32_t bf[8][2];
                #pragma unroll
                for (int nf = 0; nf < 8; nf += 2) {
                    uint32_t addr = Bo + (uint32_t)(wn + nf * 8 + bRow) * PADB + kb + bColH;
                    uint32_t r0, r1, r2, r3;
                    ldmatrix_x4(r0, r1, r2, r3, addr);
                    bf[nf][0] = r0;     bf[nf][1] = r1;
                    bf[nf + 1][0] = r2; bf[nf + 1][1] = r3;
                }
                #pragma unroll
                for (int nf = 0; nf < 8; nf++)
                    mma_f16(acc[nf], af[0], af[1], af[2], af[3], bf[nf][0], bf[nf][1]);
            }
        }
        __syncthreads();
    }

    // ---- epilogue (unchanged formats: q/k/v stored bf16 hi/lo) ----
    if (z <= 1) {
        __nv_bfloat16* dhi = z ? g_k_hi : g_q_hi;
        __nv_bfloat16* dlo = z ? g_k_lo : g_q_lo;
        const int h = ((n0 + wn) >> 6) & 15;
        float tsv[8];
        #pragma unroll
        for (int nf = 0; nf < 4; nf++)
            #pragma unroll
            for (int j = 0; j < 2; j++) {
                int i = nf * 8 + 2 * t + j;
                tsv[nf * 2 + j] = powf(10000.0f, (float)i / 32.0f);
            }
        #pragma unroll
        for (int rh = 0; rh < 2; rh++) {
            int row = m0 + wm + g + rh * 8;
            int b   = row >> 10, n = row & 1023;
            float pos = (float)positions[b * NN + n];
            size_t base = ((size_t)(b * HH + h) * NN + n) * CC;
            #pragma unroll
            for (int nf = 0; nf < 4; nf++) {
                float o1[2], o2[2];
                #pragma unroll
                for (int j = 0; j < 2; j++) {
                    float ang = pos / tsv[nf * 2 + j];
                    float sv, cv;
                    sincosf(ang, &sv, &cv);
                    float x1 = acc[nf][rh * 2 + j];
                    float x2 = acc[nf + 4][rh * 2 + j];
                    o1[j] = x1 * cv - x2 * sv;
                    o2[j] = x2 * cv + x1 * sv;
                }
                int cc = nf * 8 + 2 * t;
                __nv_bfloat16 h0, l0, h1, l1;
                split2(o1[0], h0, l0); split2(o1[1], h1, l1);
                *(uint32_t*)&dhi[base + cc]      = pack_bf16x2(h0, h1);
                *(uint32_t*)&dlo[base + cc]      = pack_bf16x2(l0, l1);
                split2(o2[0], h0, l0); split2(o2[1], h1, l1);
                *(uint32_t*)&dhi[base + cc + 32] = pack_bf16x2(h0, h1);
                *(uint32_t*)&dlo[base + cc + 32] = pack_bf16x2(l0, l1);
            }
        }
    } else {
        #pragma unroll
        for (int nf = 0; nf < 8; nf++) {
            int row = m0 + wm + g;
            int b   = row >> 10, n = row & 1023;
            int col = n0 + wn + nf * 8 + 2 * t;
            int h   = col >> 6, cc = col & 63;
            size_t adr0 = ((size_t)(b * HH + h) * NN + n) * CC + cc;
            size_t adr1 = ((size_t)(b * HH + h) * NN + n + 8) * CC + cc;
            __nv_bfloat16 h0, l0, h1, l1;
            split2(acc[nf][0], h0, l0); split2(acc[nf][1], h1, l1);
            *(uint32_t*)&g_v_hi[adr0] = pack_bf16x2(h0, h1);
            *(uint32_t*)&g_v_lo[adr0] = pack_bf16x2(l0, l1);
            split2(acc[nf][2], h0, l0); split2(acc[nf][3], h1, l1);
            *(uint32_t*)&g_v_hi[adr1] = pack_bf16x2(h0, h1);
            *(uint32_t*)&g_v_lo[adr1] = pack_bf16x2(l0, l1);
        }
    }
}

// ---------------- 3) bias: single-converted-operand bf16 mma, 64-k chunks ------------
#define BCHK (64 * PADB)                  // 9216 B pair chunk (bf16 hi)
#define BO_WBH BCHK
#define BO_WBL (BO_WBH + 16 * PADB)
#define BIAS_SMEM (BO_WBL + 16 * PADB)    // 13824

__global__ void __launch_bounds__(256) bias_mma_kernel(
    const float* __restrict__ pair,
    const float* __restrict__ Wb,
    const int* __restrict__ seg)
{
    __shared__ char smem[BIAS_SMEM];
    const uint32_t sb = smem_to_u32(smem);
    const int tid  = threadIdx.x;
    const int lane = tid & 31;
    const int w    = tid >> 5;
    const int g    = lane >> 2;
    const int t    = lane & 3;
    const int bx   = blockIdx.x;
    const int b    = bx >> 10;
    const int q    = 1023 - (bx & 1023);       // heavy rows first
    const int segq = seg[b * NN + q];

    if (tid < 64) {
        int f = tid;
        #pragma unroll
        for (int h = 0; h < 16; h++) {
            float x = Wb[f * HH + h];
            __nv_bfloat16 hh, ll;
            split2(x, hh, ll);
            *(__nv_bfloat16*)(smem + BO_WBH + h * PADB + f * 2) = hh;
            *(__nv_bfloat16*)(smem + BO_WBL + h * PADB + f * 2) = ll;
        }
    }

    int lo = 0, hi = q;
    while (lo < hi) {
        int mid = (lo + hi) >> 1;
        if (seg[b * NN + mid] < segq) lo = mid + 1; else hi = mid;
    }
    const int kstart = lo & ~63;
    __syncthreads();

    const uint32_t aRow  = (uint32_t)(lane & 15);
    const uint32_t aColH = (uint32_t)(lane >> 4) * 16;
    uint32_t ah[4][4], alr[4][4];
    #pragma unroll
    for (int ks = 0; ks < 4; ks++) {
        uint32_t addr = sb + BO_WBH + aRow * PADB + (uint32_t)(ks * 32) + aColH;
        ldmatrix_x4(ah[ks][0],  ah[ks][1],  ah[ks][2],  ah[ks][3],  addr);
        ldmatrix_x4(alr[ks][0], alr[ks][1], alr[ks][2], alr[ks][3], addr + 16 * PADB);
    }

    const uint32_t bRow  = (uint32_t)(lane & 7);
    const uint32_t bColH = ((uint32_t)(lane >> 3) & 1) * 16;
    const float* psrc = &pair[((size_t)(b * NN + q)) * NN * FZ];

    #pragma unroll 1
    for (int k0 = kstart; k0 <= q; k0 += 64) {
        __syncthreads();
        #pragma unroll
        for (int it = 0; it < 4; it++) {
            int idx = tid + it * 256;
            int r   = idx >> 4;
            int c4  = (idx & 15) << 2;
            int row = k0 + r; if (row > 1023) row = 1023;
            float4 v = *(const float4*)&psrc[(size_t)row * FZ + c4];
            uint2 u;
            u.x = cvt_bf16x2(v.x, v.y);
            u.y = cvt_bf16x2(v.z, v.w);
            *(uint2*)(smem + r * PADB + c4 * 2) = u;
        }
        __syncthreads();

        float S[4] = {0.f, 0.f, 0.f, 0.f};
        #pragma unroll
        for (int ks = 0; ks < 4; ks++) {
            uint32_t baddr = sb + (uint32_t)(w * 8 + bRow) * PADB
                           + (uint32_t)(ks * 32) + bColH;
            uint32_t r0, r1;
            ldmatrix_x2(r0, r1, baddr);
            mma_bf16a(S, ah[ks],  r0, r1);
            mma_bf16a(S, alr[ks], r0, r1);
        }

        int k = k0 + w * 8 + 2 * t;
        if (k <= 1022) {
            __nv_bfloat16 x0 = __float2bfloat16(S[0]);
            __nv_bfloat16 x1 = __float2bfloat16(S[1]);
            __nv_bfloat16 x2 = __float2bfloat16(S[2]);
            __nv_bfloat16 x3 = __float2bfloat16(S[3]);
            *(uint32_t*)&g_bias[(((size_t)(b * HH + g))     * NN + q) * NN + k] =
                pack_bf16x2(x0, x1);
            *(uint32_t*)&g_bias[(((size_t)(b * HH + g + 8)) * NN + q) * NN + k] =
                pack_bf16x2(x2, x3);
        }
    }
}

// ---------------- 4) flash attention: cp.async pipelined, pre-split operands ---------
#define AQT (128 * PADB)                  // 18432 per Q piece
#define AKT (64 * PADB)                   // 9216 per K/V piece
#define AST (4 * AKT)                     // 36864 per stage
#define O_ST0  (2 * AQT)                  // stage 0 base
#define O_SEG  (2 * AQT + 2 * AST)        // seg[2][64] ints
#define O_LIST (O_SEG + 512)              // tile list (16) + count
#define ATTN_SMEM (O_LIST + 128)

__device__ __forceinline__ void attn_issue(uint32_t stbase, int bh, int k0, int tid)
{
    #pragma unroll
    for (int it = 0; it < 8; it++) {
        int idx  = tid + it * 256;
        int a    = idx >> 9;
        int idx2 = idx & 511;
        int row  = idx2 >> 3;
        int c16  = idx2 & 7;
        size_t e = ((size_t)bh * NN + k0 + row) * CC + c16 * 8;
        const __nv_bfloat16* src;
        if (a == 0)      src = &g_k_hi[e];
        else if (a == 1) src = &g_k_lo[e];
        else if (a == 2) src = &g_v_hi[e];
        else             src = &g_v_lo[e];
        cp_async16(stbase + (uint32_t)(a * AKT + row * PADB + c16 * 16), src);
    }
}

__global__ void __launch_bounds__(256, 1) attn_mma_kernel(
    const int* __restrict__ seg, float* __restrict__ out)
{
    extern __shared__ char smem[];
    const uint32_t sb = smem_to_u32(smem);
    int* tile_list = (int*)(smem + O_LIST);

    const int tid  = threadIdx.x;
    const int lane = tid & 31;
    const int w    = tid >> 5;
    const int g    = lane >> 2;
    const int t    = lane & 3;
    const int qt   = 7 - blockIdx.x;          // heavy tiles first
    const int h    = blockIdx.y;
    const int b    = blockIdx.z;
    const int q0   = qt * 128;
    const int bh   = b * HH + h;
    const float sm_scale = 0.125f;

    const int r0g = q0 + w * 16 + g;
    const int r1g = r0g + 8;
    const int seg_q0 = seg[b * NN + q0];
    const int myseg0 = seg[b * NN + r0g];
    const int myseg1 = seg[b * NN + r1g];
    const int jmax   = 2 * qt + 1;

    if (tid < 32) {
        bool valid = (lane <= jmax) && (seg[b * NN + lane * 64 + 63] >= seg_q0);
        uint32_t m = __ballot_sync(0xffffffffu, valid);
        if (valid) tile_list[1 + __popc(m & ((1u << lane) - 1u))] = lane;
        if (lane == 0) tile_list[0] = __popc(m);
    }
    __syncthreads();
    const int T = tile_list[0];

    {
        #pragma unroll
        for (int it = 0; it < 8; it++) {
            int idx  = tid + it * 256;
            int a    = idx >> 10;
            int idx2 = idx & 1023;
            int row  = idx2 >> 3;
            int c16  = idx2 & 7;
            size_t e = ((size_t)bh * NN + q0 + row) * CC + c16 * 8;
            const __nv_bfloat16* src = a ? &g_q_lo[e] : &g_q_hi[e];
            cp_async16(sb + (uint32_t)(a * AQT + row * PADB + c16 * 16), src);
        }
        int k0 = tile_list[1] * 64;
        attn_issue(sb + O_ST0, bh, k0, tid);
        if (tid < 16) cp_async16(sb + O_SEG + tid * 16, &seg[b * NN + k0 + tid * 4]);
        CP_COMMIT();
    }

    float O[8][4];
    #pragma unroll
    for (int nf = 0; nf < 8; nf++)
        #pragma unroll
        for (int u = 0; u < 4; u++) O[nf][u] = 0.f;
    float m0r = -1e30f, m1r = -1e30f, l0r = 0.f, l1r = 0.f;

    const uint32_t aRow  = (uint32_t)(lane & 15);
    const uint32_t aColH = (uint32_t)(lane >> 4) * 16;
    const uint32_t bTile = (uint32_t)(lane >> 3);
    const uint32_t bRow  = (bTile >> 1) * 8 + (uint32_t)(lane & 7);
    const uint32_t bColH = (bTile & 1) * 16;
    const uint32_t vRow  = (bTile & 1) * 8 + (uint32_t)(lane & 7);
    const uint32_t vColH = (uint32_t)(lane >> 4) * 16;

    const __nv_bfloat16* bias0 = &g_bias[((size_t)bh * NN + r0g) * NN];
    const __nv_bfloat16* bias1 = &g_bias[((size_t)bh * NN + r1g) * NN];

    uint32_t qh[4][4], ql[4][4];

    #pragma unroll 1
    for (int i = 0; i < T; i++) {
        const int st = i & 1;
        const uint32_t stb = sb + O_ST0 + (uint32_t)st * AST;
        if (i + 1 < T) {
            int k0n = tile_list[1 + i + 1] * 64;
            attn_issue(sb + O_ST0 + (uint32_t)(st ^ 1) * AST, bh, k0n, tid);
            if (tid < 16)
                cp_async16(sb + O_SEG + (uint32_t)(st ^ 1) * 256 + tid * 16,
                           &seg[b * NN + k0n + tid * 4]);
            CP_COMMIT();
            cp_wait<1>();
        } else {
            cp_wait<0>();
        }
        __syncthreads();

        if (i == 0) {
            #pragma unroll
            for (int ks = 0; ks < 4; ks++) {
                uint32_t qaddr = sb + (uint32_t)(w * 16 + aRow) * PADB
                               + (uint32_t)(ks * 32) + aColH;
                ldmatrix_x4(qh[ks][0], qh[ks][1], qh[ks][2], qh[ks][3], qaddr);
                ldmatrix_x4(ql[ks][0], ql[ks][1], ql[ks][2], ql[ks][3], qaddr + AQT);
            }
        }

        const int k0 = tile_list[1 + i] * 64;
        const int* seg_ks = (const int*)(smem + O_SEG + st * 256);

        float S[8][4];
        #pragma unroll
        for (int nf = 0; nf < 8; nf++)
            #pragma unroll
            for (int u = 0; u < 4; u++) S[nf][u] = 0.f;

        #pragma unroll
        for (int ks = 0; ks < 4; ks++) {
            const uint32_t kb = (uint32_t)(ks * 32);
            #pragma unroll
            for (int np = 0; np < 4; np++) {
                uint32_t kaddr = stb + (uint32_t)(np * 16 + bRow) * PADB + kb + bColH;
                uint32_t r0, r1, r2, r3;
                ldmatrix_x4(r0, r1, r2, r3, kaddr);              // K hi
                mma_bf16a(S[2 * np],     qh[ks], r0, r1);
                mma_bf16a(S[2 * np + 1], qh[ks], r2, r3);
                mma_bf16a(S[2 * np],     ql[ks], r0, r1);
                mma_bf16a(S[2 * np + 1], ql[ks], r2, r3);
                ldmatrix_x4(r0, r1, r2, r3, kaddr + AKT);        // K lo
                mma_bf16a(S[2 * np],     qh[ks], r0, r1);
                mma_bf16a(S[2 * np + 1], qh[ks], r2, r3);
            }
        }

        float mx0 = -1e30f, mx1 = -1e30f;
        #pragma unroll
        for (int nf = 0; nf < 8; nf++) {
            int cl = nf * 8 + 2 * t;
            int cg = k0 + cl;
            __nv_bfloat162 bb0 = *(const __nv_bfloat162*)&bias0[cg];
            __nv_bfloat162 bb1 = *(const __nv_bfloat162*)&bias1[cg];
            int sk0 = seg_ks[cl], sk1 = seg_ks[cl + 1];
            bool v00 = (cg     <= r0g) && (sk0 == myseg0);
            bool v01 = (cg + 1 <= r0g) && (sk1 == myseg0);
            bool v10 = (cg     <= r1g) && (sk0 == myseg1);
            bool v11 = (cg + 1 <= r1g) && (sk1 == myseg1);
            S[nf][0] = v00 ? fmaf(S[nf][0], sm_scale, __bfloat162float(bb0.x)) : -1e30f;
            S[nf][1] = v01 ? fmaf(S[nf][1], sm_scale, __bfloat162float(bb0.y)) : -1e30f;
            S[nf][2] = v10 ? fmaf(S[nf][2], sm_scale, __bfloat162float(bb1.x)) : -1e30f;
            S[nf][3] = v11 ? fmaf(S[nf][3], sm_scale, __bfloat162float(bb1.y)) : -1e30f;
            mx0 = fmaxf(mx0, fmaxf(S[nf][0], S[nf][1]));
            mx1 = fmaxf(mx1, fmaxf(S[nf][2], S[nf][3]));
        }
        mx0 = fmaxf(mx0, __shfl_xor_sync(0xffffffffu, mx0, 1));
        mx0 = fmaxf(mx0, __shfl_xor_sync(0xffffffffu, mx0, 2));
        mx1 = fmaxf(mx1, __shfl_xor_sync(0xffffffffu, mx1, 1));
        mx1 = fmaxf(mx1, __shfl_xor_sync(0xffffffffu, mx1, 2));

        float mn0 = fmaxf(m0r, mx0), mn1 = fmaxf(m1r, mx1);
        float al0 = __expf(m0r - mn0), al1 = __expf(m1r - mn1);
        m0r = mn0; m1r = mn1;

        float sum0 = 0.f, sum1 = 0.f;
        #pragma unroll
        for (int nf = 0; nf < 8; nf++) {
            float p0 = (S[nf][0] > -1e29f) ? __expf(S[nf][0] - mn0) : 0.f;
            float p1 = (S[nf][1] > -1e29f) ? __expf(S[nf][1] - mn0) : 0.f;
            float p2 = (S[nf][2] > -1e29f) ? __expf(S[nf][2] - mn1) : 0.f;
            float p3 = (S[nf][3] > -1e29f) ? __expf(S[nf][3] - mn1) : 0.f;
            S[nf][0] = p0; S[nf][1] = p1; S[nf][2] = p2; S[nf][3] = p3;
            sum0 += p0 + p1; sum1 += p2 + p3;
        }
        sum0 += __shfl_xor_sync(0xffffffffu, sum0, 1);
        sum0 += __shfl_xor_sync(0xffffffffu, sum0, 2);
        sum1 += __shfl_xor_sync(0xffffffffu, sum1, 1);
        sum1 += __shfl_xor_sync(0xffffffffu, sum1, 2);
        l0r = l0r * al0 + sum0;
        l1r = l1r * al1 + sum1;

        #pragma unroll
        for (int nf = 0; nf < 8; nf++) {
            O[nf][0] *= al0; O[nf][1] *= al0;
            O[nf][2] *= al1; O[nf][3] *= al1;
        }

        #pragma unroll
        for (int kf = 0; kf < 4; kf++) {
            uint32_t ah[4], al[4];
            {
                __nv_bfloat16 h0, l0, h1, l1;
                split2(S[2 * kf][0], h0, l0); split2(S[2 * kf][1], h1, l1);
                ah[0] = pack_bf16x2(h0, h1);  al[0] = pack_bf16x2(l0, l1);
                split2(S[2 * kf][2], h0, l0); split2(S[2 * kf][3], h1, l1);
                ah[1] = pack_bf16x2(h0, h1);  al[1] = pack_bf16x2(l0, l1);
                split2(S[2 * kf + 1][0], h0, l0); split2(S[2 * kf + 1][1], h1, l1);
                ah[2] = pack_bf16x2(h0, h1);  al[2] = pack_bf16x2(l0, l1);
                split2(S[2 * kf + 1][2], h0, l0); split2(S[2 * kf + 1][3], h1, l1);
                ah[3] = pack_bf16x2(h0, h1);  al[3] = pack_bf16x2(l0, l1);
            }
            #pragma unroll
            for (int cf = 0; cf < 4; cf++) {
                uint32_t vaddr = stb + 2u * AKT + (uint32_t)(kf * 16 + vRow) * PADB
                               + (uint32_t)(cf * 32) + vColH;
                uint32_t r0, r1, r2, r3;
                ldmatrix_x4_trans(r0, r1, r2, r3, vaddr);        // V hi
                mma_bf16a(O[2 * cf],     ah, r0, r1);
                mma_bf16a(O[2 * cf + 1], ah, r2, r3);
                mma_bf16a(O[2 * cf],     al, r0, r1);
                mma_bf16a(O[2 * cf + 1], al, r2, r3);
                ldmatrix_x4_trans(r0, r1, r2, r3, vaddr + AKT);  // V lo
                mma_bf16a(O[2 * cf],     ah, r0, r1);
                mma_bf16a(O[2 * cf + 1], ah, r2, r3);
            }
        }
        __syncthreads();
    }

    float inv0 = 1.f / l0r;
    float inv1 = 1.f / l1r;
    size_t base0 = (((size_t)(b * NN + r0g)) * HH + h) * CC;
    size_t base1 = (((size_t)(b * NN + r1g)) * HH + h) * CC;
    #pragma unroll
    for (int nf = 0; nf < 8; nf++) {
        int col = nf * 8 + 2 * t;
        *(float2*)&out[base0 + col] = make_float2(O[nf][0] * inv0, O[nf][1] * inv0);
        *(float2*)&out[base1 + col] = make_float2(O[nf][2] * inv1, O[nf][3] * inv1);
    }
}

// ---------------- launcher: bias runs concurrently with prep+qkv ----------------
extern "C" void kernel_launch(void* const* d_in, const int* in_sizes, int n_in,
                              void* d_out, int out_size)
{
    const float* s    = (const float*)d_in[0];
    const float* pair = (const float*)d_in[1];
    const int*   segs = (const int*)d_in[2];
    const int*   pos  = (const int*)d_in[3];
    const float* Wq   = (const float*)d_in[4];
    const float* Wk   = (const float*)d_in[5];
    const float* Wv   = (const float*)d_in[6];
    const float* Wb   = (const float*)d_in[7];
    float* out = (float*)d_out;

    static cudaStream_t sB = nullptr;
    static cudaEvent_t  eF = nullptr, eJ = nullptr;
    if (!sB) {
        cudaStreamCreateWithFlags(&sB, cudaStreamNonBlocking);
        cudaEventCreateWithFlags(&eF, cudaEventDisableTiming);
        cudaEventCreateWithFlags(&eJ, cudaEventDisableTiming);
    }

    cudaFuncSetAttribute(qkv_mma_kernel, cudaFuncAttributeMaxDynamicSharedMemorySize,
                         QKV_SMEM);
    cudaFuncSetAttribute(attn_mma_kernel, cudaFuncAttributeMaxDynamicSharedMemorySize,
                         ATTN_SMEM);

    // fork: bias (depends only on pair/Wb/seg) runs on sB concurrently
    cudaEventRecord(eF, 0);
    cudaStreamWaitEvent(sB, eF, 0);
    bias_mma_kernel<<<BB * NN, 256, 0, sB>>>(pair, Wb, segs);
    cudaEventRecord(eJ, sB);

    // main branch: prep -> qkv (2-pass fp16, rope fused)
    prep_kernel<<<5120, 256>>>(s, Wq, Wk, Wv);
    qkv_mma_kernel<<<dim3(8, 16, 3), 512, QKV_SMEM>>>(pos);

    // join, then attention
    cudaStreamWaitEvent(0, eJ, 0);
    attn_mma_kernel<<<dim3(8, HH, BB), 256, ATTN_SMEM>>>(segs, out);
}

// round 13
// speedup vs baseline: 2.7712x; 1.0505x over previous
#include <cuda_runtime.h>
#include <cuda_bf16.h>
#include <cuda_fp16.h>
#include <math.h>
#include <stdint.h>

#define BB 2
#define NN 1024
#define FSZ 1024
#define FZ 64
#define HH 16
#define CC 64

// ---------------- scratch (device globals: no runtime allocation) ----------------
__device__ __half         g_q_hi[BB*HH*NN*CC];
__device__ __half         g_q_lo[BB*HH*NN*CC];
__device__ __half         g_k_hi[BB*HH*NN*CC];               // fp16 hi only
__device__ __half         g_v_hi[BB*HH*NN*CC];               // fp16 hi only
__device__ __half         g_s_hi[BB*NN*FSZ];
__device__ __half         g_s_lo[BB*NN*FSZ];
__device__ __half         g_wt_hi[3*FSZ*HH*CC];              // [z][n][k], fp16 hi only
__device__ __nv_bfloat16  g_bias[(size_t)BB*HH*NN*NN];       // (b,h,q,k)

// ================= helpers =================
__device__ __forceinline__ uint32_t smem_to_u32(const void* p) {
    uint32_t a;
    asm("{ .reg .u64 t; cvta.to.shared.u64 t, %1; cvt.u32.u64 %0, t; }" : "=r"(a) : "l"(p));
    return a;
}
__device__ __forceinline__ uint32_t pack_bf16x2(__nv_bfloat16 a, __nv_bfloat16 b) {
    __nv_bfloat162 t(a, b);
    return *reinterpret_cast<uint32_t*>(&t);
}
__device__ __forceinline__ uint32_t pack_h16x2(__half a, __half b) {
    __half2 t(a, b);
    return *reinterpret_cast<uint32_t*>(&t);
}
__device__ __forceinline__ uint32_t cvt_bf16x2(float lo, float hi) {
    uint32_t r;
    asm("cvt.rn.bf16x2.f32 %0, %1, %2;" : "=r"(r) : "f"(hi), "f"(lo));
    return r;
}
__device__ __forceinline__ void split2(float x, __nv_bfloat16& h, __nv_bfloat16& l) {
    h = __float2bfloat16(x);
    l = __float2bfloat16(x - __bfloat162float(h));
}
__device__ __forceinline__ void split2h(float x, __half& h, __half& l) {
    h = __float2half_rn(x);
    l = __float2half_rn(x - __half2float(h));
}
__device__ __forceinline__ void ldmatrix_x4(uint32_t& r0, uint32_t& r1, uint32_t& r2,
                                            uint32_t& r3, uint32_t addr) {
    asm volatile("ldmatrix.sync.aligned.m8n8.x4.shared.b16 {%0,%1,%2,%3}, [%4];"
                 : "=r"(r0), "=r"(r1), "=r"(r2), "=r"(r3) : "r"(addr));
}
__device__ __forceinline__ void ldmatrix_x2(uint32_t& r0, uint32_t& r1, uint32_t addr) {
    asm volatile("ldmatrix.sync.aligned.m8n8.x2.shared.b16 {%0,%1}, [%2];"
                 : "=r"(r0), "=r"(r1) : "r"(addr));
}
__device__ __forceinline__ void ldmatrix_x4_trans(uint32_t& r0, uint32_t& r1, uint32_t& r2,
                                                  uint32_t& r3, uint32_t addr) {
    asm volatile("ldmatrix.sync.aligned.m8n8.x4.trans.shared.b16 {%0,%1,%2,%3}, [%4];"
                 : "=r"(r0), "=r"(r1), "=r"(r2), "=r"(r3) : "r"(addr));
}
__device__ __forceinline__ void mma_bf16(float* c, uint32_t a0, uint32_t a1, uint32_t a2,
                                         uint32_t a3, uint32_t b0, uint32_t b1) {
    asm volatile(
        "mma.sync.aligned.m16n8k16.row.col.f32.bf16.bf16.f32 "
        "{%0,%1,%2,%3}, {%4,%5,%6,%7}, {%8,%9}, {%0,%1,%2,%3};"
        : "+f"(c[0]), "+f"(c[1]), "+f"(c[2]), "+f"(c[3])
        : "r"(a0), "r"(a1), "r"(a2), "r"(a3), "r"(b0), "r"(b1));
}
__device__ __forceinline__ void mma_f16(float* c, uint32_t a0, uint32_t a1, uint32_t a2,
                                        uint32_t a3, uint32_t b0, uint32_t b1) {
    asm volatile(
        "mma.sync.aligned.m16n8k16.row.col.f32.f16.f16.f32 "
        "{%0,%1,%2,%3}, {%4,%5,%6,%7}, {%8,%9}, {%0,%1,%2,%3};"
        : "+f"(c[0]), "+f"(c[1]), "+f"(c[2]), "+f"(c[3])
        : "r"(a0), "r"(a1), "r"(a2), "r"(a3), "r"(b0), "r"(b1));
}
__device__ __forceinline__ void mma_bf16a(float* c, const uint32_t* a, uint32_t b0, uint32_t b1) {
    mma_bf16(c, a[0], a[1], a[2], a[3], b0, b1);
}
__device__ __forceinline__ void mma_f16a(float* c, const uint32_t* a, uint32_t b0, uint32_t b1) {
    mma_f16(c, a[0], a[1], a[2], a[3], b0, b1);
}
__device__ __forceinline__ void cp_async16(uint32_t dst, const void* src) {
    asm volatile(
        "{ .reg .u64 g; cvta.to.global.u64 g, %1; cp.async.cg.shared.global [%0], [g], 16; }"
        :: "r"(dst), "l"(src) : "memory");
}
#define CP_COMMIT() asm volatile("cp.async.commit_group;" ::: "memory")
template<int N> __device__ __forceinline__ void cp_wait() {
    asm volatile("cp.async.wait_group %0;" :: "n"(N) : "memory");
}

#define PADB 144                  // padded row stride in bytes (72 halfwords)

// ---------------- 0) merged prep: split s (fp16 hi/lo), transpose W (fp16 hi) --------
__global__ void __launch_bounds__(256) prep_kernel(
    const float* __restrict__ s,
    const float* __restrict__ Wq, const float* __restrict__ Wk, const float* __restrict__ Wv)
{
    __shared__ float tbuf[32][33];
    const int bid = blockIdx.x;
    const int tid = threadIdx.x;
    if (bid < 2048) {
        int idx = bid * 256 + tid;        // 0..524287
        float4 v = *(const float4*)&s[(size_t)idx * 4];
        __half h0, l0, h1, l1, h2, l2, h3, l3;
        split2h(v.x, h0, l0); split2h(v.y, h1, l1);
        split2h(v.z, h2, l2); split2h(v.w, h3, l3);
        uint2 hv, lv;
        hv.x = pack_h16x2(h0, h1); hv.y = pack_h16x2(h2, h3);
        lv.x = pack_h16x2(l0, l1); lv.y = pack_h16x2(l2, l3);
        *(uint2*)&g_s_hi[(size_t)idx * 4] = hv;
        *(uint2*)&g_s_lo[(size_t)idx * 4] = lv;
    } else {
        int b2  = bid - 2048;             // 0..3071
        int z   = b2 >> 10;
        int rem = b2 & 1023;
        int k0  = (rem >> 5) * 32;
        int n0  = (rem & 31) * 32;
        const float* W = (z == 0) ? Wq : (z == 1) ? Wk : Wv;
        int tx = tid & 31, ty = tid >> 5;
        #pragma unroll
        for (int i = 0; i < 4; i++) {
            int ky = ty + i * 8;
            tbuf[ky][tx] = W[(size_t)(k0 + ky) * (HH * CC) + n0 + tx];
        }
        __syncthreads();
        #pragma unroll
        for (int i = 0; i < 4; i++) {
            int ny = ty + i * 8;
            size_t adr = ((size_t)z * FSZ + n0 + ny) * FSZ + k0 + tx;
            g_wt_hi[adr] = __float2half_rn(tbuf[tx][ny]);
        }
    }
}

// ---------------- 1) QKV projection: 2-pass fp16, cp.async double-buffered -----------
#define QTILEB (128 * PADB)               // 18432 B per piece
#define QBUF   (3 * QTILEB)               // 55296 B per chunk buffer (A_hi, A_lo, B_hi)
#define QKV_SMEM (2 * QBUF)               // 110592

__device__ __forceinline__ void qkv_issue(uint32_t buf, int z, int m0, int n0, int k0, int tid)
{
    #pragma unroll
    for (int it = 0; it < 6; it++) {
        int idx  = tid + it * 512;        // 0..3071
        int a    = idx >> 10;             // 0..2
        int idx2 = idx & 1023;
        int row  = idx2 >> 3;
        int c16  = idx2 & 7;
        const __half* src;
        if (a == 0)      src = &g_s_hi[(size_t)(m0 + row) * FSZ + k0 + c16 * 8];
        else if (a == 1) src = &g_s_lo[(size_t)(m0 + row) * FSZ + k0 + c16 * 8];
        else             src = &g_wt_hi[((size_t)z * FSZ + n0 + row) * FSZ + k0 + c16 * 8];
        cp_async16(buf + (uint32_t)(a * QTILEB + row * PADB + c16 * 16), src);
    }
}

__global__ void __launch_bounds__(512, 1) qkv_mma_kernel(const int* __restrict__ positions)
{
    extern __shared__ char smem[];
    const uint32_t sb = smem_to_u32(smem);
    const int tid  = threadIdx.x;
    const int lane = tid & 31;
    const int wid  = tid >> 5;        // 0..15
    const int g    = lane >> 2;
    const int t    = lane & 3;
    const int z    = blockIdx.z;
    const int m0   = blockIdx.y * 128;
    const int n0   = blockIdx.x * 128;
    const int wm   = (wid >> 1) * 16; // 8 m-strips of 16
    const int wn   = (wid & 1) * 64;  // 2 n-halves of 64 (full head per warp)

    float acc[8][4];
    #pragma unroll
    for (int j = 0; j < 8; j++)
        #pragma unroll
        for (int u = 0; u < 4; u++) acc[j][u] = 0.f;

    const uint32_t aRow  = (uint32_t)(lane & 15);
    const uint32_t aColH = (uint32_t)(lane >> 4) * 16;
    const uint32_t bTile = (uint32_t)(lane >> 3);
    const uint32_t bRow  = (bTile >> 1) * 8 + (uint32_t)(lane & 7);
    const uint32_t bColH = (bTile & 1) * 16;

    qkv_issue(sb, z, m0, n0, 0, tid);
    CP_COMMIT();

    #pragma unroll 1
    for (int c = 0; c < 16; c++) {
        const uint32_t buf = sb + (uint32_t)(c & 1) * QBUF;
        if (c + 1 < 16) {
            qkv_issue(sb + (uint32_t)((c + 1) & 1) * QBUF, z, m0, n0, (c + 1) * 64, tid);
            CP_COMMIT();
            cp_wait<1>();
        } else {
            cp_wait<0>();
        }
        __syncthreads();

        #pragma unroll
        for (int pass = 0; pass < 2; pass++) {
            const uint32_t Ao = buf + (pass == 1 ? QTILEB : 0u);
            const uint32_t Bo = buf + 2u * QTILEB;
            #pragma unroll
            for (int ks = 0; ks < 4; ks++) {
                const uint32_t kb = (uint32_t)(ks * 32);
                uint32_t af[4];
                {
                    uint32_t addr = Ao + (uint32_t)(wm + aRow) * PADB + kb + aColH;
                    ldmatrix_x4(af[0], af[1], af[2], af[3], addr);
                }
                uint32_t bf[8][2];
                #pragma unroll
                for (int nf = 0; nf < 8; nf += 2) {
                    uint32_t addr = Bo + (uint32_t)(wn + nf * 8 + bRow) * PADB + kb + bColH;
                    uint32_t r0, r1, r2, r3;
                    ldmatrix_x4(r0, r1, r2, r3, addr);
                    bf[nf][0] = r0;     bf[nf][1] = r1;
                    bf[nf + 1][0] = r2; bf[nf + 1][1] = r3;
                }
                #pragma unroll
                for (int nf = 0; nf < 8; nf++)
                    mma_f16(acc[nf], af[0], af[1], af[2], af[3], bf[nf][0], bf[nf][1]);
            }
        }
        __syncthreads();
    }

    // ---- epilogue: q fp16 hi/lo; k,v fp16 hi only ----
    if (z <= 1) {
        const int h = ((n0 + wn) >> 6) & 15;
        float tsv[8];
        #pragma unroll
        for (int nf = 0; nf < 4; nf++)
            #pragma unroll
            for (int j = 0; j < 2; j++) {
                int i = nf * 8 + 2 * t + j;
                tsv[nf * 2 + j] = powf(10000.0f, (float)i / 32.0f);
            }
        #pragma unroll
        for (int rh = 0; rh < 2; rh++) {
            int row = m0 + wm + g + rh * 8;
            int b   = row >> 10, n = row & 1023;
            float pos = (float)positions[b * NN + n];
            size_t base = ((size_t)(b * HH + h) * NN + n) * CC;
            #pragma unroll
            for (int nf = 0; nf < 4; nf++) {
                float o1[2], o2[2];
                #pragma unroll
                for (int j = 0; j < 2; j++) {
                    float ang = pos / tsv[nf * 2 + j];
                    float sv, cv;
                    sincosf(ang, &sv, &cv);
                    float x1 = acc[nf][rh * 2 + j];
                    float x2 = acc[nf + 4][rh * 2 + j];
                    o1[j] = x1 * cv - x2 * sv;
                    o2[j] = x2 * cv + x1 * sv;
                }
                int cc = nf * 8 + 2 * t;
                if (z == 0) {
                    __half h0, l0, h1, l1;
                    split2h(o1[0], h0, l0); split2h(o1[1], h1, l1);
                    *(uint32_t*)&g_q_hi[base + cc]      = pack_h16x2(h0, h1);
                    *(uint32_t*)&g_q_lo[base + cc]      = pack_h16x2(l0, l1);
                    split2h(o2[0], h0, l0); split2h(o2[1], h1, l1);
                    *(uint32_t*)&g_q_hi[base + cc + 32] = pack_h16x2(h0, h1);
                    *(uint32_t*)&g_q_lo[base + cc + 32] = pack_h16x2(l0, l1);
                } else {
                    *(uint32_t*)&g_k_hi[base + cc] =
                        pack_h16x2(__float2half_rn(o1[0]), __float2half_rn(o1[1]));
                    *(uint32_t*)&g_k_hi[base + cc + 32] =
                        pack_h16x2(__float2half_rn(o2[0]), __float2half_rn(o2[1]));
                }
            }
        }
    } else {
        #pragma unroll
        for (int nf = 0; nf < 8; nf++) {
            int row = m0 + wm + g;
            int b   = row >> 10, n = row & 1023;
            int col = n0 + wn + nf * 8 + 2 * t;
            int h   = col >> 6, cc = col & 63;
            size_t adr0 = ((size_t)(b * HH + h) * NN + n) * CC + cc;
            size_t adr1 = ((size_t)(b * HH + h) * NN + n + 8) * CC + cc;
            *(uint32_t*)&g_v_hi[adr0] =
                pack_h16x2(__float2half_rn(acc[nf][0]), __float2half_rn(acc[nf][1]));
            *(uint32_t*)&g_v_hi[adr1] =
                pack_h16x2(__float2half_rn(acc[nf][2]), __float2half_rn(acc[nf][3]));
        }
    }
}

// ---------------- 3) bias: single-converted-operand bf16 mma, 64-k chunks ------------
#define BCHK (64 * PADB)                  // 9216 B pair chunk (bf16 hi)
#define BO_WBH BCHK
#define BO_WBL (BO_WBH + 16 * PADB)
#define BIAS_SMEM (BO_WBL + 16 * PADB)    // 13824

__global__ void __launch_bounds__(256) bias_mma_kernel(
    const float* __restrict__ pair,
    const float* __restrict__ Wb,
    const int* __restrict__ seg)
{
    __shared__ char smem[BIAS_SMEM];
    const uint32_t sb = smem_to_u32(smem);
    const int tid  = threadIdx.x;
    const int lane = tid & 31;
    const int w    = tid >> 5;
    const int g    = lane >> 2;
    const int t    = lane & 3;
    const int bx   = blockIdx.x;
    const int b    = bx >> 10;
    const int q    = 1023 - (bx & 1023);       // heavy rows first
    const int segq = seg[b * NN + q];

    if (tid < 64) {
        int f = tid;
        #pragma unroll
        for (int h = 0; h < 16; h++) {
            float x = Wb[f * HH + h];
            __nv_bfloat16 hh, ll;
            split2(x, hh, ll);
            *(__nv_bfloat16*)(smem + BO_WBH + h * PADB + f * 2) = hh;
            *(__nv_bfloat16*)(smem + BO_WBL + h * PADB + f * 2) = ll;
        }
    }

    int lo = 0, hi = q;
    while (lo < hi) {
        int mid = (lo + hi) >> 1;
        if (seg[b * NN + mid] < segq) lo = mid + 1; else hi = mid;
    }
    const int kstart = lo & ~63;
    __syncthreads();

    const uint32_t aRow  = (uint32_t)(lane & 15);
    const uint32_t aColH = (uint32_t)(lane >> 4) * 16;
    uint32_t ah[4][4], alr[4][4];
    #pragma unroll
    for (int ks = 0; ks < 4; ks++) {
        uint32_t addr = sb + BO_WBH + aRow * PADB + (uint32_t)(ks * 32) + aColH;
        ldmatrix_x4(ah[ks][0],  ah[ks][1],  ah[ks][2],  ah[ks][3],  addr);
        ldmatrix_x4(alr[ks][0], alr[ks][1], alr[ks][2], alr[ks][3], addr + 16 * PADB);
    }

    const uint32_t bRow  = (uint32_t)(lane & 7);
    const uint32_t bColH = ((uint32_t)(lane >> 3) & 1) * 16;
    const float* psrc = &pair[((size_t)(b * NN + q)) * NN * FZ];

    #pragma unroll 1
    for (int k0 = kstart; k0 <= q; k0 += 64) {
        __syncthreads();
        #pragma unroll
        for (int it = 0; it < 4; it++) {
            int idx = tid + it * 256;
            int r   = idx >> 4;
            int c4  = (idx & 15) << 2;
            int row = k0 + r; if (row > 1023) row = 1023;
            float4 v = *(const float4*)&psrc[(size_t)row * FZ + c4];
            uint2 u;
            u.x = cvt_bf16x2(v.x, v.y);
            u.y = cvt_bf16x2(v.z, v.w);
            *(uint2*)(smem + r * PADB + c4 * 2) = u;
        }
        __syncthreads();

        float S[4] = {0.f, 0.f, 0.f, 0.f};
        #pragma unroll
        for (int ks = 0; ks < 4; ks++) {
            uint32_t baddr = sb + (uint32_t)(w * 8 + bRow) * PADB
                           + (uint32_t)(ks * 32) + bColH;
            uint32_t r0, r1;
            ldmatrix_x2(r0, r1, baddr);
            mma_bf16a(S, ah[ks],  r0, r1);
            mma_bf16a(S, alr[ks], r0, r1);
        }

        int k = k0 + w * 8 + 2 * t;
        if (k <= 1022) {
            __nv_bfloat16 x0 = __float2bfloat16(S[0]);
            __nv_bfloat16 x1 = __float2bfloat16(S[1]);
            __nv_bfloat16 x2 = __float2bfloat16(S[2]);
            __nv_bfloat16 x3 = __float2bfloat16(S[3]);
            *(uint32_t*)&g_bias[(((size_t)(b * HH + g))     * NN + q) * NN + k] =
                pack_bf16x2(x0, x1);
            *(uint32_t*)&g_bias[(((size_t)(b * HH + g + 8)) * NN + q) * NN + k] =
                pack_bf16x2(x2, x3);
        }
    }
}

// ---------------- 4) flash attention: 2-pass fp16, halved tiles ----------------------
#define AQT (128 * PADB)                  // 18432 per Q piece
#define AKT (64 * PADB)                   // 9216 per K/V piece
#define AST (2 * AKT)                     // 18432 per stage (K hi, V hi)
#define O_ST0  (2 * AQT)                  // stage 0 base
#define O_SEG  (2 * AQT + 2 * AST)        // seg[2][64] ints
#define O_LIST (O_SEG + 512)              // tile list (16) + count
#define ATTN_SMEM (O_LIST + 128)          // ~74.4 KB

__device__ __forceinline__ void attn_issue(uint32_t stbase, int bh, int k0, int tid)
{
    #pragma unroll
    for (int it = 0; it < 4; it++) {
        int idx  = tid + it * 256;        // 0..1023
        int a    = idx >> 9;              // 0: K hi, 1: V hi
        int idx2 = idx & 511;
        int row  = idx2 >> 3;
        int c16  = idx2 & 7;
        size_t e = ((size_t)bh * NN + k0 + row) * CC + c16 * 8;
        const __half* src = a ? &g_v_hi[e] : &g_k_hi[e];
        cp_async16(stbase + (uint32_t)(a * AKT + row * PADB + c16 * 16), src);
    }
}

__global__ void __launch_bounds__(256, 1) attn_mma_kernel(
    const int* __restrict__ seg, float* __restrict__ out)
{
    extern __shared__ char smem[];
    const uint32_t sb = smem_to_u32(smem);
    int* tile_list = (int*)(smem + O_LIST);

    const int tid  = threadIdx.x;
    const int lane = tid & 31;
    const int w    = tid >> 5;
    const int g    = lane >> 2;
    const int t    = lane & 3;
    const int qt   = 7 - blockIdx.x;          // heavy tiles first
    const int h    = blockIdx.y;
    const int b    = blockIdx.z;
    const int q0   = qt * 128;
    const int bh   = b * HH + h;
    const float sm_scale = 0.125f;

    const int r0g = q0 + w * 16 + g;
    const int r1g = r0g + 8;
    const int seg_q0 = seg[b * NN + q0];
    const int myseg0 = seg[b * NN + r0g];
    const int myseg1 = seg[b * NN + r1g];
    const int jmax   = 2 * qt + 1;

    if (tid < 32) {
        bool valid = (lane <= jmax) && (seg[b * NN + lane * 64 + 63] >= seg_q0);
        uint32_t m = __ballot_sync(0xffffffffu, valid);
        if (valid) tile_list[1 + __popc(m & ((1u << lane) - 1u))] = lane;
        if (lane == 0) tile_list[0] = __popc(m);
    }
    __syncthreads();
    const int T = tile_list[0];

    {
        #pragma unroll
        for (int it = 0; it < 8; it++) {
            int idx  = tid + it * 256;
            int a    = idx >> 10;
            int idx2 = idx & 1023;
            int row  = idx2 >> 3;
            int c16  = idx2 & 7;
            size_t e = ((size_t)bh * NN + q0 + row) * CC + c16 * 8;
            const __half* src = a ? &g_q_lo[e] : &g_q_hi[e];
            cp_async16(sb + (uint32_t)(a * AQT + row * PADB + c16 * 16), src);
        }
        int k0 = tile_list[1] * 64;
        attn_issue(sb + O_ST0, bh, k0, tid);
        if (tid < 16) cp_async16(sb + O_SEG + tid * 16, &seg[b * NN + k0 + tid * 4]);
        CP_COMMIT();
    }

    float O[8][4];
    #pragma unroll
    for (int nf = 0; nf < 8; nf++)
        #pragma unroll
        for (int u = 0; u < 4; u++) O[nf][u] = 0.f;
    float m0r = -1e30f, m1r = -1e30f, l0r = 0.f, l1r = 0.f;

    const uint32_t aRow  = (uint32_t)(lane & 15);
    const uint32_t aColH = (uint32_t)(lane >> 4) * 16;
    const uint32_t bTile = (uint32_t)(lane >> 3);
    const uint32_t bRow  = (bTile >> 1) * 8 + (uint32_t)(lane & 7);
    const uint32_t bColH = (bTile & 1) * 16;
    const uint32_t vRow  = (bTile & 1) * 8 + (uint32_t)(lane & 7);
    const uint32_t vColH = (uint32_t)(lane >> 4) * 16;

    const __nv_bfloat16* bias0 = &g_bias[((size_t)bh * NN + r0g) * NN];
    const __nv_bfloat16* bias1 = &g_bias[((size_t)bh * NN + r1g) * NN];

    uint32_t qh[4][4], ql[4][4];

    #pragma unroll 1
    for (int i = 0; i < T; i++) {
        const int st = i & 1;
        const uint32_t stb = sb + O_ST0 + (uint32_t)st * AST;
        if (i + 1 < T) {
            int k0n = tile_list[1 + i + 1] * 64;
            attn_issue(sb + O_ST0 + (uint32_t)(st ^ 1) * AST, bh, k0n, tid);
            if (tid < 16)
                cp_async16(sb + O_SEG + (uint32_t)(st ^ 1) * 256 + tid * 16,
                           &seg[b * NN + k0n + tid * 4]);
            CP_COMMIT();
            cp_wait<1>();
        } else {
            cp_wait<0>();
        }
        __syncthreads();

        if (i == 0) {
            #pragma unroll
            for (int ks = 0; ks < 4; ks++) {
                uint32_t qaddr = sb + (uint32_t)(w * 16 + aRow) * PADB
                               + (uint32_t)(ks * 32) + aColH;
                ldmatrix_x4(qh[ks][0], qh[ks][1], qh[ks][2], qh[ks][3], qaddr);
                ldmatrix_x4(ql[ks][0], ql[ks][1], ql[ks][2], ql[ks][3], qaddr + AQT);
            }
        }

        const int k0 = tile_list[1 + i] * 64;
        const int* seg_ks = (const int*)(smem + O_SEG + st * 256);

        // ---- S = (Q_hi + Q_lo) · K_hi  (2-pass fp16) ----
        float S[8][4];
        #pragma unroll
        for (int nf = 0; nf < 8; nf++)
            #pragma unroll
            for (int u = 0; u < 4; u++) S[nf][u] = 0.f;

        #pragma unroll
        for (int ks = 0; ks < 4; ks++) {
            const uint32_t kb = (uint32_t)(ks * 32);
            #pragma unroll
            for (int np = 0; np < 4; np++) {
                uint32_t kaddr = stb + (uint32_t)(np * 16 + bRow) * PADB + kb + bColH;
                uint32_t r0, r1, r2, r3;
                ldmatrix_x4(r0, r1, r2, r3, kaddr);              // K hi
                mma_f16a(S[2 * np],     qh[ks], r0, r1);
                mma_f16a(S[2 * np + 1], qh[ks], r2, r3);
                mma_f16a(S[2 * np],     ql[ks], r0, r1);
                mma_f16a(S[2 * np + 1], ql[ks], r2, r3);
            }
        }

        float mx0 = -1e30f, mx1 = -1e30f;
        #pragma unroll
        for (int nf = 0; nf < 8; nf++) {
            int cl = nf * 8 + 2 * t;
            int cg = k0 + cl;
            __nv_bfloat162 bb0 = *(const __nv_bfloat162*)&bias0[cg];
            __nv_bfloat162 bb1 = *(const __nv_bfloat162*)&bias1[cg];
            int sk0 = seg_ks[cl], sk1 = seg_ks[cl + 1];
            bool v00 = (cg     <= r0g) && (sk0 == myseg0);
            bool v01 = (cg + 1 <= r0g) && (sk1 == myseg0);
            bool v10 = (cg     <= r1g) && (sk0 == myseg1);
            bool v11 = (cg + 1 <= r1g) && (sk1 == myseg1);
            S[nf][0] = v00 ? fmaf(S[nf][0], sm_scale, __bfloat162float(bb0.x)) : -1e30f;
            S[nf][1] = v01 ? fmaf(S[nf][1], sm_scale, __bfloat162float(bb0.y)) : -1e30f;
            S[nf][2] = v10 ? fmaf(S[nf][2], sm_scale, __bfloat162float(bb1.x)) : -1e30f;
            S[nf][3] = v11 ? fmaf(S[nf][3], sm_scale, __bfloat162float(bb1.y)) : -1e30f;
            mx0 = fmaxf(mx0, fmaxf(S[nf][0], S[nf][1]));
            mx1 = fmaxf(mx1, fmaxf(S[nf][2], S[nf][3]));
        }
        mx0 = fmaxf(mx0, __shfl_xor_sync(0xffffffffu, mx0, 1));
        mx0 = fmaxf(mx0, __shfl_xor_sync(0xffffffffu, mx0, 2));
        mx1 = fmaxf(mx1, __shfl_xor_sync(0xffffffffu, mx1, 1));
        mx1 = fmaxf(mx1, __shfl_xor_sync(0xffffffffu, mx1, 2));

        float mn0 = fmaxf(m0r, mx0), mn1 = fmaxf(m1r, mx1);
        float al0 = __expf(m0r - mn0), al1 = __expf(m1r - mn1);
        m0r = mn0; m1r = mn1;

        float sum0 = 0.f, sum1 = 0.f;
        #pragma unroll
        for (int nf = 0; nf < 8; nf++) {
            float p0 = (S[nf][0] > -1e29f) ? __expf(S[nf][0] - mn0) : 0.f;
            float p1 = (S[nf][1] > -1e29f) ? __expf(S[nf][1] - mn0) : 0.f;
            float p2 = (S[nf][2] > -1e29f) ? __expf(S[nf][2] - mn1) : 0.f;
            float p3 = (S[nf][3] > -1e29f) ? __expf(S[nf][3] - mn1) : 0.f;
            S[nf][0] = p0; S[nf][1] = p1; S[nf][2] = p2; S[nf][3] = p3;
            sum0 += p0 + p1; sum1 += p2 + p3;
        }
        sum0 += __shfl_xor_sync(0xffffffffu, sum0, 1);
        sum0 += __shfl_xor_sync(0xffffffffu, sum0, 2);
        sum1 += __shfl_xor_sync(0xffffffffu, sum1, 1);
        sum1 += __shfl_xor_sync(0xffffffffu, sum1, 2);
        l0r = l0r * al0 + sum0;
        l1r = l1r * al1 + sum1;

        #pragma unroll
        for (int nf = 0; nf < 8; nf++) {
            O[nf][0] *= al0; O[nf][1] *= al0;
            O[nf][2] *= al1; O[nf][3] *= al1;
        }

        // ---- O += (P_hi + P_lo) · V_hi  (2-pass fp16, V via ldmatrix.trans) ----
        #pragma unroll
        for (int kf = 0; kf < 4; kf++) {
            uint32_t ah[4], al[4];
            {
                __half h0, l0, h1, l1;
                split2h(S[2 * kf][0], h0, l0); split2h(S[2 * kf][1], h1, l1);
                ah[0] = pack_h16x2(h0, h1);  al[0] = pack_h16x2(l0, l1);
                split2h(S[2 * kf][2], h0, l0); split2h(S[2 * kf][3], h1, l1);
                ah[1] = pack_h16x2(h0, h1);  al[1] = pack_h16x2(l0, l1);
                split2h(S[2 * kf + 1][0], h0, l0); split2h(S[2 * kf + 1][1], h1, l1);
                ah[2] = pack_h16x2(h0, h1);  al[2] = pack_h16x2(l0, l1);
                split2h(S[2 * kf + 1][2], h0, l0); split2h(S[2 * kf + 1][3], h1, l1);
                ah[3] = pack_h16x2(h0, h1);  al[3] = pack_h16x2(l0, l1);
            }
            #pragma unroll
            for (int cf = 0; cf < 4; cf++) {
                uint32_t vaddr = stb + (uint32_t)AKT + (uint32_t)(kf * 16 + vRow) * PADB
                               + (uint32_t)(cf * 32) + vColH;
                uint32_t r0, r1, r2, r3;
                ldmatrix_x4_trans(r0, r1, r2, r3, vaddr);        // V hi
                mma_f16a(O[2 * cf],     ah, r0, r1);
                mma_f16a(O[2 * cf + 1], ah, r2, r3);
                mma_f16a(O[2 * cf],     al, r0, r1);
                mma_f16a(O[2 * cf + 1], al, r2, r3);
            }
        }
        __syncthreads();
    }

    float inv0 = 1.f / l0r;
    float inv1 = 1.f / l1r;
    size_t base0 = (((size_t)(b * NN + r0g)) * HH + h) * CC;
    size_t base1 = (((size_t)(b * NN + r1g)) * HH + h) * CC;
    #pragma unroll
    for (int nf = 0; nf < 8; nf++) {
        int col = nf * 8 + 2 * t;
        *(float2*)&out[base0 + col] = make_float2(O[nf][0] * inv0, O[nf][1] * inv0);
        *(float2*)&out[base1 + col] = make_float2(O[nf][2] * inv1, O[nf][3] * inv1);
    }
}

// ---------------- launcher: bias runs concurrently with prep+qkv ----------------
extern "C" void kernel_launch(void* const* d_in, const int* in_sizes, int n_in,
                              void* d_out, int out_size)
{
    const float* s    = (const float*)d_in[0];
    const float* pair = (const float*)d_in[1];
    const int*   segs = (const int*)d_in[2];
    const int*   pos  = (const int*)d_in[3];
    const float* Wq   = (const float*)d_in[4];
    const float* Wk   = (const float*)d_in[5];
    const float* Wv   = (const float*)d_in[6];
    const float* Wb   = (const float*)d_in[7];
    float* out = (float*)d_out;

    static cudaStream_t sB = nullptr;
    static cudaEvent_t  eF = nullptr, eJ = nullptr;
    if (!sB) {
        cudaStreamCreateWithFlags(&sB, cudaStreamNonBlocking);
        cudaEventCreateWithFlags(&eF, cudaEventDisableTiming);
        cudaEventCreateWithFlags(&eJ, cudaEventDisableTiming);
    }

    cudaFuncSetAttribute(qkv_mma_kernel, cudaFuncAttributeMaxDynamicSharedMemorySize,
                         QKV_SMEM);
    cudaFuncSetAttribute(attn_mma_kernel, cudaFuncAttributeMaxDynamicSharedMemorySize,
                         ATTN_SMEM);

    // fork: bias (depends only on pair/Wb/seg) runs on sB concurrently
    cudaEventRecord(eF, 0);
    cudaStreamWaitEvent(sB, eF, 0);
    bias_mma_kernel<<<BB * NN, 256, 0, sB>>>(pair, Wb, segs);
    cudaEventRecord(eJ, sB);

    // main branch: prep -> qkv (2-pass fp16, rope fused)
    prep_kernel<<<5120, 256>>>(s, Wq, Wk, Wv);
    qkv_mma_kernel<<<dim3(8, 16, 3), 512, QKV_SMEM>>>(pos);

    // join, then attention
    cudaStreamWaitEvent(0, eJ, 0);
    attn_mma_kernel<<<dim3(8, HH, BB), 256, ATTN_SMEM>>>(segs, out);
}